// round 8
// baseline (speedup 1.0000x reference)
#include <cuda_runtime.h>
#include <cuda_bf16.h>
#include <math.h>

#define NN 16384
#define NE 262144
#define HH 128
#define BB 64
#define SS 256
#define RR 32

__device__ float g_ie[NE*HH];
__device__ float g_me[NE*HH];
__device__ float g_in[NN*HH];
__device__ float g_P[NN*HH];
__device__ float g_D[NN*HH];
__device__ float g_U[NN*HH];
__device__ float g_mn[NN*HH];
__device__ float g_agg[NN*HH];
__device__ float g_V[NN*HH];
__device__ float g_nodeh[NN*HH];
__device__ float g_msg[NN*HH];
__device__ float g_scr[NN*HH];
__device__ float g_gi[NN*384];
__device__ float g_gif[128*384];
__device__ float g_msg2[128*HH];
__device__ float g_WihT[2*384*128];
__device__ float g_Qrel[RR*HH];
__device__ float g_Qd[2*RR*HH];
__device__ float g_h0[BB*HH];
__device__ float g_y[4*BB*HH];
__device__ int   g_is64[2];
__device__ int   g_cnt[NN];
__device__ int   g_off[NN+1];
__device__ int   g_cur[NN];
__device__ int   g_eid[NE];
__device__ int   g_bsum[16], g_bpre[16];
__device__ unsigned short g_Whg[3*16384];
__device__ unsigned short g_Wlg[3*16384];

__device__ __forceinline__ int ld_idx(const void* p, long long i, int sel) {
    if (g_is64[sel]) return (int)((const long long*)p)[i];
    return ((const int*)p)[i];
}

__global__ void k_detect(const void* src, const void* et) {
    if (threadIdx.x == 0) {
        const unsigned long long* a = (const unsigned long long*)src;
        int v = 1;
        for (int i = 0; i < 8; i++) if (a[i] >= (unsigned long long)NN) v = 0;
        g_is64[0] = v;
        const unsigned long long* b = (const unsigned long long*)et;
        v = 1;
        for (int i = 0; i < 8; i++) if (b[i] >= (unsigned long long)RR) v = 0;
        g_is64[1] = v;
    }
}

// ---------- bf16 hi/lo helpers ----------
__device__ __forceinline__ void f2bf(float x, unsigned short& h, unsigned short& l) {
    __nv_bfloat16 bh = __float2bfloat16(x);
    h = __bfloat16_as_ushort(bh);
    l = __bfloat16_as_ushort(__float2bfloat16(x - __bfloat162float(bh)));
}

__device__ __forceinline__ void mma16(float* d, const unsigned* a, const unsigned* b) {
    asm volatile("mma.sync.aligned.m16n8k16.row.col.f32.bf16.bf16.f32 "
        "{%0,%1,%2,%3}, {%4,%5,%6,%7}, {%8,%9}, {%0,%1,%2,%3};"
        : "+f"(d[0]), "+f"(d[1]), "+f"(d[2]), "+f"(d[3])
        : "r"(a[0]), "r"(a[1]), "r"(a[2]), "r"(a[3]), "r"(b[0]), "r"(b[1]));
}

// weight pre-conversion: Wm fp32 [128][128] row-major -> Wh/Wl bf16 [c*128+k]
__global__ void k_wconv(const float* __restrict__ Wm,
                        unsigned short* __restrict__ Wh,
                        unsigned short* __restrict__ Wl)
{
    int t = blockIdx.x*256 + threadIdx.x;   // 16384
    int k = t >> 7, c = t & 127;
    unsigned short h, l;
    f2bf(Wm[k*128 + c], h, l);
    Wh[c*128 + k] = h;
    Wl[c*128 + k] = l;
}

#define APITCH 40
#define WPITCH 42
#define EAPITCH 136
#define SMEM_EA (2*128*EAPITCH*2)

// ---------- bf16 3-split tensor-core GEMM (unchanged) ----------
__global__ void __launch_bounds__(256, 2) k_tgemm_bf(
    const float* __restrict__ A, const float* __restrict__ W, float* __restrict__ C,
    int K, int M, const float* __restrict__ bias, int doRelu, int accum)
{
    __shared__ unsigned short sAh[128*APITCH], sAl[128*APITCH];
    __shared__ unsigned short sWh[128*WPITCH], sWl[128*WPITCH];
    const int tid = threadIdx.x;
    const int w = tid >> 5, lane = tid & 31;
    const int g = lane >> 2, t = lane & 3;
    const int wr0 = (w >> 1) * 32, wc0 = (w & 1) * 64;
    const long long row0 = (long long)blockIdx.x * 128;
    const int col0 = blockIdx.y * 128;

    float acc[2][8][4];
#pragma unroll
    for (int a = 0; a < 2; a++)
#pragma unroll
        for (int b = 0; b < 8; b++)
#pragma unroll
            for (int c = 0; c < 4; c++) acc[a][b][c] = 0.f;

    for (int k0 = 0; k0 < K; k0 += 32) {
        __syncthreads();
#pragma unroll
        for (int i = 0; i < 4; i++) {
            int f = tid + 256 * i;
            int r = f >> 3, j = (f & 7) << 2;
            float4 v = *(const float4*)(A + (row0 + r) * K + k0 + j);
            unsigned short h, l;
            f2bf(v.x, h, l); sAh[r*APITCH+j+0] = h; sAl[r*APITCH+j+0] = l;
            f2bf(v.y, h, l); sAh[r*APITCH+j+1] = h; sAl[r*APITCH+j+1] = l;
            f2bf(v.z, h, l); sAh[r*APITCH+j+2] = h; sAl[r*APITCH+j+2] = l;
            f2bf(v.w, h, l); sAh[r*APITCH+j+3] = h; sAl[r*APITCH+j+3] = l;
        }
#pragma unroll
        for (int i = 0; i < 4; i++) {
            int f = tid + 256 * i;
            int kk = f >> 5, c = (f & 31) << 2;
            float4 v = *(const float4*)(W + (long long)(k0 + kk) * M + col0 + c);
            unsigned short h, l;
            f2bf(v.x, h, l); sWh[(c+0)*WPITCH+kk] = h; sWl[(c+0)*WPITCH+kk] = l;
            f2bf(v.y, h, l); sWh[(c+1)*WPITCH+kk] = h; sWl[(c+1)*WPITCH+kk] = l;
            f2bf(v.z, h, l); sWh[(c+2)*WPITCH+kk] = h; sWl[(c+2)*WPITCH+kk] = l;
            f2bf(v.w, h, l); sWh[(c+3)*WPITCH+kk] = h; sWl[(c+3)*WPITCH+kk] = l;
        }
        __syncthreads();
#pragma unroll
        for (int ks = 0; ks < 32; ks += 16) {
            unsigned ah[2][4], al[2][4];
#pragma unroll
            for (int mt = 0; mt < 2; mt++) {
                int rb = wr0 + mt * 16 + g;
                const unsigned short* p = &sAh[rb*APITCH + ks + 2*t];
                ah[mt][0] = *(const unsigned*)p;
                ah[mt][1] = *(const unsigned*)(p + 8*APITCH);
                ah[mt][2] = *(const unsigned*)(p + 8);
                ah[mt][3] = *(const unsigned*)(p + 8*APITCH + 8);
                const unsigned short* q = &sAl[rb*APITCH + ks + 2*t];
                al[mt][0] = *(const unsigned*)q;
                al[mt][1] = *(const unsigned*)(q + 8*APITCH);
                al[mt][2] = *(const unsigned*)(q + 8);
                al[mt][3] = *(const unsigned*)(q + 8*APITCH + 8);
            }
#pragma unroll
            for (int nt = 0; nt < 8; nt++) {
                int cn = wc0 + nt * 8 + g;
                unsigned bh[2], bl[2];
                const unsigned short* p = &sWh[cn*WPITCH + ks + 2*t];
                bh[0] = *(const unsigned*)p; bh[1] = *(const unsigned*)(p + 8);
                const unsigned short* q = &sWl[cn*WPITCH + ks + 2*t];
                bl[0] = *(const unsigned*)q; bl[1] = *(const unsigned*)(q + 8);
#pragma unroll
                for (int mt = 0; mt < 2; mt++) {
                    mma16(acc[mt][nt], ah[mt], bh);
                    mma16(acc[mt][nt], ah[mt], bl);
                    mma16(acc[mt][nt], al[mt], bh);
                }
            }
        }
    }
#pragma unroll
    for (int mt = 0; mt < 2; mt++) {
#pragma unroll
        for (int nt = 0; nt < 8; nt++) {
            int c = col0 + wc0 + nt * 8 + t * 2;
            long long r0 = row0 + wr0 + mt * 16 + g;
            float b0 = bias ? bias[c] : 0.f, b1 = bias ? bias[c+1] : 0.f;
            float v0 = acc[mt][nt][0] + b0, v1 = acc[mt][nt][1] + b1;
            float v2 = acc[mt][nt][2] + b0, v3 = acc[mt][nt][3] + b1;
            if (accum) {
                float2 o0 = *(const float2*)(C + r0 * M + c);
                float2 o1 = *(const float2*)(C + (r0 + 8) * M + c);
                v0 += o0.x; v1 += o0.y; v2 += o1.x; v3 += o1.y;
            }
            if (doRelu) {
                v0 = fmaxf(v0, 0.f); v1 = fmaxf(v1, 0.f);
                v2 = fmaxf(v2, 0.f); v3 = fmaxf(v3, 0.f);
            }
            *(float2*)(C + r0 * M + c)       = make_float2(v0, v1);
            *(float2*)(C + (r0 + 8) * M + c) = make_float2(v2, v3);
        }
    }
}

// ---------- small SIMT GEMM for 32-row rel_emb GEMMs ----------
__global__ void k_sgemm(const float* __restrict__ A, const float* __restrict__ W,
                        float* __restrict__ C, int rows, int K, int M)
{
    __shared__ float As[16][64];
    __shared__ float Ws[16][64];
    const int tid = threadIdx.x;
    const int tx = tid & 15, ty = tid >> 4;
    const int row0 = blockIdx.x * 64, col0 = blockIdx.y * 64;
    const int la_r = tid >> 2, la_k = (tid & 3) << 2;
    const int lw_k = tid >> 4, lw_c = (tid & 15) << 2;
    float acc[4][4];
#pragma unroll
    for (int i = 0; i < 4; i++)
#pragma unroll
        for (int j = 0; j < 4; j++) acc[i][j] = 0.f;
    for (int k0 = 0; k0 < K; k0 += 16) {
        float4 av = make_float4(0.f,0.f,0.f,0.f);
        if (row0 + la_r < rows)
            av = *(const float4*)(A + (size_t)(row0 + la_r) * K + (k0 + la_k));
        As[la_k+0][la_r] = av.x; As[la_k+1][la_r] = av.y;
        As[la_k+2][la_r] = av.z; As[la_k+3][la_r] = av.w;
        *(float4*)&Ws[lw_k][lw_c] = *(const float4*)(W + (size_t)(k0+lw_k)*M + col0 + lw_c);
        __syncthreads();
#pragma unroll
        for (int k = 0; k < 16; k++) {
            float4 a4 = *(const float4*)&As[k][ty<<2];
            float4 w4 = *(const float4*)&Ws[k][tx<<2];
            float ar[4] = {a4.x,a4.y,a4.z,a4.w};
            float wr[4] = {w4.x,w4.y,w4.z,w4.w};
#pragma unroll
            for (int i = 0; i < 4; i++)
#pragma unroll
                for (int j = 0; j < 4; j++) acc[i][j] += ar[i]*wr[j];
        }
        __syncthreads();
    }
#pragma unroll
    for (int i = 0; i < 4; i++) {
        int r = row0 + (ty<<2) + i;
        if (r < rows)
#pragma unroll
            for (int j = 0; j < 4; j++)
                C[(size_t)r*M + col0 + (tx<<2) + j] = acc[i][j];
    }
}

// ---------- bf16 tensor-core fused edge attention (full-K A smem, global bf16 W) ----------
// mode 1: X = me;  out = relu(ie + a*V[src])
// mode 2: A = relu(P[src]+Q[et]+D[dst]) computed in-kernel, written to ie_out; out = ie * a
__global__ void __launch_bounds__(256, 2) k_edge_att_tc(
    const float* __restrict__ X,
    const unsigned short* __restrict__ Wh, const unsigned short* __restrict__ Wl,
    const float* __restrict__ addvec, const void* idx_add, int sel_add,
    const void* idx_src, const float* __restrict__ w2,
    const float* __restrict__ ie, const float* __restrict__ V,
    float* __restrict__ outp, int mode,
    const float* __restrict__ Pm, const float* __restrict__ Qm,
    const float* __restrict__ Dm, const void* idx_et, const void* idx_dst,
    float* __restrict__ ie_out)
{
    extern __shared__ unsigned short sm_ea[];
    unsigned short* sAh = sm_ea;
    unsigned short* sAl = sm_ea + 128*EAPITCH;
    __shared__ int ia_s[128], is_s[128], iet_s[128], idd_s[128];
    __shared__ float a_s[128], part_s[256], w2_s[128];

    const int tid = threadIdx.x;
    const int w = tid >> 5, lane = tid & 31;
    const int g = lane >> 2, t = lane & 3;
    const int wr0 = (w >> 1) * 32, wc0 = (w & 1) * 64;
    const long long e0 = (long long)blockIdx.x * 128;

    if (tid < 128) {
        ia_s[tid] = ld_idx(idx_add, e0 + tid, sel_add);
        is_s[tid] = ld_idx(idx_src, e0 + tid, 0);
        w2_s[tid] = w2[tid];
        if (mode == 2) {
            iet_s[tid] = ld_idx(idx_et, e0 + tid, 1);
            idd_s[tid] = ld_idx(idx_dst, e0 + tid, 0);
        }
    }
    __syncthreads();

    // load + convert full 128x128 A tile
#pragma unroll
    for (int i = 0; i < 16; i++) {
        int f = tid + 256 * i;
        int r = f >> 5, j = (f & 31) << 2;
        float4 v;
        if (mode == 2) {
            int s = is_s[r], et = iet_s[r], dd = idd_s[r];
            float4 p = *(const float4*)(Pm + (size_t)s*HH + j);
            float4 q = *(const float4*)(Qm + (size_t)et*HH + j);
            float4 dv = *(const float4*)(Dm + (size_t)dd*HH + j);
            v.x = fmaxf(p.x+q.x+dv.x, 0.f); v.y = fmaxf(p.y+q.y+dv.y, 0.f);
            v.z = fmaxf(p.z+q.z+dv.z, 0.f); v.w = fmaxf(p.w+q.w+dv.w, 0.f);
            *(float4*)(ie_out + (e0 + r)*HH + j) = v;
        } else {
            v = *(const float4*)(X + (e0 + r) * HH + j);
        }
        unsigned short h, l;
        f2bf(v.x, h, l); sAh[r*EAPITCH+j+0] = h; sAl[r*EAPITCH+j+0] = l;
        f2bf(v.y, h, l); sAh[r*EAPITCH+j+1] = h; sAl[r*EAPITCH+j+1] = l;
        f2bf(v.z, h, l); sAh[r*EAPITCH+j+2] = h; sAl[r*EAPITCH+j+2] = l;
        f2bf(v.w, h, l); sAh[r*EAPITCH+j+3] = h; sAl[r*EAPITCH+j+3] = l;
    }
    __syncthreads();

    float acc[2][8][4];
#pragma unroll
    for (int a = 0; a < 2; a++)
#pragma unroll
        for (int b = 0; b < 8; b++)
#pragma unroll
            for (int c = 0; c < 4; c++) acc[a][b][c] = 0.f;

    for (int ks = 0; ks < 128; ks += 16) {
        unsigned ah[2][4], al[2][4];
#pragma unroll
        for (int mt = 0; mt < 2; mt++) {
            int rb = wr0 + mt * 16 + g;
            const unsigned short* p = &sAh[rb*EAPITCH + ks + 2*t];
            ah[mt][0] = *(const unsigned*)p;
            ah[mt][1] = *(const unsigned*)(p + 8*EAPITCH);
            ah[mt][2] = *(const unsigned*)(p + 8);
            ah[mt][3] = *(const unsigned*)(p + 8*EAPITCH + 8);
            const unsigned short* q = &sAl[rb*EAPITCH + ks + 2*t];
            al[mt][0] = *(const unsigned*)q;
            al[mt][1] = *(const unsigned*)(q + 8*EAPITCH);
            al[mt][2] = *(const unsigned*)(q + 8);
            al[mt][3] = *(const unsigned*)(q + 8*EAPITCH + 8);
        }
#pragma unroll
        for (int nt = 0; nt < 8; nt++) {
            int cn = wc0 + nt * 8 + g;
            unsigned bh[2], bl[2];
            const unsigned short* p = &Wh[cn*128 + ks + 2*t];
            bh[0] = *(const unsigned*)p; bh[1] = *(const unsigned*)(p + 8);
            const unsigned short* q = &Wl[cn*128 + ks + 2*t];
            bl[0] = *(const unsigned*)q; bl[1] = *(const unsigned*)(q + 8);
#pragma unroll
            for (int mt = 0; mt < 2; mt++) {
                mma16(acc[mt][nt], ah[mt], bh);
                mma16(acc[mt][nt], ah[mt], bl);
                mma16(acc[mt][nt], al[mt], bh);
            }
        }
    }

    // attention scalar
#pragma unroll
    for (int mt = 0; mt < 2; mt++) {
        int r0 = wr0 + mt * 16 + g, r1 = r0 + 8;
        const float2* ar0 = (const float2*)(addvec + (size_t)ia_s[r0] * HH);
        const float2* ar1 = (const float2*)(addvec + (size_t)ia_s[r1] * HH);
        float p0 = 0.f, p1 = 0.f;
#pragma unroll
        for (int nt = 0; nt < 8; nt++) {
            int c = wc0 + nt * 8 + t * 2;
            float w0 = w2_s[c], w1 = w2_s[c+1];
            float2 a0 = ar0[c >> 1], a1 = ar1[c >> 1];
            p0 += fmaxf(acc[mt][nt][0] + a0.x, 0.f) * w0
                + fmaxf(acc[mt][nt][1] + a0.y, 0.f) * w1;
            p1 += fmaxf(acc[mt][nt][2] + a1.x, 0.f) * w0
                + fmaxf(acc[mt][nt][3] + a1.y, 0.f) * w1;
        }
        p0 += __shfl_xor_sync(0xffffffffu, p0, 1);
        p0 += __shfl_xor_sync(0xffffffffu, p0, 2);
        p1 += __shfl_xor_sync(0xffffffffu, p1, 1);
        p1 += __shfl_xor_sync(0xffffffffu, p1, 2);
        if (t == 0) {
            part_s[r0 * 2 + (w & 1)] = p0;
            part_s[r1 * 2 + (w & 1)] = p1;
        }
    }
    __syncthreads();
    if (tid < 128) {
        float ps = part_s[tid * 2] + part_s[tid * 2 + 1];
        a_s[tid] = 1.f / (1.f + expf(-ps));
    }
    __syncthreads();

    // output epilogue
#pragma unroll
    for (int i = 0; i < 16; i++) {
        int f = tid + 256 * i;
        int r = f >> 5, q = (f & 31) << 2;
        size_t base = (size_t)(e0 + r) * HH + q;
        float4 iv = *(const float4*)(ie + base);
        float a = a_s[r];
        float4 o;
        if (mode == 1) {
            float4 v4 = *(const float4*)(V + (size_t)is_s[r] * HH + q);
            o.x = fmaxf(iv.x + a*v4.x, 0.f); o.y = fmaxf(iv.y + a*v4.y, 0.f);
            o.z = fmaxf(iv.z + a*v4.z, 0.f); o.w = fmaxf(iv.w + a*v4.w, 0.f);
        } else {
            o = make_float4(iv.x*a, iv.y*a, iv.z*a, iv.w*a);
        }
        *(float4*)(outp + base) = o;
    }
}

// ---------- CSR build ----------
__global__ void k_cnt_zero() {
    int t = blockIdx.x*256 + threadIdx.x;
    if (t < NN) g_cnt[t] = 0;
}
__global__ void k_count(const void* dstp) {
    int e = blockIdx.x*256 + threadIdx.x;
    if (e < NE) atomicAdd(&g_cnt[ld_idx(dstp, e, 0)], 1);
}
__global__ void __launch_bounds__(1024) k_scan1() {
    __shared__ int wsum[32];
    int b = blockIdx.x, t = threadIdx.x;
    int lane = t & 31, wid = t >> 5;
    int v = g_cnt[b*1024 + t];
    int orig = v;
#pragma unroll
    for (int off = 1; off < 32; off <<= 1) {
        int u = __shfl_up_sync(0xffffffffu, v, off);
        if (lane >= off) v += u;
    }
    if (lane == 31) wsum[wid] = v;
    __syncthreads();
    if (wid == 0) {
        int y = wsum[lane];
#pragma unroll
        for (int off = 1; off < 32; off <<= 1) {
            int u = __shfl_up_sync(0xffffffffu, y, off);
            if (lane >= off) y += u;
        }
        wsum[lane] = y;
    }
    __syncthreads();
    int incl = v + (wid ? wsum[wid-1] : 0);
    g_off[b*1024 + t] = incl - orig;   // block-local exclusive
    if (t == 1023) g_bsum[b] = incl;
}
__global__ void k_scan2() {
    int t = threadIdx.x;   // 32 threads
    int v = (t < 16) ? g_bsum[t] : 0;
    int x = v;
#pragma unroll
    for (int off = 1; off < 32; off <<= 1) {
        int u = __shfl_up_sync(0xffffffffu, x, off);
        if (t >= off) x += u;
    }
    if (t < 16) g_bpre[t] = x - v;
    if (t == 15) g_off[NN] = x;
}
__global__ void k_scan3() {
    int i = blockIdx.x*256 + threadIdx.x;
    if (i < NN) {
        int o = g_off[i] + g_bpre[i >> 10];
        g_off[i] = o;
        g_cur[i] = o;
    }
}
__global__ void k_fill(const void* dstp) {
    int e = blockIdx.x*256 + threadIdx.x;
    if (e < NE) {
        int d = ld_idx(dstp, e, 0);
        int pos = atomicAdd(&g_cur[d], 1);
        g_eid[pos] = e;
    }
}

// ---------- CSR gather aggregation ----------
__global__ void __launch_bounds__(128) k_gather(const float* __restrict__ me,
                                                const float* __restrict__ addb,
                                                float* __restrict__ out)
{
    int n = blockIdx.x, j = threadIdx.x;
    int o0 = g_off[n], o1 = g_off[n+1];
    float s = addb ? addb[(size_t)n*HH + j] : 0.f;
    for (int i = o0; i < o1; i++) {
        int e = g_eid[i];
        s += me[(size_t)e*HH + j];
    }
    out[(size_t)n*HH + j] = s;
}

// ---------- GRU prep ----------
__global__ void k_msg(const float* __restrict__ gru_bias) {
    int t = blockIdx.x*256 + threadIdx.x;
    g_msg[t] = fmaxf(g_nodeh[t] + gru_bias[t & 127], 0.f);
}
__global__ void k_h0() {
    int b = blockIdx.x, j = threadIdx.x;
    float m = -1e30f;
    for (int s = 0; s < SS; s++)
        m = fmaxf(m, g_nodeh[((size_t)(b*SS + s))*HH + j]);
    g_h0[b*HH + j] = m;
}
__global__ void k_twih(const float* __restrict__ Wih) {
    int t = blockIdx.x*256 + threadIdx.x;
    if (t < 2*384*128) {
        int d = t / (384*128), rem = t % (384*128);
        int o = rem / 128, k = rem % 128;
        g_WihT[d*384*128 + k*384 + o] = Wih[t];
    }
}
__global__ void k_msg2() {
    int t = blockIdx.x*256 + threadIdx.x;
    int r = t >> 7, j = t & 127;
    int b = r >> 1, s = r & 1;
    g_msg2[t] = g_msg[((size_t)(b*SS + s))*HH + j];
}

__global__ void __launch_bounds__(384) k_gru(const float* __restrict__ Whh,
                                             const float* __restrict__ bhh)
{
    const int b = blockIdx.x, dir = blockIdx.y;
    const int o = threadIdx.x;
    float w[128];
    const float* wr = Whh + ((size_t)dir*384 + o)*128;
#pragma unroll
    for (int k = 0; k < 128; k += 4) {
        float4 v = *(const float4*)(wr + k);
        w[k]=v.x; w[k+1]=v.y; w[k+2]=v.z; w[k+3]=v.w;
    }
    const float bh = bhh[dir*384 + o];
    __shared__ float h_s[128];
    __shared__ float gh_s[384];
    if (o < 128) h_s[o] = g_h0[b*128 + o];
    __syncthreads();
    const int nsteps = (dir == 0) ? 2 : SS;
    for (int i2 = 0; i2 < nsteps; i2++) {
        int t = (dir == 0) ? i2 : (SS - 1 - i2);
        float gh = bh;
#pragma unroll
        for (int k = 0; k < 128; k += 4) {
            float4 hv = *(const float4*)&h_s[k];
            gh += w[k]*hv.x + w[k+1]*hv.y + w[k+2]*hv.z + w[k+3]*hv.w;
        }
        gh_s[o] = gh;
        __syncthreads();
        if (o < 128) {
            const float* gi = (dir == 0) ? (g_gif + (size_t)(b*2 + t)*384)
                                         : (g_gi  + (size_t)(b*SS + t)*384);
            float ir = gi[o], iz = gi[128+o], inn = gi[256+o];
            float r = 1.f/(1.f+expf(-(ir + gh_s[o])));
            float z = 1.f/(1.f+expf(-(iz + gh_s[128+o])));
            float n = tanhf(inn + r*gh_s[256+o]);
            float hnew = (1.f-z)*n + z*h_s[o];
            if (dir == 0) {
                if (i2 == 0)      g_y[0*BB*128 + b*128 + o] = hnew;
                else if (i2 == 1) g_y[1*BB*128 + b*128 + o] = hnew;
            } else {
                if (i2 == SS-1)      g_y[2*BB*128 + b*128 + o] = hnew;
                else if (i2 == SS-2) g_y[3*BB*128 + b*128 + o] = hnew;
            }
            h_s[o] = hnew;
        }
        __syncthreads();
    }
}

__global__ void k_final(const float* __restrict__ Wo, const float* __restrict__ bo,
                        const float* __restrict__ rel_emb, const void* trg,
                        const float* __restrict__ l1W, const float* __restrict__ l1b,
                        const float* __restrict__ l2W, const float* __restrict__ l2b,
                        float* __restrict__ out)
{
    const int b = blockIdx.x, j = threadIdx.x;
    __shared__ float conv[128];
    __shared__ float s16[16];
    float hh = bo[j], ht = bo[j];
    const float* yf0 = g_y + 0*BB*128 + b*128;
    const float* yf1 = g_y + 1*BB*128 + b*128;
    const float* yb0 = g_y + 2*BB*128 + b*128;
    const float* yb1 = g_y + 3*BB*128 + b*128;
    for (int k = 0; k < 128; k++) {
        float wk = Wo[k*128 + j];
        hh += yf0[k]*wk; ht += yf1[k]*wk;
    }
    for (int k = 0; k < 128; k++) {
        float wk = Wo[(128+k)*128 + j];
        hh += yb0[k]*wk; ht += yb1[k]*wk;
    }
    hh = fmaxf(hh, 0.f); ht = fmaxf(ht, 0.f);
    int tr = ld_idx(trg, b, 1);
    conv[j] = tanhf(hh + rel_emb[tr*128 + j] - ht);
    __syncthreads();
    if (j < 16) {
        float s = l1b[j];
        for (int k = 0; k < 128; k++) s += conv[k]*l1W[k*16 + j];
        s16[j] = s;
    }
    __syncthreads();
    if (j == 0) {
        float o = l2b[0];
        for (int i = 0; i < 16; i++) o += s16[i]*l2W[i];
        out[b] = o;
    }
}

extern "C" void kernel_launch(void* const* d_in, const int* in_sizes, int n_in,
                              void* d_out, int out_size)
{
    const float* node_feat = (const float*)d_in[0];
    const float* rel_emb   = (const float*)d_in[1];
    const float* W_i_node  = (const float*)d_in[2];
    const float* W_i_edge  = (const float*)d_in[3];
    const float* W_att_in1 = (const float*)d_in[4];
    const float* W_att_in2 = (const float*)d_in[5];
    const float* W_h_node  = (const float*)d_in[6];
    const float* W_h_edge  = (const float*)d_in[7];
    const float* W_att1    = (const float*)d_in[8];
    const float* W_att2    = (const float*)d_in[9];
    const float* comm_W    = (const float*)d_in[10];
    const float* W_o       = (const float*)d_in[11];
    const float* b_o       = (const float*)d_in[12];
    const float* gru_bias  = (const float*)d_in[13];
    const float* gru_Wih   = (const float*)d_in[14];
    const float* gru_Whh   = (const float*)d_in[15];
    const float* gru_bih   = (const float*)d_in[16];
    const float* gru_bhh   = (const float*)d_in[17];
    const float* lin1_W    = (const float*)d_in[18];
    const float* lin1_b    = (const float*)d_in[19];
    const float* lin2_W    = (const float*)d_in[20];
    const float* lin2_b    = (const float*)d_in[21];
    const void*  src       = d_in[22];
    const void*  dst       = d_in[23];
    const void*  etype     = d_in[24];
    const void*  elabel    = d_in[25];
    const void*  trg       = d_in[26];
    float* out = (float*)d_out;

    float *ge_ie, *ge_me, *ge_in, *ge_P, *ge_D, *ge_U, *ge_mn, *ge_agg, *ge_V;
    float *ge_nodeh, *ge_msg, *ge_scr, *ge_gi, *ge_gif, *ge_msg2, *ge_WihT, *ge_Qrel, *ge_Qd;
    unsigned short *ge_Wh, *ge_Wl;
    cudaGetSymbolAddress((void**)&ge_ie, g_ie);
    cudaGetSymbolAddress((void**)&ge_me, g_me);
    cudaGetSymbolAddress((void**)&ge_in, g_in);
    cudaGetSymbolAddress((void**)&ge_P, g_P);
    cudaGetSymbolAddress((void**)&ge_D, g_D);
    cudaGetSymbolAddress((void**)&ge_U, g_U);
    cudaGetSymbolAddress((void**)&ge_mn, g_mn);
    cudaGetSymbolAddress((void**)&ge_agg, g_agg);
    cudaGetSymbolAddress((void**)&ge_V, g_V);
    cudaGetSymbolAddress((void**)&ge_nodeh, g_nodeh);
    cudaGetSymbolAddress((void**)&ge_msg, g_msg);
    cudaGetSymbolAddress((void**)&ge_scr, g_scr);
    cudaGetSymbolAddress((void**)&ge_gi, g_gi);
    cudaGetSymbolAddress((void**)&ge_gif, g_gif);
    cudaGetSymbolAddress((void**)&ge_msg2, g_msg2);
    cudaGetSymbolAddress((void**)&ge_WihT, g_WihT);
    cudaGetSymbolAddress((void**)&ge_Qrel, g_Qrel);
    cudaGetSymbolAddress((void**)&ge_Qd, g_Qd);
    cudaGetSymbolAddress((void**)&ge_Wh, g_Whg);
    cudaGetSymbolAddress((void**)&ge_Wl, g_Wlg);

    cudaFuncSetAttribute(k_edge_att_tc, cudaFuncAttributeMaxDynamicSharedMemorySize, SMEM_EA);

    k_detect<<<1, 32>>>(src, etype);

    // CSR of dst
    k_cnt_zero<<<NN/256, 256>>>();
    k_count<<<NE/256, 256>>>(dst);
    k_scan1<<<16, 1024>>>();
    k_scan2<<<1, 32>>>();
    k_scan3<<<NN/256, 256>>>();
    k_fill<<<NE/256, 256>>>(dst);

    // edge attention weights -> bf16 hi/lo, fragment-ready
    k_wconv<<<64, 256>>>(W_att_in1 + 128*128, ge_Wh,           ge_Wl);
    k_wconv<<<64, 256>>>(W_att1,              ge_Wh + 16384,   ge_Wl + 16384);
    k_wconv<<<64, 256>>>(W_att1 + 32768,      ge_Wh + 32768,   ge_Wl + 32768);

    // node-side GEMMs
    k_tgemm_bf<<<dim3(NN/128, 1), 256>>>(node_feat, W_i_edge,           ge_P, 64, 128, NULL, 0, 0);
    k_tgemm_bf<<<dim3(NN/128, 1), 256>>>(node_feat, W_i_edge + 192*128, ge_D, 64, 128, NULL, 0, 0);
    k_tgemm_bf<<<dim3(NN/128, 1), 256>>>(node_feat, W_i_node,           ge_in, 64, 128, NULL, 1, 0);
    // small rel_emb GEMMs
    k_sgemm<<<dim3(1,2), 256>>>(rel_emb, W_i_edge + 64*128,         ge_Qrel,        RR, 128, 128);
    k_sgemm<<<dim3(1,2), 256>>>(rel_emb, W_att1 + 128*128,          ge_Qd,          RR, 128, 128);
    k_sgemm<<<dim3(1,2), 256>>>(rel_emb, W_att1 + 32768 + 128*128,  ge_Qd + RR*128, RR, 128, 128);

    // fused edge_init + input attention (mode 2)
    k_tgemm_bf<<<dim3(NN/128, 1), 256>>>(ge_in, W_att_in1, ge_U, 128, 128, NULL, 0, 0);
    k_edge_att_tc<<<NE/128, 256, SMEM_EA>>>(NULL, ge_Wh, ge_Wl, ge_U, src, 0, src,
                                            W_att_in2, ge_ie, NULL, ge_me, 2,
                                            ge_P, ge_Qrel, ge_D, etype, dst, ge_ie);

    // two message-passing depths
    for (int d = 0; d < 2; d++) {
        const float* mn_old = (d == 0) ? ge_in : ge_mn;
        k_gather<<<NN, 128>>>(ge_me, mn_old, ge_scr);
        k_tgemm_bf<<<dim3(NN/128, 1), 256>>>(ge_scr, W_h_node + d*16384, ge_mn, 128, 128, NULL, 1, 0);
        k_tgemm_bf<<<dim3(NN/128, 1), 256>>>(ge_mn, W_h_edge + d*16384, ge_V, 128, 128, NULL, 0, 0);
        k_edge_att_tc<<<NE/128, 256, SMEM_EA>>>(ge_me, ge_Wh + (d+1)*16384, ge_Wl + (d+1)*16384,
                                                ge_Qd + d*RR*128, elabel, 1,
                                                src, W_att2 + d*128, ge_ie, ge_V, ge_me, 1,
                                                NULL, NULL, NULL, NULL, NULL, NULL);
    }

    // readout aggregation + comm
    k_gather<<<NN, 128>>>(ge_me, NULL, ge_agg);
    k_tgemm_bf<<<dim3(NN/128, 1), 256>>>(ge_agg, comm_W,           ge_nodeh, 128, 128, NULL, 0, 0);
    k_tgemm_bf<<<dim3(NN/128, 1), 256>>>(ge_mn,  comm_W + 128*128, ge_nodeh, 128, 128, NULL, 0, 1);
    k_tgemm_bf<<<dim3(NN/128, 1), 256>>>(ge_in,  comm_W + 256*128, ge_nodeh, 128, 128, NULL, 0, 1);

    // GRU
    k_msg<<<NN*128/256, 256>>>(gru_bias);
    k_h0<<<BB, 128>>>();
    k_twih<<<(2*384*128 + 255)/256, 256>>>(gru_Wih);
    k_msg2<<<128*128/256, 256>>>();
    k_tgemm_bf<<<dim3(1, 3), 256>>>(ge_msg2, ge_WihT,           ge_gif, 128, 384, gru_bih,       0, 0);
    k_tgemm_bf<<<dim3(NN/128, 3), 256>>>(ge_msg, ge_WihT + 384*128, ge_gi, 128, 384, gru_bih + 384, 0, 0);
    k_gru<<<dim3(BB, 2), 384>>>(gru_Whh, gru_bhh);

    k_final<<<BB, 128>>>(W_o, b_o, rel_emb, trg, lin1_W, lin1_b, lin2_W, lin2_b, out);
}

// round 9
// speedup vs baseline: 1.2447x; 1.2447x over previous
#include <cuda_runtime.h>
#include <cuda_bf16.h>
#include <math.h>

#define NN 16384
#define NE 262144
#define HH 128
#define BB 64
#define SS 256
#define RR 32

__device__ float g_ie[NE*HH];
__device__ float g_me[NE*HH];
__device__ float g_in[NN*HH];
__device__ float g_P[NN*HH];
__device__ float g_D[NN*HH];
__device__ float g_U[NN*HH];
__device__ float g_mn[NN*HH];
__device__ float g_agg[NN*HH];
__device__ float g_V[NN*HH];
__device__ float g_nodeh[NN*HH];
__device__ float g_msg[NN*HH];
__device__ float g_scr[NN*HH];
__device__ float g_gi[NN*384];
__device__ float g_gif[128*384];
__device__ float g_msg2[128*HH];
__device__ float g_WihT[2*384*128];
__device__ float g_Qrel[RR*HH];
__device__ float g_Qd[2*RR*HH];
__device__ float g_h0[BB*HH];
__device__ float g_y[4*BB*HH];
__device__ int   g_is64[2];
__device__ int   g_cnt[NN];
__device__ int   g_off[NN+1];
__device__ int   g_cur[NN];
__device__ int   g_eid[NE];
__device__ int   g_bsum[16], g_bpre[16];
__device__ unsigned short g_Whg[3*16384];
__device__ unsigned short g_Wlg[3*16384];

__device__ __forceinline__ int ld_idx(const void* p, long long i, int sel) {
    if (g_is64[sel]) return (int)((const long long*)p)[i];
    return ((const int*)p)[i];
}

__global__ void k_detect(const void* src, const void* et) {
    if (threadIdx.x == 0) {
        const unsigned long long* a = (const unsigned long long*)src;
        int v = 1;
        for (int i = 0; i < 8; i++) if (a[i] >= (unsigned long long)NN) v = 0;
        g_is64[0] = v;
        const unsigned long long* b = (const unsigned long long*)et;
        v = 1;
        for (int i = 0; i < 8; i++) if (b[i] >= (unsigned long long)RR) v = 0;
        g_is64[1] = v;
    }
}

// ---------- bf16 hi/lo helpers ----------
__device__ __forceinline__ void f2bf(float x, unsigned short& h, unsigned short& l) {
    __nv_bfloat16 bh = __float2bfloat16(x);
    h = __bfloat16_as_ushort(bh);
    l = __bfloat16_as_ushort(__float2bfloat16(x - __bfloat162float(bh)));
}

__device__ __forceinline__ void mma16(float* d, const unsigned* a, const unsigned* b) {
    asm volatile("mma.sync.aligned.m16n8k16.row.col.f32.bf16.bf16.f32 "
        "{%0,%1,%2,%3}, {%4,%5,%6,%7}, {%8,%9}, {%0,%1,%2,%3};"
        : "+f"(d[0]), "+f"(d[1]), "+f"(d[2]), "+f"(d[3])
        : "r"(a[0]), "r"(a[1]), "r"(a[2]), "r"(a[3]), "r"(b[0]), "r"(b[1]));
}

// weight pre-conversion: Wm fp32 [128][128] row-major -> Wh/Wl bf16 [c*128+k]
__global__ void k_wconv(const float* __restrict__ Wm,
                        unsigned short* __restrict__ Wh,
                        unsigned short* __restrict__ Wl)
{
    int t = blockIdx.x*256 + threadIdx.x;   // 16384
    int k = t >> 7, c = t & 127;
    unsigned short h, l;
    f2bf(Wm[k*128 + c], h, l);
    Wh[c*128 + k] = h;
    Wl[c*128 + k] = l;
}

#define APITCH 40
#define WPITCH 42

// ---------- bf16 3-split tensor-core GEMM ----------
__global__ void __launch_bounds__(256, 2) k_tgemm_bf(
    const float* __restrict__ A, const float* __restrict__ W, float* __restrict__ C,
    int K, int M, const float* __restrict__ bias, int doRelu, int accum)
{
    __shared__ unsigned short sAh[128*APITCH], sAl[128*APITCH];
    __shared__ unsigned short sWh[128*WPITCH], sWl[128*WPITCH];
    const int tid = threadIdx.x;
    const int w = tid >> 5, lane = tid & 31;
    const int g = lane >> 2, t = lane & 3;
    const int wr0 = (w >> 1) * 32, wc0 = (w & 1) * 64;
    const long long row0 = (long long)blockIdx.x * 128;
    const int col0 = blockIdx.y * 128;

    float acc[2][8][4];
#pragma unroll
    for (int a = 0; a < 2; a++)
#pragma unroll
        for (int b = 0; b < 8; b++)
#pragma unroll
            for (int c = 0; c < 4; c++) acc[a][b][c] = 0.f;

    for (int k0 = 0; k0 < K; k0 += 32) {
        __syncthreads();
#pragma unroll
        for (int i = 0; i < 4; i++) {
            int f = tid + 256 * i;
            int r = f >> 3, j = (f & 7) << 2;
            float4 v = *(const float4*)(A + (row0 + r) * K + k0 + j);
            unsigned short h, l;
            f2bf(v.x, h, l); sAh[r*APITCH+j+0] = h; sAl[r*APITCH+j+0] = l;
            f2bf(v.y, h, l); sAh[r*APITCH+j+1] = h; sAl[r*APITCH+j+1] = l;
            f2bf(v.z, h, l); sAh[r*APITCH+j+2] = h; sAl[r*APITCH+j+2] = l;
            f2bf(v.w, h, l); sAh[r*APITCH+j+3] = h; sAl[r*APITCH+j+3] = l;
        }
#pragma unroll
        for (int i = 0; i < 4; i++) {
            int f = tid + 256 * i;
            int kk = f >> 5, c = (f & 31) << 2;
            float4 v = *(const float4*)(W + (long long)(k0 + kk) * M + col0 + c);
            unsigned short h, l;
            f2bf(v.x, h, l); sWh[(c+0)*WPITCH+kk] = h; sWl[(c+0)*WPITCH+kk] = l;
            f2bf(v.y, h, l); sWh[(c+1)*WPITCH+kk] = h; sWl[(c+1)*WPITCH+kk] = l;
            f2bf(v.z, h, l); sWh[(c+2)*WPITCH+kk] = h; sWl[(c+2)*WPITCH+kk] = l;
            f2bf(v.w, h, l); sWh[(c+3)*WPITCH+kk] = h; sWl[(c+3)*WPITCH+kk] = l;
        }
        __syncthreads();
#pragma unroll
        for (int ks = 0; ks < 32; ks += 16) {
            unsigned ah[2][4], al[2][4];
#pragma unroll
            for (int mt = 0; mt < 2; mt++) {
                int rb = wr0 + mt * 16 + g;
                const unsigned short* p = &sAh[rb*APITCH + ks + 2*t];
                ah[mt][0] = *(const unsigned*)p;
                ah[mt][1] = *(const unsigned*)(p + 8*APITCH);
                ah[mt][2] = *(const unsigned*)(p + 8);
                ah[mt][3] = *(const unsigned*)(p + 8*APITCH + 8);
                const unsigned short* q = &sAl[rb*APITCH + ks + 2*t];
                al[mt][0] = *(const unsigned*)q;
                al[mt][1] = *(const unsigned*)(q + 8*APITCH);
                al[mt][2] = *(const unsigned*)(q + 8);
                al[mt][3] = *(const unsigned*)(q + 8*APITCH + 8);
            }
#pragma unroll
            for (int nt = 0; nt < 8; nt++) {
                int cn = wc0 + nt * 8 + g;
                unsigned bh[2], bl[2];
                const unsigned short* p = &sWh[cn*WPITCH + ks + 2*t];
                bh[0] = *(const unsigned*)p; bh[1] = *(const unsigned*)(p + 8);
                const unsigned short* q = &sWl[cn*WPITCH + ks + 2*t];
                bl[0] = *(const unsigned*)q; bl[1] = *(const unsigned*)(q + 8);
#pragma unroll
                for (int mt = 0; mt < 2; mt++) {
                    mma16(acc[mt][nt], ah[mt], bh);
                    mma16(acc[mt][nt], ah[mt], bl);
                    mma16(acc[mt][nt], al[mt], bh);
                }
            }
        }
    }
#pragma unroll
    for (int mt = 0; mt < 2; mt++) {
#pragma unroll
        for (int nt = 0; nt < 8; nt++) {
            int c = col0 + wc0 + nt * 8 + t * 2;
            long long r0 = row0 + wr0 + mt * 16 + g;
            float b0 = bias ? bias[c] : 0.f, b1 = bias ? bias[c+1] : 0.f;
            float v0 = acc[mt][nt][0] + b0, v1 = acc[mt][nt][1] + b1;
            float v2 = acc[mt][nt][2] + b0, v3 = acc[mt][nt][3] + b1;
            if (accum) {
                float2 o0 = *(const float2*)(C + r0 * M + c);
                float2 o1 = *(const float2*)(C + (r0 + 8) * M + c);
                v0 += o0.x; v1 += o0.y; v2 += o1.x; v3 += o1.y;
            }
            if (doRelu) {
                v0 = fmaxf(v0, 0.f); v1 = fmaxf(v1, 0.f);
                v2 = fmaxf(v2, 0.f); v3 = fmaxf(v3, 0.f);
            }
            *(float2*)(C + r0 * M + c)       = make_float2(v0, v1);
            *(float2*)(C + (r0 + 8) * M + c) = make_float2(v2, v3);
        }
    }
}

// ---------- small SIMT GEMM for 32-row rel_emb GEMMs ----------
__global__ void k_sgemm(const float* __restrict__ A, const float* __restrict__ W,
                        float* __restrict__ C, int rows, int K, int M)
{
    __shared__ float As[16][64];
    __shared__ float Ws[16][64];
    const int tid = threadIdx.x;
    const int tx = tid & 15, ty = tid >> 4;
    const int row0 = blockIdx.x * 64, col0 = blockIdx.y * 64;
    const int la_r = tid >> 2, la_k = (tid & 3) << 2;
    const int lw_k = tid >> 4, lw_c = (tid & 15) << 2;
    float acc[4][4];
#pragma unroll
    for (int i = 0; i < 4; i++)
#pragma unroll
        for (int j = 0; j < 4; j++) acc[i][j] = 0.f;
    for (int k0 = 0; k0 < K; k0 += 16) {
        float4 av = make_float4(0.f,0.f,0.f,0.f);
        if (row0 + la_r < rows)
            av = *(const float4*)(A + (size_t)(row0 + la_r) * K + (k0 + la_k));
        As[la_k+0][la_r] = av.x; As[la_k+1][la_r] = av.y;
        As[la_k+2][la_r] = av.z; As[la_k+3][la_r] = av.w;
        *(float4*)&Ws[lw_k][lw_c] = *(const float4*)(W + (size_t)(k0+lw_k)*M + col0 + lw_c);
        __syncthreads();
#pragma unroll
        for (int k = 0; k < 16; k++) {
            float4 a4 = *(const float4*)&As[k][ty<<2];
            float4 w4 = *(const float4*)&Ws[k][tx<<2];
            float ar[4] = {a4.x,a4.y,a4.z,a4.w};
            float wr[4] = {w4.x,w4.y,w4.z,w4.w};
#pragma unroll
            for (int i = 0; i < 4; i++)
#pragma unroll
                for (int j = 0; j < 4; j++) acc[i][j] += ar[i]*wr[j];
        }
        __syncthreads();
    }
#pragma unroll
    for (int i = 0; i < 4; i++) {
        int r = row0 + (ty<<2) + i;
        if (r < rows)
#pragma unroll
            for (int j = 0; j < 4; j++)
                C[(size_t)r*M + col0 + (tx<<2) + j] = acc[i][j];
    }
}

// ---------- bf16 tensor-core fused edge attention (round-7 structure, preconverted W) ----------
// mode 1: X = me;  out = relu(ie + a*V[src])
// mode 2: A = relu(P[src]+Q[et]+D[dst]) computed in-kernel, written to ie_out; out = ie * a
__global__ void __launch_bounds__(256, 2) k_edge_att_tc(
    const float* __restrict__ X,
    const unsigned short* __restrict__ Wh, const unsigned short* __restrict__ Wl,
    const float* __restrict__ addvec, const void* idx_add, int sel_add,
    const void* idx_src, const float* __restrict__ w2,
    const float* __restrict__ ie, const float* __restrict__ V,
    float* __restrict__ outp, int mode,
    const float* __restrict__ Pm, const float* __restrict__ Qm,
    const float* __restrict__ Dm, const void* idx_et, const void* idx_dst,
    float* __restrict__ ie_out)
{
    __shared__ unsigned short sAh[128*APITCH], sAl[128*APITCH];
    __shared__ unsigned short sWh[128*WPITCH], sWl[128*WPITCH];
    __shared__ int ia_s[128], is_s[128], iet_s[128], idd_s[128];
    __shared__ float a_s[128], part_s[256], w2_s[128];

    const int tid = threadIdx.x;
    const int w = tid >> 5, lane = tid & 31;
    const int g = lane >> 2, t = lane & 3;
    const int wr0 = (w >> 1) * 32, wc0 = (w & 1) * 64;
    const long long e0 = (long long)blockIdx.x * 128;

    if (tid < 128) {
        ia_s[tid] = ld_idx(idx_add, e0 + tid, sel_add);
        is_s[tid] = ld_idx(idx_src, e0 + tid, 0);
        w2_s[tid] = w2[tid];
        if (mode == 2) {
            iet_s[tid] = ld_idx(idx_et, e0 + tid, 1);
            idd_s[tid] = ld_idx(idx_dst, e0 + tid, 0);
        }
    }

    float acc[2][8][4];
#pragma unroll
    for (int a = 0; a < 2; a++)
#pragma unroll
        for (int b = 0; b < 8; b++)
#pragma unroll
            for (int c = 0; c < 4; c++) acc[a][b][c] = 0.f;

    for (int k0 = 0; k0 < 128; k0 += 32) {
        __syncthreads();
        if (mode == 2) {
#pragma unroll
            for (int i = 0; i < 4; i++) {
                int f = tid + 256 * i;
                int r = f >> 3, j = (f & 7) << 2;
                int s = is_s[r], et = iet_s[r], dd = idd_s[r];
                float4 p = *(const float4*)(Pm + (size_t)s*HH + k0 + j);
                float4 q = *(const float4*)(Qm + (size_t)et*HH + k0 + j);
                float4 dv = *(const float4*)(Dm + (size_t)dd*HH + k0 + j);
                float4 v;
                v.x = fmaxf(p.x+q.x+dv.x, 0.f); v.y = fmaxf(p.y+q.y+dv.y, 0.f);
                v.z = fmaxf(p.z+q.z+dv.z, 0.f); v.w = fmaxf(p.w+q.w+dv.w, 0.f);
                *(float4*)(ie_out + (e0 + r)*HH + k0 + j) = v;
                unsigned short h, l;
                f2bf(v.x, h, l); sAh[r*APITCH+j+0] = h; sAl[r*APITCH+j+0] = l;
                f2bf(v.y, h, l); sAh[r*APITCH+j+1] = h; sAl[r*APITCH+j+1] = l;
                f2bf(v.z, h, l); sAh[r*APITCH+j+2] = h; sAl[r*APITCH+j+2] = l;
                f2bf(v.w, h, l); sAh[r*APITCH+j+3] = h; sAl[r*APITCH+j+3] = l;
            }
        } else {
#pragma unroll
            for (int i = 0; i < 4; i++) {
                int f = tid + 256 * i;
                int r = f >> 3, j = (f & 7) << 2;
                float4 v = *(const float4*)(X + (e0 + r) * HH + k0 + j);
                unsigned short h, l;
                f2bf(v.x, h, l); sAh[r*APITCH+j+0] = h; sAl[r*APITCH+j+0] = l;
                f2bf(v.y, h, l); sAh[r*APITCH+j+1] = h; sAl[r*APITCH+j+1] = l;
                f2bf(v.z, h, l); sAh[r*APITCH+j+2] = h; sAl[r*APITCH+j+2] = l;
                f2bf(v.w, h, l); sAh[r*APITCH+j+3] = h; sAl[r*APITCH+j+3] = l;
            }
        }
        // W staging: plain ushort2 copies from pre-converted bf16 global arrays
#pragma unroll
        for (int i = 0; i < 8; i++) {
            int f = tid + 256 * i;           // 2048 ushort2 per array
            int cc = f >> 4, kk = (f & 15) << 1;
            *(ushort2*)&sWh[cc*WPITCH + kk] = *(const ushort2*)&Wh[cc*128 + k0 + kk];
            *(ushort2*)&sWl[cc*WPITCH + kk] = *(const ushort2*)&Wl[cc*128 + k0 + kk];
        }
        __syncthreads();
#pragma unroll
        for (int ks = 0; ks < 32; ks += 16) {
            unsigned ah[2][4], al[2][4];
#pragma unroll
            for (int mt = 0; mt < 2; mt++) {
                int rb = wr0 + mt * 16 + g;
                const unsigned short* p = &sAh[rb*APITCH + ks + 2*t];
                ah[mt][0] = *(const unsigned*)p;
                ah[mt][1] = *(const unsigned*)(p + 8*APITCH);
                ah[mt][2] = *(const unsigned*)(p + 8);
                ah[mt][3] = *(const unsigned*)(p + 8*APITCH + 8);
                const unsigned short* q = &sAl[rb*APITCH + ks + 2*t];
                al[mt][0] = *(const unsigned*)q;
                al[mt][1] = *(const unsigned*)(q + 8*APITCH);
                al[mt][2] = *(const unsigned*)(q + 8);
                al[mt][3] = *(const unsigned*)(q + 8*APITCH + 8);
            }
#pragma unroll
            for (int nt = 0; nt < 8; nt++) {
                int cn = wc0 + nt * 8 + g;
                unsigned bh[2], bl[2];
                const unsigned short* p = &sWh[cn*WPITCH + ks + 2*t];
                bh[0] = *(const unsigned*)p; bh[1] = *(const unsigned*)(p + 8);
                const unsigned short* q = &sWl[cn*WPITCH + ks + 2*t];
                bl[0] = *(const unsigned*)q; bl[1] = *(const unsigned*)(q + 8);
#pragma unroll
                for (int mt = 0; mt < 2; mt++) {
                    mma16(acc[mt][nt], ah[mt], bh);
                    mma16(acc[mt][nt], ah[mt], bl);
                    mma16(acc[mt][nt], al[mt], bh);
                }
            }
        }
    }

    // attention scalar
#pragma unroll
    for (int mt = 0; mt < 2; mt++) {
        int r0 = wr0 + mt * 16 + g, r1 = r0 + 8;
        const float2* ar0 = (const float2*)(addvec + (size_t)ia_s[r0] * HH);
        const float2* ar1 = (const float2*)(addvec + (size_t)ia_s[r1] * HH);
        float p0 = 0.f, p1 = 0.f;
#pragma unroll
        for (int nt = 0; nt < 8; nt++) {
            int c = wc0 + nt * 8 + t * 2;
            float w0 = w2_s[c], w1 = w2_s[c+1];
            float2 a0 = ar0[c >> 1], a1 = ar1[c >> 1];
            p0 += fmaxf(acc[mt][nt][0] + a0.x, 0.f) * w0
                + fmaxf(acc[mt][nt][1] + a0.y, 0.f) * w1;
            p1 += fmaxf(acc[mt][nt][2] + a1.x, 0.f) * w0
                + fmaxf(acc[mt][nt][3] + a1.y, 0.f) * w1;
        }
        p0 += __shfl_xor_sync(0xffffffffu, p0, 1);
        p0 += __shfl_xor_sync(0xffffffffu, p0, 2);
        p1 += __shfl_xor_sync(0xffffffffu, p1, 1);
        p1 += __shfl_xor_sync(0xffffffffu, p1, 2);
        if (t == 0) {
            part_s[r0 * 2 + (w & 1)] = p0;
            part_s[r1 * 2 + (w & 1)] = p1;
        }
    }
    __syncthreads();
    if (tid < 128) {
        float ps = part_s[tid * 2] + part_s[tid * 2 + 1];
        a_s[tid] = 1.f / (1.f + expf(-ps));
    }
    __syncthreads();

    // output epilogue
#pragma unroll
    for (int i = 0; i < 16; i++) {
        int f = tid + 256 * i;
        int r = f >> 5, q = (f & 31) << 2;
        size_t base = (size_t)(e0 + r) * HH + q;
        float4 iv = *(const float4*)(ie + base);
        float a = a_s[r];
        float4 o;
        if (mode == 1) {
            float4 v4 = *(const float4*)(V + (size_t)is_s[r] * HH + q);
            o.x = fmaxf(iv.x + a*v4.x, 0.f); o.y = fmaxf(iv.y + a*v4.y, 0.f);
            o.z = fmaxf(iv.z + a*v4.z, 0.f); o.w = fmaxf(iv.w + a*v4.w, 0.f);
        } else {
            o = make_float4(iv.x*a, iv.y*a, iv.z*a, iv.w*a);
        }
        *(float4*)(outp + base) = o;
    }
}

// ---------- CSR build ----------
__global__ void k_cnt_zero() {
    int t = blockIdx.x*256 + threadIdx.x;
    if (t < NN) g_cnt[t] = 0;
}
__global__ void k_count(const void* dstp) {
    int e = blockIdx.x*256 + threadIdx.x;
    if (e < NE) atomicAdd(&g_cnt[ld_idx(dstp, e, 0)], 1);
}
__global__ void __launch_bounds__(1024) k_scan1() {
    __shared__ int wsum[32];
    int b = blockIdx.x, t = threadIdx.x;
    int lane = t & 31, wid = t >> 5;
    int v = g_cnt[b*1024 + t];
    int orig = v;
#pragma unroll
    for (int off = 1; off < 32; off <<= 1) {
        int u = __shfl_up_sync(0xffffffffu, v, off);
        if (lane >= off) v += u;
    }
    if (lane == 31) wsum[wid] = v;
    __syncthreads();
    if (wid == 0) {
        int y = wsum[lane];
#pragma unroll
        for (int off = 1; off < 32; off <<= 1) {
            int u = __shfl_up_sync(0xffffffffu, y, off);
            if (lane >= off) y += u;
        }
        wsum[lane] = y;
    }
    __syncthreads();
    int incl = v + (wid ? wsum[wid-1] : 0);
    g_off[b*1024 + t] = incl - orig;
    if (t == 1023) g_bsum[b] = incl;
}
__global__ void k_scan2() {
    int t = threadIdx.x;
    int v = (t < 16) ? g_bsum[t] : 0;
    int x = v;
#pragma unroll
    for (int off = 1; off < 32; off <<= 1) {
        int u = __shfl_up_sync(0xffffffffu, x, off);
        if (t >= off) x += u;
    }
    if (t < 16) g_bpre[t] = x - v;
    if (t == 15) g_off[NN] = x;
}
__global__ void k_scan3() {
    int i = blockIdx.x*256 + threadIdx.x;
    if (i < NN) {
        int o = g_off[i] + g_bpre[i >> 10];
        g_off[i] = o;
        g_cur[i] = o;
    }
}
__global__ void k_fill(const void* dstp) {
    int e = blockIdx.x*256 + threadIdx.x;
    if (e < NE) {
        int d = ld_idx(dstp, e, 0);
        int pos = atomicAdd(&g_cur[d], 1);
        g_eid[pos] = e;
    }
}

// ---------- CSR gather aggregation ----------
__global__ void __launch_bounds__(128) k_gather(const float* __restrict__ me,
                                                const float* __restrict__ addb,
                                                float* __restrict__ out)
{
    int n = blockIdx.x, j = threadIdx.x;
    int o0 = g_off[n], o1 = g_off[n+1];
    float s = addb ? addb[(size_t)n*HH + j] : 0.f;
    for (int i = o0; i < o1; i++) {
        int e = g_eid[i];
        s += me[(size_t)e*HH + j];
    }
    out[(size_t)n*HH + j] = s;
}

// ---------- GRU prep ----------
__global__ void k_msg(const float* __restrict__ gru_bias) {
    int t = blockIdx.x*256 + threadIdx.x;
    g_msg[t] = fmaxf(g_nodeh[t] + gru_bias[t & 127], 0.f);
}
__global__ void k_h0() {
    int b = blockIdx.x, j = threadIdx.x;
    float m = -1e30f;
    for (int s = 0; s < SS; s++)
        m = fmaxf(m, g_nodeh[((size_t)(b*SS + s))*HH + j]);
    g_h0[b*HH + j] = m;
}
__global__ void k_twih(const float* __restrict__ Wih) {
    int t = blockIdx.x*256 + threadIdx.x;
    if (t < 2*384*128) {
        int d = t / (384*128), rem = t % (384*128);
        int o = rem / 128, k = rem % 128;
        g_WihT[d*384*128 + k*384 + o] = Wih[t];
    }
}
__global__ void k_msg2() {
    int t = blockIdx.x*256 + threadIdx.x;
    int r = t >> 7, j = t & 127;
    int b = r >> 1, s = r & 1;
    g_msg2[t] = g_msg[((size_t)(b*SS + s))*HH + j];
}

__global__ void __launch_bounds__(384) k_gru(const float* __restrict__ Whh,
                                             const float* __restrict__ bhh)
{
    const int b = blockIdx.x, dir = blockIdx.y;
    const int o = threadIdx.x;
    float w[128];
    const float* wr = Whh + ((size_t)dir*384 + o)*128;
#pragma unroll
    for (int k = 0; k < 128; k += 4) {
        float4 v = *(const float4*)(wr + k);
        w[k]=v.x; w[k+1]=v.y; w[k+2]=v.z; w[k+3]=v.w;
    }
    const float bh = bhh[dir*384 + o];
    __shared__ float h_s[128];
    __shared__ float gh_s[384];
    if (o < 128) h_s[o] = g_h0[b*128 + o];
    __syncthreads();
    const int nsteps = (dir == 0) ? 2 : SS;
    for (int i2 = 0; i2 < nsteps; i2++) {
        int t = (dir == 0) ? i2 : (SS - 1 - i2);
        float gh = bh;
#pragma unroll
        for (int k = 0; k < 128; k += 4) {
            float4 hv = *(const float4*)&h_s[k];
            gh += w[k]*hv.x + w[k+1]*hv.y + w[k+2]*hv.z + w[k+3]*hv.w;
        }
        gh_s[o] = gh;
        __syncthreads();
        if (o < 128) {
            const float* gi = (dir == 0) ? (g_gif + (size_t)(b*2 + t)*384)
                                         : (g_gi  + (size_t)(b*SS + t)*384);
            float ir = gi[o], iz = gi[128+o], inn = gi[256+o];
            float r = 1.f/(1.f+expf(-(ir + gh_s[o])));
            float z = 1.f/(1.f+expf(-(iz + gh_s[128+o])));
            float n = tanhf(inn + r*gh_s[256+o]);
            float hnew = (1.f-z)*n + z*h_s[o];
            if (dir == 0) {
                if (i2 == 0)      g_y[0*BB*128 + b*128 + o] = hnew;
                else if (i2 == 1) g_y[1*BB*128 + b*128 + o] = hnew;
            } else {
                if (i2 == SS-1)      g_y[2*BB*128 + b*128 + o] = hnew;
                else if (i2 == SS-2) g_y[3*BB*128 + b*128 + o] = hnew;
            }
            h_s[o] = hnew;
        }
        __syncthreads();
    }
}

__global__ void k_final(const float* __restrict__ Wo, const float* __restrict__ bo,
                        const float* __restrict__ rel_emb, const void* trg,
                        const float* __restrict__ l1W, const float* __restrict__ l1b,
                        const float* __restrict__ l2W, const float* __restrict__ l2b,
                        float* __restrict__ out)
{
    const int b = blockIdx.x, j = threadIdx.x;
    __shared__ float conv[128];
    __shared__ float s16[16];
    float hh = bo[j], ht = bo[j];
    const float* yf0 = g_y + 0*BB*128 + b*128;
    const float* yf1 = g_y + 1*BB*128 + b*128;
    const float* yb0 = g_y + 2*BB*128 + b*128;
    const float* yb1 = g_y + 3*BB*128 + b*128;
    for (int k = 0; k < 128; k++) {
        float wk = Wo[k*128 + j];
        hh += yf0[k]*wk; ht += yf1[k]*wk;
    }
    for (int k = 0; k < 128; k++) {
        float wk = Wo[(128+k)*128 + j];
        hh += yb0[k]*wk; ht += yb1[k]*wk;
    }
    hh = fmaxf(hh, 0.f); ht = fmaxf(ht, 0.f);
    int tr = ld_idx(trg, b, 1);
    conv[j] = tanhf(hh + rel_emb[tr*128 + j] - ht);
    __syncthreads();
    if (j < 16) {
        float s = l1b[j];
        for (int k = 0; k < 128; k++) s += conv[k]*l1W[k*16 + j];
        s16[j] = s;
    }
    __syncthreads();
    if (j == 0) {
        float o = l2b[0];
        for (int i = 0; i < 16; i++) o += s16[i]*l2W[i];
        out[b] = o;
    }
}

extern "C" void kernel_launch(void* const* d_in, const int* in_sizes, int n_in,
                              void* d_out, int out_size)
{
    const float* node_feat = (const float*)d_in[0];
    const float* rel_emb   = (const float*)d_in[1];
    const float* W_i_node  = (const float*)d_in[2];
    const float* W_i_edge  = (const float*)d_in[3];
    const float* W_att_in1 = (const float*)d_in[4];
    const float* W_att_in2 = (const float*)d_in[5];
    const float* W_h_node  = (const float*)d_in[6];
    const float* W_h_edge  = (const float*)d_in[7];
    const float* W_att1    = (const float*)d_in[8];
    const float* W_att2    = (const float*)d_in[9];
    const float* comm_W    = (const float*)d_in[10];
    const float* W_o       = (const float*)d_in[11];
    const float* b_o       = (const float*)d_in[12];
    const float* gru_bias  = (const float*)d_in[13];
    const float* gru_Wih   = (const float*)d_in[14];
    const float* gru_Whh   = (const float*)d_in[15];
    const float* gru_bih   = (const float*)d_in[16];
    const float* gru_bhh   = (const float*)d_in[17];
    const float* lin1_W    = (const float*)d_in[18];
    const float* lin1_b    = (const float*)d_in[19];
    const float* lin2_W    = (const float*)d_in[20];
    const float* lin2_b    = (const float*)d_in[21];
    const void*  src       = d_in[22];
    const void*  dst       = d_in[23];
    const void*  etype     = d_in[24];
    const void*  elabel    = d_in[25];
    const void*  trg       = d_in[26];
    float* out = (float*)d_out;

    float *ge_ie, *ge_me, *ge_in, *ge_P, *ge_D, *ge_U, *ge_mn, *ge_agg, *ge_V;
    float *ge_nodeh, *ge_msg, *ge_scr, *ge_gi, *ge_gif, *ge_msg2, *ge_WihT, *ge_Qrel, *ge_Qd;
    unsigned short *ge_Wh, *ge_Wl;
    cudaGetSymbolAddress((void**)&ge_ie, g_ie);
    cudaGetSymbolAddress((void**)&ge_me, g_me);
    cudaGetSymbolAddress((void**)&ge_in, g_in);
    cudaGetSymbolAddress((void**)&ge_P, g_P);
    cudaGetSymbolAddress((void**)&ge_D, g_D);
    cudaGetSymbolAddress((void**)&ge_U, g_U);
    cudaGetSymbolAddress((void**)&ge_mn, g_mn);
    cudaGetSymbolAddress((void**)&ge_agg, g_agg);
    cudaGetSymbolAddress((void**)&ge_V, g_V);
    cudaGetSymbolAddress((void**)&ge_nodeh, g_nodeh);
    cudaGetSymbolAddress((void**)&ge_msg, g_msg);
    cudaGetSymbolAddress((void**)&ge_scr, g_scr);
    cudaGetSymbolAddress((void**)&ge_gi, g_gi);
    cudaGetSymbolAddress((void**)&ge_gif, g_gif);
    cudaGetSymbolAddress((void**)&ge_msg2, g_msg2);
    cudaGetSymbolAddress((void**)&ge_WihT, g_WihT);
    cudaGetSymbolAddress((void**)&ge_Qrel, g_Qrel);
    cudaGetSymbolAddress((void**)&ge_Qd, g_Qd);
    cudaGetSymbolAddress((void**)&ge_Wh, g_Whg);
    cudaGetSymbolAddress((void**)&ge_Wl, g_Wlg);

    k_detect<<<1, 32>>>(src, etype);

    // CSR of dst
    k_cnt_zero<<<NN/256, 256>>>();
    k_count<<<NE/256, 256>>>(dst);
    k_scan1<<<16, 1024>>>();
    k_scan2<<<1, 32>>>();
    k_scan3<<<NN/256, 256>>>();
    k_fill<<<NE/256, 256>>>(dst);

    // edge attention weights -> bf16 hi/lo, fragment-ready
    k_wconv<<<64, 256>>>(W_att_in1 + 128*128, ge_Wh,           ge_Wl);
    k_wconv<<<64, 256>>>(W_att1,              ge_Wh + 16384,   ge_Wl + 16384);
    k_wconv<<<64, 256>>>(W_att1 + 32768,      ge_Wh + 32768,   ge_Wl + 32768);

    // node-side GEMMs
    k_tgemm_bf<<<dim3(NN/128, 1), 256>>>(node_feat, W_i_edge,           ge_P, 64, 128, NULL, 0, 0);
    k_tgemm_bf<<<dim3(NN/128, 1), 256>>>(node_feat, W_i_edge + 192*128, ge_D, 64, 128, NULL, 0, 0);
    k_tgemm_bf<<<dim3(NN/128, 1), 256>>>(node_feat, W_i_node,           ge_in, 64, 128, NULL, 1, 0);
    // small rel_emb GEMMs
    k_sgemm<<<dim3(1,2), 256>>>(rel_emb, W_i_edge + 64*128,         ge_Qrel,        RR, 128, 128);
    k_sgemm<<<dim3(1,2), 256>>>(rel_emb, W_att1 + 128*128,          ge_Qd,          RR, 128, 128);
    k_sgemm<<<dim3(1,2), 256>>>(rel_emb, W_att1 + 32768 + 128*128,  ge_Qd + RR*128, RR, 128, 128);

    // fused edge_init + input attention (mode 2)
    k_tgemm_bf<<<dim3(NN/128, 1), 256>>>(ge_in, W_att_in1, ge_U, 128, 128, NULL, 0, 0);
    k_edge_att_tc<<<NE/128, 256>>>(NULL, ge_Wh, ge_Wl, ge_U, src, 0, src,
                                   W_att_in2, ge_ie, NULL, ge_me, 2,
                                   ge_P, ge_Qrel, ge_D, etype, dst, ge_ie);

    // two message-passing depths
    for (int d = 0; d < 2; d++) {
        const float* mn_old = (d == 0) ? ge_in : ge_mn;
        k_gather<<<NN, 128>>>(ge_me, mn_old, ge_scr);
        k_tgemm_bf<<<dim3(NN/128, 1), 256>>>(ge_scr, W_h_node + d*16384, ge_mn, 128, 128, NULL, 1, 0);
        k_tgemm_bf<<<dim3(NN/128, 1), 256>>>(ge_mn, W_h_edge + d*16384, ge_V, 128, 128, NULL, 0, 0);
        k_edge_att_tc<<<NE/128, 256>>>(ge_me, ge_Wh + (d+1)*16384, ge_Wl + (d+1)*16384,
                                       ge_Qd + d*RR*128, elabel, 1,
                                       src, W_att2 + d*128, ge_ie, ge_V, ge_me, 1,
                                       NULL, NULL, NULL, NULL, NULL, NULL);
    }

    // readout aggregation + comm
    k_gather<<<NN, 128>>>(ge_me, NULL, ge_agg);
    k_tgemm_bf<<<dim3(NN/128, 1), 256>>>(ge_agg, comm_W,           ge_nodeh, 128, 128, NULL, 0, 0);
    k_tgemm_bf<<<dim3(NN/128, 1), 256>>>(ge_mn,  comm_W + 128*128, ge_nodeh, 128, 128, NULL, 0, 1);
    k_tgemm_bf<<<dim3(NN/128, 1), 256>>>(ge_in,  comm_W + 256*128, ge_nodeh, 128, 128, NULL, 0, 1);

    // GRU
    k_msg<<<NN*128/256, 256>>>(gru_bias);
    k_h0<<<BB, 128>>>();
    k_twih<<<(2*384*128 + 255)/256, 256>>>(gru_Wih);
    k_msg2<<<128*128/256, 256>>>();
    k_tgemm_bf<<<dim3(1, 3), 256>>>(ge_msg2, ge_WihT,           ge_gif, 128, 384, gru_bih,       0, 0);
    k_tgemm_bf<<<dim3(NN/128, 3), 256>>>(ge_msg, ge_WihT + 384*128, ge_gi, 128, 384, gru_bih + 384, 0, 0);
    k_gru<<<dim3(BB, 2), 384>>>(gru_Whh, gru_bhh);

    k_final<<<BB, 128>>>(W_o, b_o, rel_emb, trg, lin1_W, lin1_b, lin2_W, lin2_b, out);
}

// round 11
// speedup vs baseline: 1.2594x; 1.0119x over previous
#include <cuda_runtime.h>
#include <cuda_bf16.h>
#include <math.h>

#define NN 16384
#define NE 262144
#define HH 128
#define BB 64
#define SS 256
#define RR 32

__device__ float g_ie[NE*HH];
__device__ float g_me[NE*HH];
__device__ float g_in[NN*HH];
__device__ float g_P[NN*HH];
__device__ float g_D[NN*HH];
__device__ float g_U[NN*HH];
__device__ float g_mn[NN*HH];
__device__ float g_agg[NN*HH];
__device__ float g_V[NN*HH];
__device__ float g_nodeh[NN*HH];
__device__ float g_msg[NN*HH];
__device__ float g_scr[NN*HH];
__device__ float g_gi[NN*384];
__device__ float g_gif[128*384];
__device__ float g_msg2[128*HH];
__device__ float g_WihT[2*384*128];
__device__ float g_Qrel[RR*HH];
__device__ float g_Qd[2*RR*HH];
__device__ float g_h0[BB*HH];
__device__ float g_y[4*BB*HH];
__device__ int   g_is64[2];
__device__ int   g_cnt[NN];
__device__ int   g_off[NN+1];
__device__ int   g_cur[NN];
__device__ int   g_eid[NE];
__device__ int   g_bsum[16], g_bpre[16];
__device__ unsigned short g_Whg[3*16384];
__device__ unsigned short g_Wlg[3*16384];

__device__ __forceinline__ int ld_idx(const void* p, long long i, int sel) {
    if (g_is64[sel]) return (int)((const long long*)p)[i];
    return ((const int*)p)[i];
}

__global__ void k_detect(const void* src, const void* et) {
    if (threadIdx.x == 0) {
        const unsigned long long* a = (const unsigned long long*)src;
        int v = 1;
        for (int i = 0; i < 8; i++) if (a[i] >= (unsigned long long)NN) v = 0;
        g_is64[0] = v;
        const unsigned long long* b = (const unsigned long long*)et;
        v = 1;
        for (int i = 0; i < 8; i++) if (b[i] >= (unsigned long long)RR) v = 0;
        g_is64[1] = v;
    }
}

// ---------- bf16 hi/lo helpers ----------
__device__ __forceinline__ void f2bf(float x, unsigned short& h, unsigned short& l) {
    __nv_bfloat16 bh = __float2bfloat16(x);
    h = __bfloat16_as_ushort(bh);
    l = __bfloat16_as_ushort(__float2bfloat16(x - __bfloat162float(bh)));
}

__device__ __forceinline__ void mma16(float* d, const unsigned* a, const unsigned* b) {
    asm volatile("mma.sync.aligned.m16n8k16.row.col.f32.bf16.bf16.f32 "
        "{%0,%1,%2,%3}, {%4,%5,%6,%7}, {%8,%9}, {%0,%1,%2,%3};"
        : "+f"(d[0]), "+f"(d[1]), "+f"(d[2]), "+f"(d[3])
        : "r"(a[0]), "r"(a[1]), "r"(a[2]), "r"(a[3]), "r"(b[0]), "r"(b[1]));
}

__device__ __forceinline__ void cp16(const void* smem_dst, const void* gsrc) {
    unsigned d = (unsigned)__cvta_generic_to_shared(smem_dst);
    asm volatile("cp.async.cg.shared.global [%0], [%1], 16;" :: "r"(d), "l"(gsrc));
}

// weight pre-conversion: Wm fp32 [128][128] row-major -> Wh/Wl bf16 [c*128+k]
__global__ void k_wconv(const float* __restrict__ Wm,
                        unsigned short* __restrict__ Wh,
                        unsigned short* __restrict__ Wl)
{
    int t = blockIdx.x*256 + threadIdx.x;   // 16384
    int k = t >> 7, c = t & 127;
    unsigned short h, l;
    f2bf(Wm[k*128 + c], h, l);
    Wh[c*128 + k] = h;
    Wl[c*128 + k] = l;
}

#define APITCH 40
#define WPITCH 42
#define WPIT2 40
#define A32PITCH 36
// dynamic smem: A32 dbl (2*4608 floats = 36864B), Wh dbl (2*5120 us = 20480B), Wl dbl
#define DYN_WH_OFF 36864
#define DYN_WL_OFF 57344
#define DYN_BYTES  77824

// ---------- bf16 3-split tensor-core GEMM ----------
__global__ void __launch_bounds__(256, 2) k_tgemm_bf(
    const float* __restrict__ A, const float* __restrict__ W, float* __restrict__ C,
    int K, int M, const float* __restrict__ bias, int doRelu, int accum)
{
    __shared__ unsigned short sAh[128*APITCH], sAl[128*APITCH];
    __shared__ unsigned short sWh[128*WPITCH], sWl[128*WPITCH];
    const int tid = threadIdx.x;
    const int w = tid >> 5, lane = tid & 31;
    const int g = lane >> 2, t = lane & 3;
    const int wr0 = (w >> 1) * 32, wc0 = (w & 1) * 64;
    const long long row0 = (long long)blockIdx.x * 128;
    const int col0 = blockIdx.y * 128;

    float acc[2][8][4];
#pragma unroll
    for (int a = 0; a < 2; a++)
#pragma unroll
        for (int b = 0; b < 8; b++)
#pragma unroll
            for (int c = 0; c < 4; c++) acc[a][b][c] = 0.f;

    for (int k0 = 0; k0 < K; k0 += 32) {
        __syncthreads();
#pragma unroll
        for (int i = 0; i < 4; i++) {
            int f = tid + 256 * i;
            int r = f >> 3, j = (f & 7) << 2;
            float4 v = *(const float4*)(A + (row0 + r) * K + k0 + j);
            unsigned short h, l;
            f2bf(v.x, h, l); sAh[r*APITCH+j+0] = h; sAl[r*APITCH+j+0] = l;
            f2bf(v.y, h, l); sAh[r*APITCH+j+1] = h; sAl[r*APITCH+j+1] = l;
            f2bf(v.z, h, l); sAh[r*APITCH+j+2] = h; sAl[r*APITCH+j+2] = l;
            f2bf(v.w, h, l); sAh[r*APITCH+j+3] = h; sAl[r*APITCH+j+3] = l;
        }
#pragma unroll
        for (int i = 0; i < 4; i++) {
            int f = tid + 256 * i;
            int kk = f >> 5, c = (f & 31) << 2;
            float4 v = *(const float4*)(W + (long long)(k0 + kk) * M + col0 + c);
            unsigned short h, l;
            f2bf(v.x, h, l); sWh[(c+0)*WPITCH+kk] = h; sWl[(c+0)*WPITCH+kk] = l;
            f2bf(v.y, h, l); sWh[(c+1)*WPITCH+kk] = h; sWl[(c+1)*WPITCH+kk] = l;
            f2bf(v.z, h, l); sWh[(c+2)*WPITCH+kk] = h; sWl[(c+2)*WPITCH+kk] = l;
            f2bf(v.w, h, l); sWh[(c+3)*WPITCH+kk] = h; sWl[(c+3)*WPITCH+kk] = l;
        }
        __syncthreads();
#pragma unroll
        for (int ks = 0; ks < 32; ks += 16) {
            unsigned ah[2][4], al[2][4];
#pragma unroll
            for (int mt = 0; mt < 2; mt++) {
                int rb = wr0 + mt * 16 + g;
                const unsigned short* p = &sAh[rb*APITCH + ks + 2*t];
                ah[mt][0] = *(const unsigned*)p;
                ah[mt][1] = *(const unsigned*)(p + 8*APITCH);
                ah[mt][2] = *(const unsigned*)(p + 8);
                ah[mt][3] = *(const unsigned*)(p + 8*APITCH + 8);
                const unsigned short* q = &sAl[rb*APITCH + ks + 2*t];
                al[mt][0] = *(const unsigned*)q;
                al[mt][1] = *(const unsigned*)(q + 8*APITCH);
                al[mt][2] = *(const unsigned*)(q + 8);
                al[mt][3] = *(const unsigned*)(q + 8*APITCH + 8);
            }
#pragma unroll
            for (int nt = 0; nt < 8; nt++) {
                int cn = wc0 + nt * 8 + g;
                unsigned bh[2], bl[2];
                const unsigned short* p = &sWh[cn*WPITCH + ks + 2*t];
                bh[0] = *(const unsigned*)p; bh[1] = *(const unsigned*)(p + 8);
                const unsigned short* q = &sWl[cn*WPITCH + ks + 2*t];
                bl[0] = *(const unsigned*)q; bl[1] = *(const unsigned*)(q + 8);
#pragma unroll
                for (int mt = 0; mt < 2; mt++) {
                    mma16(acc[mt][nt], ah[mt], bh);
                    mma16(acc[mt][nt], ah[mt], bl);
                    mma16(acc[mt][nt], al[mt], bh);
                }
            }
        }
    }
#pragma unroll
    for (int mt = 0; mt < 2; mt++) {
#pragma unroll
        for (int nt = 0; nt < 8; nt++) {
            int c = col0 + wc0 + nt * 8 + t * 2;
            long long r0 = row0 + wr0 + mt * 16 + g;
            float b0 = bias ? bias[c] : 0.f, b1 = bias ? bias[c+1] : 0.f;
            float v0 = acc[mt][nt][0] + b0, v1 = acc[mt][nt][1] + b1;
            float v2 = acc[mt][nt][2] + b0, v3 = acc[mt][nt][3] + b1;
            if (accum) {
                float2 o0 = *(const float2*)(C + r0 * M + c);
                float2 o1 = *(const float2*)(C + (r0 + 8) * M + c);
                v0 += o0.x; v1 += o0.y; v2 += o1.x; v3 += o1.y;
            }
            if (doRelu) {
                v0 = fmaxf(v0, 0.f); v1 = fmaxf(v1, 0.f);
                v2 = fmaxf(v2, 0.f); v3 = fmaxf(v3, 0.f);
            }
            *(float2*)(C + r0 * M + c)       = make_float2(v0, v1);
            *(float2*)(C + (r0 + 8) * M + c) = make_float2(v2, v3);
        }
    }
}

// ---------- small SIMT GEMM for 32-row rel_emb GEMMs ----------
__global__ void k_sgemm(const float* __restrict__ A, const float* __restrict__ W,
                        float* __restrict__ C, int rows, int K, int M)
{
    __shared__ float As[16][64];
    __shared__ float Ws[16][64];
    const int tid = threadIdx.x;
    const int tx = tid & 15, ty = tid >> 4;
    const int row0 = blockIdx.x * 64, col0 = blockIdx.y * 64;
    const int la_r = tid >> 2, la_k = (tid & 3) << 2;
    const int lw_k = tid >> 4, lw_c = (tid & 15) << 2;
    float acc[4][4];
#pragma unroll
    for (int i = 0; i < 4; i++)
#pragma unroll
        for (int j = 0; j < 4; j++) acc[i][j] = 0.f;
    for (int k0 = 0; k0 < K; k0 += 16) {
        float4 av = make_float4(0.f,0.f,0.f,0.f);
        if (row0 + la_r < rows)
            av = *(const float4*)(A + (size_t)(row0 + la_r) * K + (k0 + la_k));
        As[la_k+0][la_r] = av.x; As[la_k+1][la_r] = av.y;
        As[la_k+2][la_r] = av.z; As[la_k+3][la_r] = av.w;
        *(float4*)&Ws[lw_k][lw_c] = *(const float4*)(W + (size_t)(k0+lw_k)*M + col0 + lw_c);
        __syncthreads();
#pragma unroll
        for (int k = 0; k < 16; k++) {
            float4 a4 = *(const float4*)&As[k][ty<<2];
            float4 w4 = *(const float4*)&Ws[k][tx<<2];
            float ar[4] = {a4.x,a4.y,a4.z,a4.w};
            float wr[4] = {w4.x,w4.y,w4.z,w4.w};
#pragma unroll
            for (int i = 0; i < 4; i++)
#pragma unroll
                for (int j = 0; j < 4; j++) acc[i][j] += ar[i]*wr[j];
        }
        __syncthreads();
    }
#pragma unroll
    for (int i = 0; i < 4; i++) {
        int r = row0 + (ty<<2) + i;
        if (r < rows)
#pragma unroll
            for (int j = 0; j < 4; j++)
                C[(size_t)r*M + col0 + (tx<<2) + j] = acc[i][j];
    }
}

// ---------- bf16 tensor-core fused edge attention, cp.async double-buffered (race-fixed) ----------
// mode 1: X = me;  out = relu(ie + a*V[src])
// mode 2: A = relu(P[src]+Q[et]+D[dst]) computed in-kernel, written to ie_out; out = ie * a
__global__ void __launch_bounds__(256, 2) k_edge_att_tc(
    const float* __restrict__ X,
    const unsigned short* __restrict__ Wh, const unsigned short* __restrict__ Wl,
    const float* __restrict__ addvec, const void* idx_add, int sel_add,
    const void* idx_src, const float* __restrict__ w2,
    const float* __restrict__ ie, const float* __restrict__ V,
    float* __restrict__ outp, int mode,
    const float* __restrict__ Pm, const float* __restrict__ Qm,
    const float* __restrict__ Dm, const void* idx_et, const void* idx_dst,
    float* __restrict__ ie_out)
{
    extern __shared__ char dynsm[];
    float* pA32 = (float*)dynsm;                                   // 2 x 4608 floats
    unsigned short* pWh = (unsigned short*)(dynsm + DYN_WH_OFF);   // 2 x 5120
    unsigned short* pWl = (unsigned short*)(dynsm + DYN_WL_OFF);   // 2 x 5120
    __shared__ unsigned short sAh[128*APITCH], sAl[128*APITCH];
    __shared__ int ia_s[128], is_s[128], iet_s[128], idd_s[128];
    __shared__ float a_s[128], part_s[256], w2_s[128];

    const int tid = threadIdx.x;
    const int w = tid >> 5, lane = tid & 31;
    const int g = lane >> 2, t = lane & 3;
    const int wr0 = (w >> 1) * 32, wc0 = (w & 1) * 64;
    const long long e0 = (long long)blockIdx.x * 128;

    if (tid < 128) {
        ia_s[tid] = ld_idx(idx_add, e0 + tid, sel_add);
        is_s[tid] = ld_idx(idx_src, e0 + tid, 0);
        w2_s[tid] = w2[tid];
        if (mode == 2) {
            iet_s[tid] = ld_idx(idx_et, e0 + tid, 1);
            idd_s[tid] = ld_idx(idx_dst, e0 + tid, 0);
        }
    }

    auto issue = [&](int chunk) {
        int b = chunk & 1;
        int k0 = chunk * 32;
        if (mode != 2) {
            float* dA = pA32 + b * 4608;
#pragma unroll
            for (int it = 0; it < 4; it++) {
                int f = tid + 256 * it;
                int r = f >> 3, j = (f & 7) << 2;
                cp16(dA + r*A32PITCH + j, X + (e0 + r)*HH + k0 + j);
            }
        }
        unsigned short* dWh = pWh + b * 5120;
        unsigned short* dWl = pWl + b * 5120;
#pragma unroll
        for (int it = 0; it < 2; it++) {
            int f = tid + 256 * it;
            int c = f >> 2, seg = f & 3;
            cp16(dWh + c*WPIT2 + seg*8, Wh + c*128 + k0 + seg*8);
            cp16(dWl + c*WPIT2 + seg*8, Wl + c*128 + k0 + seg*8);
        }
        asm volatile("cp.async.commit_group;");
    };

    float acc[2][8][4];
#pragma unroll
    for (int a = 0; a < 2; a++)
#pragma unroll
        for (int b = 0; b < 8; b++)
#pragma unroll
            for (int c = 0; c < 4; c++) acc[a][b][c] = 0.f;

    issue(0);
    for (int ch = 0; ch < 4; ch++) {
        // drain ALL warps' reads of the buffer we are about to overwrite
        __syncthreads();
        if (ch < 3) {
            issue(ch + 1);
            asm volatile("cp.async.wait_group 1;");
        } else {
            asm volatile("cp.async.wait_group 0;");
        }
        __syncthreads();
        const int b = ch & 1;
        const int k0 = ch * 32;
        if (mode == 2) {
#pragma unroll
            for (int i = 0; i < 4; i++) {
                int f = tid + 256 * i;
                int r = f >> 3, j = (f & 7) << 2;
                int s = is_s[r], et = iet_s[r], dd = idd_s[r];
                float4 p = *(const float4*)(Pm + (size_t)s*HH + k0 + j);
                float4 q = *(const float4*)(Qm + (size_t)et*HH + k0 + j);
                float4 dv = *(const float4*)(Dm + (size_t)dd*HH + k0 + j);
                float4 v;
                v.x = fmaxf(p.x+q.x+dv.x, 0.f); v.y = fmaxf(p.y+q.y+dv.y, 0.f);
                v.z = fmaxf(p.z+q.z+dv.z, 0.f); v.w = fmaxf(p.w+q.w+dv.w, 0.f);
                *(float4*)(ie_out + (e0 + r)*HH + k0 + j) = v;
                unsigned short h, l;
                f2bf(v.x, h, l); sAh[r*APITCH+j+0] = h; sAl[r*APITCH+j+0] = l;
                f2bf(v.y, h, l); sAh[r*APITCH+j+1] = h; sAl[r*APITCH+j+1] = l;
                f2bf(v.z, h, l); sAh[r*APITCH+j+2] = h; sAl[r*APITCH+j+2] = l;
                f2bf(v.w, h, l); sAh[r*APITCH+j+3] = h; sAl[r*APITCH+j+3] = l;
            }
        } else {
            const float* sA = pA32 + b * 4608;
#pragma unroll
            for (int i = 0; i < 4; i++) {
                int f = tid + 256 * i;
                int r = f >> 3, j = (f & 7) << 2;
                float4 v = *(const float4*)(sA + r*A32PITCH + j);
                unsigned short h, l;
                f2bf(v.x, h, l); sAh[r*APITCH+j+0] = h; sAl[r*APITCH+j+0] = l;
                f2bf(v.y, h, l); sAh[r*APITCH+j+1] = h; sAl[r*APITCH+j+1] = l;
                f2bf(v.z, h, l); sAh[r*APITCH+j+2] = h; sAl[r*APITCH+j+2] = l;
                f2bf(v.w, h, l); sAh[r*APITCH+j+3] = h; sAl[r*APITCH+j+3] = l;
            }
        }
        __syncthreads();
        const unsigned short* cWh = pWh + b * 5120;
        const unsigned short* cWl = pWl + b * 5120;
#pragma unroll
        for (int ks = 0; ks < 32; ks += 16) {
            unsigned ah[2][4], al[2][4];
#pragma unroll
            for (int mt = 0; mt < 2; mt++) {
                int rb = wr0 + mt * 16 + g;
                const unsigned short* p = &sAh[rb*APITCH + ks + 2*t];
                ah[mt][0] = *(const unsigned*)p;
                ah[mt][1] = *(const unsigned*)(p + 8*APITCH);
                ah[mt][2] = *(const unsigned*)(p + 8);
                ah[mt][3] = *(const unsigned*)(p + 8*APITCH + 8);
                const unsigned short* q = &sAl[rb*APITCH + ks + 2*t];
                al[mt][0] = *(const unsigned*)q;
                al[mt][1] = *(const unsigned*)(q + 8*APITCH);
                al[mt][2] = *(const unsigned*)(q + 8);
                al[mt][3] = *(const unsigned*)(q + 8*APITCH + 8);
            }
#pragma unroll
            for (int nt = 0; nt < 8; nt++) {
                int cn = wc0 + nt * 8 + g;
                unsigned bh[2], bl[2];
                const unsigned short* p = &cWh[cn*WPIT2 + ks + 2*t];
                bh[0] = *(const unsigned*)p; bh[1] = *(const unsigned*)(p + 8);
                const unsigned short* q = &cWl[cn*WPIT2 + ks + 2*t];
                bl[0] = *(const unsigned*)q; bl[1] = *(const unsigned*)(q + 8);
#pragma unroll
                for (int mt = 0; mt < 2; mt++) {
                    mma16(acc[mt][nt], ah[mt], bh);
                    mma16(acc[mt][nt], ah[mt], bl);
                    mma16(acc[mt][nt], al[mt], bh);
                }
            }
        }
    }

    // attention scalar
#pragma unroll
    for (int mt = 0; mt < 2; mt++) {
        int r0 = wr0 + mt * 16 + g, r1 = r0 + 8;
        const float2* ar0 = (const float2*)(addvec + (size_t)ia_s[r0] * HH);
        const float2* ar1 = (const float2*)(addvec + (size_t)ia_s[r1] * HH);
        float p0 = 0.f, p1 = 0.f;
#pragma unroll
        for (int nt = 0; nt < 8; nt++) {
            int c = wc0 + nt * 8 + t * 2;
            float w0 = w2_s[c], w1 = w2_s[c+1];
            float2 a0 = ar0[c >> 1], a1 = ar1[c >> 1];
            p0 += fmaxf(acc[mt][nt][0] + a0.x, 0.f) * w0
                + fmaxf(acc[mt][nt][1] + a0.y, 0.f) * w1;
            p1 += fmaxf(acc[mt][nt][2] + a1.x, 0.f) * w0
                + fmaxf(acc[mt][nt][3] + a1.y, 0.f) * w1;
        }
        p0 += __shfl_xor_sync(0xffffffffu, p0, 1);
        p0 += __shfl_xor_sync(0xffffffffu, p0, 2);
        p1 += __shfl_xor_sync(0xffffffffu, p1, 1);
        p1 += __shfl_xor_sync(0xffffffffu, p1, 2);
        if (t == 0) {
            part_s[r0 * 2 + (w & 1)] = p0;
            part_s[r1 * 2 + (w & 1)] = p1;
        }
    }
    __syncthreads();
    if (tid < 128) {
        float ps = part_s[tid * 2] + part_s[tid * 2 + 1];
        a_s[tid] = 1.f / (1.f + expf(-ps));
    }
    __syncthreads();

    // output epilogue
#pragma unroll
    for (int i = 0; i < 16; i++) {
        int f = tid + 256 * i;
        int r = f >> 5, q = (f & 31) << 2;
        size_t base = (size_t)(e0 + r) * HH + q;
        float4 iv = *(const float4*)(ie + base);
        float a = a_s[r];
        float4 o;
        if (mode == 1) {
            float4 v4 = *(const float4*)(V + (size_t)is_s[r] * HH + q);
            o.x = fmaxf(iv.x + a*v4.x, 0.f); o.y = fmaxf(iv.y + a*v4.y, 0.f);
            o.z = fmaxf(iv.z + a*v4.z, 0.f); o.w = fmaxf(iv.w + a*v4.w, 0.f);
        } else {
            o = make_float4(iv.x*a, iv.y*a, iv.z*a, iv.w*a);
        }
        *(float4*)(outp + base) = o;
    }
}

// ---------- CSR build ----------
__global__ void k_cnt_zero() {
    int t = blockIdx.x*256 + threadIdx.x;
    if (t < NN) g_cnt[t] = 0;
}
__global__ void k_count(const void* dstp) {
    int e = blockIdx.x*256 + threadIdx.x;
    if (e < NE) atomicAdd(&g_cnt[ld_idx(dstp, e, 0)], 1);
}
__global__ void __launch_bounds__(1024) k_scan1() {
    __shared__ int wsum[32];
    int b = blockIdx.x, t = threadIdx.x;
    int lane = t & 31, wid = t >> 5;
    int v = g_cnt[b*1024 + t];
    int orig = v;
#pragma unroll
    for (int off = 1; off < 32; off <<= 1) {
        int u = __shfl_up_sync(0xffffffffu, v, off);
        if (lane >= off) v += u;
    }
    if (lane == 31) wsum[wid] = v;
    __syncthreads();
    if (wid == 0) {
        int y = wsum[lane];
#pragma unroll
        for (int off = 1; off < 32; off <<= 1) {
            int u = __shfl_up_sync(0xffffffffu, y, off);
            if (lane >= off) y += u;
        }
        wsum[lane] = y;
    }
    __syncthreads();
    int incl = v + (wid ? wsum[wid-1] : 0);
    g_off[b*1024 + t] = incl - orig;
    if (t == 1023) g_bsum[b] = incl;
}
__global__ void k_scan2() {
    int t = threadIdx.x;
    int v = (t < 16) ? g_bsum[t] : 0;
    int x = v;
#pragma unroll
    for (int off = 1; off < 32; off <<= 1) {
        int u = __shfl_up_sync(0xffffffffu, x, off);
        if (t >= off) x += u;
    }
    if (t < 16) g_bpre[t] = x - v;
    if (t == 15) g_off[NN] = x;
}
__global__ void k_scan3() {
    int i = blockIdx.x*256 + threadIdx.x;
    if (i < NN) {
        int o = g_off[i] + g_bpre[i >> 10];
        g_off[i] = o;
        g_cur[i] = o;
    }
}
__global__ void k_fill(const void* dstp) {
    int e = blockIdx.x*256 + threadIdx.x;
    if (e < NE) {
        int d = ld_idx(dstp, e, 0);
        int pos = atomicAdd(&g_cur[d], 1);
        g_eid[pos] = e;
    }
}

// ---------- CSR gather aggregation ----------
__global__ void __launch_bounds__(128) k_gather(const float* __restrict__ me,
                                                const float* __restrict__ addb,
                                                float* __restrict__ out)
{
    int n = blockIdx.x, j = threadIdx.x;
    int o0 = g_off[n], o1 = g_off[n+1];
    float s = addb ? addb[(size_t)n*HH + j] : 0.f;
    for (int i = o0; i < o1; i++) {
        int e = g_eid[i];
        s += me[(size_t)e*HH + j];
    }
    out[(size_t)n*HH + j] = s;
}

// ---------- GRU prep ----------
__global__ void k_msg(const float* __restrict__ gru_bias) {
    int t = blockIdx.x*256 + threadIdx.x;
    g_msg[t] = fmaxf(g_nodeh[t] + gru_bias[t & 127], 0.f);
}
__global__ void k_h0() {
    int b = blockIdx.x, j = threadIdx.x;
    float m = -1e30f;
    for (int s = 0; s < SS; s++)
        m = fmaxf(m, g_nodeh[((size_t)(b*SS + s))*HH + j]);
    g_h0[b*HH + j] = m;
}
__global__ void k_twih(const float* __restrict__ Wih) {
    int t = blockIdx.x*256 + threadIdx.x;
    if (t < 2*384*128) {
        int d = t / (384*128), rem = t % (384*128);
        int o = rem / 128, k = rem % 128;
        g_WihT[d*384*128 + k*384 + o] = Wih[t];
    }
}
__global__ void k_msg2() {
    int t = blockIdx.x*256 + threadIdx.x;
    int r = t >> 7, j = t & 127;
    int b = r >> 1, s = r & 1;
    g_msg2[t] = g_msg[((size_t)(b*SS + s))*HH + j];
}

__global__ void __launch_bounds__(384) k_gru(const float* __restrict__ Whh,
                                             const float* __restrict__ bhh)
{
    const int b = blockIdx.x, dir = blockIdx.y;
    const int o = threadIdx.x;
    float w[128];
    const float* wr = Whh + ((size_t)dir*384 + o)*128;
#pragma unroll
    for (int k = 0; k < 128; k += 4) {
        float4 v = *(const float4*)(wr + k);
        w[k]=v.x; w[k+1]=v.y; w[k+2]=v.z; w[k+3]=v.w;
    }
    const float bh = bhh[dir*384 + o];
    __shared__ float h_s[128];
    __shared__ float gh_s[384];
    if (o < 128) h_s[o] = g_h0[b*128 + o];
    __syncthreads();
    const int nsteps = (dir == 0) ? 2 : SS;
    for (int i2 = 0; i2 < nsteps; i2++) {
        int t = (dir == 0) ? i2 : (SS - 1 - i2);
        float gh = bh;
#pragma unroll
        for (int k = 0; k < 128; k += 4) {
            float4 hv = *(const float4*)&h_s[k];
            gh += w[k]*hv.x + w[k+1]*hv.y + w[k+2]*hv.z + w[k+3]*hv.w;
        }
        gh_s[o] = gh;
        __syncthreads();
        if (o < 128) {
            const float* gi = (dir == 0) ? (g_gif + (size_t)(b*2 + t)*384)
                                         : (g_gi  + (size_t)(b*SS + t)*384);
            float ir = gi[o], iz = gi[128+o], inn = gi[256+o];
            float r = 1.f/(1.f+expf(-(ir + gh_s[o])));
            float z = 1.f/(1.f+expf(-(iz + gh_s[128+o])));
            float n = tanhf(inn + r*gh_s[256+o]);
            float hnew = (1.f-z)*n + z*h_s[o];
            if (dir == 0) {
                if (i2 == 0)      g_y[0*BB*128 + b*128 + o] = hnew;
                else if (i2 == 1) g_y[1*BB*128 + b*128 + o] = hnew;
            } else {
                if (i2 == SS-1)      g_y[2*BB*128 + b*128 + o] = hnew;
                else if (i2 == SS-2) g_y[3*BB*128 + b*128 + o] = hnew;
            }
            h_s[o] = hnew;
        }
        __syncthreads();
    }
}

__global__ void k_final(const float* __restrict__ Wo, const float* __restrict__ bo,
                        const float* __restrict__ rel_emb, const void* trg,
                        const float* __restrict__ l1W, const float* __restrict__ l1b,
                        const float* __restrict__ l2W, const float* __restrict__ l2b,
                        float* __restrict__ out)
{
    const int b = blockIdx.x, j = threadIdx.x;
    __shared__ float conv[128];
    __shared__ float s16[16];
    float hh = bo[j], ht = bo[j];
    const float* yf0 = g_y + 0*BB*128 + b*128;
    const float* yf1 = g_y + 1*BB*128 + b*128;
    const float* yb0 = g_y + 2*BB*128 + b*128;
    const float* yb1 = g_y + 3*BB*128 + b*128;
    for (int k = 0; k < 128; k++) {
        float wk = Wo[k*128 + j];
        hh += yf0[k]*wk; ht += yf1[k]*wk;
    }
    for (int k = 0; k < 128; k++) {
        float wk = Wo[(128+k)*128 + j];
        hh += yb0[k]*wk; ht += yb1[k]*wk;
    }
    hh = fmaxf(hh, 0.f); ht = fmaxf(ht, 0.f);
    int tr = ld_idx(trg, b, 1);
    conv[j] = tanhf(hh + rel_emb[tr*128 + j] - ht);
    __syncthreads();
    if (j < 16) {
        float s = l1b[j];
        for (int k = 0; k < 128; k++) s += conv[k]*l1W[k*16 + j];
        s16[j] = s;
    }
    __syncthreads();
    if (j == 0) {
        float o = l2b[0];
        for (int i = 0; i < 16; i++) o += s16[i]*l2W[i];
        out[b] = o;
    }
}

extern "C" void kernel_launch(void* const* d_in, const int* in_sizes, int n_in,
                              void* d_out, int out_size)
{
    const float* node_feat = (const float*)d_in[0];
    const float* rel_emb   = (const float*)d_in[1];
    const float* W_i_node  = (const float*)d_in[2];
    const float* W_i_edge  = (const float*)d_in[3];
    const float* W_att_in1 = (const float*)d_in[4];
    const float* W_att_in2 = (const float*)d_in[5];
    const float* W_h_node  = (const float*)d_in[6];
    const float* W_h_edge  = (const float*)d_in[7];
    const float* W_att1    = (const float*)d_in[8];
    const float* W_att2    = (const float*)d_in[9];
    const float* comm_W    = (const float*)d_in[10];
    const float* W_o       = (const float*)d_in[11];
    const float* b_o       = (const float*)d_in[12];
    const float* gru_bias  = (const float*)d_in[13];
    const float* gru_Wih   = (const float*)d_in[14];
    const float* gru_Whh   = (const float*)d_in[15];
    const float* gru_bih   = (const float*)d_in[16];
    const float* gru_bhh   = (const float*)d_in[17];
    const float* lin1_W    = (const float*)d_in[18];
    const float* lin1_b    = (const float*)d_in[19];
    const float* lin2_W    = (const float*)d_in[20];
    const float* lin2_b    = (const float*)d_in[21];
    const void*  src       = d_in[22];
    const void*  dst       = d_in[23];
    const void*  etype     = d_in[24];
    const void*  elabel    = d_in[25];
    const void*  trg       = d_in[26];
    float* out = (float*)d_out;

    float *ge_ie, *ge_me, *ge_in, *ge_P, *ge_D, *ge_U, *ge_mn, *ge_agg, *ge_V;
    float *ge_nodeh, *ge_msg, *ge_scr, *ge_gi, *ge_gif, *ge_msg2, *ge_WihT, *ge_Qrel, *ge_Qd;
    unsigned short *ge_Wh, *ge_Wl;
    cudaGetSymbolAddress((void**)&ge_ie, g_ie);
    cudaGetSymbolAddress((void**)&ge_me, g_me);
    cudaGetSymbolAddress((void**)&ge_in, g_in);
    cudaGetSymbolAddress((void**)&ge_P, g_P);
    cudaGetSymbolAddress((void**)&ge_D, g_D);
    cudaGetSymbolAddress((void**)&ge_U, g_U);
    cudaGetSymbolAddress((void**)&ge_mn, g_mn);
    cudaGetSymbolAddress((void**)&ge_agg, g_agg);
    cudaGetSymbolAddress((void**)&ge_V, g_V);
    cudaGetSymbolAddress((void**)&ge_nodeh, g_nodeh);
    cudaGetSymbolAddress((void**)&ge_msg, g_msg);
    cudaGetSymbolAddress((void**)&ge_scr, g_scr);
    cudaGetSymbolAddress((void**)&ge_gi, g_gi);
    cudaGetSymbolAddress((void**)&ge_gif, g_gif);
    cudaGetSymbolAddress((void**)&ge_msg2, g_msg2);
    cudaGetSymbolAddress((void**)&ge_WihT, g_WihT);
    cudaGetSymbolAddress((void**)&ge_Qrel, g_Qrel);
    cudaGetSymbolAddress((void**)&ge_Qd, g_Qd);
    cudaGetSymbolAddress((void**)&ge_Wh, g_Whg);
    cudaGetSymbolAddress((void**)&ge_Wl, g_Wlg);

    cudaFuncSetAttribute(k_edge_att_tc, cudaFuncAttributeMaxDynamicSharedMemorySize, DYN_BYTES);

    k_detect<<<1, 32>>>(src, etype);

    // CSR of dst
    k_cnt_zero<<<NN/256, 256>>>();
    k_count<<<NE/256, 256>>>(dst);
    k_scan1<<<16, 1024>>>();
    k_scan2<<<1, 32>>>();
    k_scan3<<<NN/256, 256>>>();
    k_fill<<<NE/256, 256>>>(dst);

    // edge attention weights -> bf16 hi/lo, fragment-ready
    k_wconv<<<64, 256>>>(W_att_in1 + 128*128, ge_Wh,           ge_Wl);
    k_wconv<<<64, 256>>>(W_att1,              ge_Wh + 16384,   ge_Wl + 16384);
    k_wconv<<<64, 256>>>(W_att1 + 32768,      ge_Wh + 32768,   ge_Wl + 32768);

    // node-side GEMMs
    k_tgemm_bf<<<dim3(NN/128, 1), 256>>>(node_feat, W_i_edge,           ge_P, 64, 128, NULL, 0, 0);
    k_tgemm_bf<<<dim3(NN/128, 1), 256>>>(node_feat, W_i_edge + 192*128, ge_D, 64, 128, NULL, 0, 0);
    k_tgemm_bf<<<dim3(NN/128, 1), 256>>>(node_feat, W_i_node,           ge_in, 64, 128, NULL, 1, 0);
    // small rel_emb GEMMs
    k_sgemm<<<dim3(1,2), 256>>>(rel_emb, W_i_edge + 64*128,         ge_Qrel,        RR, 128, 128);
    k_sgemm<<<dim3(1,2), 256>>>(rel_emb, W_att1 + 128*128,          ge_Qd,          RR, 128, 128);
    k_sgemm<<<dim3(1,2), 256>>>(rel_emb, W_att1 + 32768 + 128*128,  ge_Qd + RR*128, RR, 128, 128);

    // fused edge_init + input attention (mode 2)
    k_tgemm_bf<<<dim3(NN/128, 1), 256>>>(ge_in, W_att_in1, ge_U, 128, 128, NULL, 0, 0);
    k_edge_att_tc<<<NE/128, 256, DYN_BYTES>>>(NULL, ge_Wh, ge_Wl, ge_U, src, 0, src,
                                              W_att_in2, ge_ie, NULL, ge_me, 2,
                                              ge_P, ge_Qrel, ge_D, etype, dst, ge_ie);

    // two message-passing depths
    for (int d = 0; d < 2; d++) {
        const float* mn_old = (d == 0) ? ge_in : ge_mn;
        k_gather<<<NN, 128>>>(ge_me, mn_old, ge_scr);
        k_tgemm_bf<<<dim3(NN/128, 1), 256>>>(ge_scr, W_h_node + d*16384, ge_mn, 128, 128, NULL, 1, 0);
        k_tgemm_bf<<<dim3(NN/128, 1), 256>>>(ge_mn, W_h_edge + d*16384, ge_V, 128, 128, NULL, 0, 0);
        k_edge_att_tc<<<NE/128, 256, DYN_BYTES>>>(ge_me, ge_Wh + (d+1)*16384, ge_Wl + (d+1)*16384,
                                                  ge_Qd + d*RR*128, elabel, 1,
                                                  src, W_att2 + d*128, ge_ie, ge_V, ge_me, 1,
                                                  NULL, NULL, NULL, NULL, NULL, NULL);
    }

    // readout aggregation + comm
    k_gather<<<NN, 128>>>(ge_me, NULL, ge_agg);
    k_tgemm_bf<<<dim3(NN/128, 1), 256>>>(ge_agg, comm_W,           ge_nodeh, 128, 128, NULL, 0, 0);
    k_tgemm_bf<<<dim3(NN/128, 1), 256>>>(ge_mn,  comm_W + 128*128, ge_nodeh, 128, 128, NULL, 0, 1);
    k_tgemm_bf<<<dim3(NN/128, 1), 256>>>(ge_in,  comm_W + 256*128, ge_nodeh, 128, 128, NULL, 0, 1);

    // GRU
    k_msg<<<NN*128/256, 256>>>(gru_bias);
    k_h0<<<BB, 128>>>();
    k_twih<<<(2*384*128 + 255)/256, 256>>>(gru_Wih);
    k_msg2<<<128*128/256, 256>>>();
    k_tgemm_bf<<<dim3(1, 3), 256>>>(ge_msg2, ge_WihT,           ge_gif, 128, 384, gru_bih,       0, 0);
    k_tgemm_bf<<<dim3(NN/128, 3), 256>>>(ge_msg, ge_WihT + 384*128, ge_gi, 128, 384, gru_bih + 384, 0, 0);
    k_gru<<<dim3(BB, 2), 384>>>(gru_Whh, gru_bhh);

    k_final<<<BB, 128>>>(W_o, b_o, rel_emb, trg, lin1_W, lin1_b, lin2_W, lin2_b, out);
}

// round 12
// speedup vs baseline: 1.3134x; 1.0429x over previous
#include <cuda_runtime.h>
#include <cuda_bf16.h>
#include <math.h>

#define NN 16384
#define NE 262144
#define HH 128
#define BB 64
#define SS 256
#define RR 32

__device__ float g_ie[NE*HH];
__device__ float g_me[NE*HH];
__device__ float g_in[NN*HH];
__device__ float g_P[NN*HH];
__device__ float g_D[NN*HH];
__device__ float g_U[NN*HH];
__device__ float g_mn[NN*HH];
__device__ float g_agg[NN*HH];
__device__ float g_V[NN*HH];
__device__ float g_nodeh[NN*HH];
__device__ float g_msg[NN*HH];
__device__ float g_scr[NN*HH];
__device__ float g_gi[NN*384];
__device__ float g_gif[128*384];
__device__ float g_msg2[128*HH];
__device__ float g_WihT[2*384*128];
__device__ float g_Qrel[RR*HH];
__device__ float g_Qd[2*RR*HH];
__device__ float g_h0[BB*HH];
__device__ float g_y[4*BB*HH];
__device__ int   g_is64[2];
__device__ int   g_cnt[NN];
__device__ int   g_off[NN+1];
__device__ int   g_cur[NN];
__device__ int   g_eid[NE];
__device__ int   g_bsum[16], g_bpre[16];
__device__ int   g_srcp[NE], g_dstp[NE], g_etp[NE], g_elp[NE];
__device__ unsigned short g_Whg[3*16384];
__device__ unsigned short g_Wlg[3*16384];

__device__ __forceinline__ int ld_idx(const void* p, long long i, int sel) {
    if (g_is64[sel]) return (int)((const long long*)p)[i];
    return ((const int*)p)[i];
}

__global__ void k_detect(const void* src, const void* et) {
    if (threadIdx.x == 0) {
        const unsigned long long* a = (const unsigned long long*)src;
        int v = 1;
        for (int i = 0; i < 8; i++) if (a[i] >= (unsigned long long)NN) v = 0;
        g_is64[0] = v;
        const unsigned long long* b = (const unsigned long long*)et;
        v = 1;
        for (int i = 0; i < 8; i++) if (b[i] >= (unsigned long long)RR) v = 0;
        g_is64[1] = v;
    }
}

// ---------- bf16 hi/lo helpers ----------
__device__ __forceinline__ void f2bf(float x, unsigned short& h, unsigned short& l) {
    __nv_bfloat16 bh = __float2bfloat16(x);
    h = __bfloat16_as_ushort(bh);
    l = __bfloat16_as_ushort(__float2bfloat16(x - __bfloat162float(bh)));
}

__device__ __forceinline__ void mma16(float* d, const unsigned* a, const unsigned* b) {
    asm volatile("mma.sync.aligned.m16n8k16.row.col.f32.bf16.bf16.f32 "
        "{%0,%1,%2,%3}, {%4,%5,%6,%7}, {%8,%9}, {%0,%1,%2,%3};"
        : "+f"(d[0]), "+f"(d[1]), "+f"(d[2]), "+f"(d[3])
        : "r"(a[0]), "r"(a[1]), "r"(a[2]), "r"(a[3]), "r"(b[0]), "r"(b[1]));
}

__device__ __forceinline__ void cp16(const void* smem_dst, const void* gsrc) {
    unsigned d = (unsigned)__cvta_generic_to_shared(smem_dst);
    asm volatile("cp.async.cg.shared.global [%0], [%1], 16;" :: "r"(d), "l"(gsrc));
}

__global__ void k_wconv(const float* __restrict__ Wm,
                        unsigned short* __restrict__ Wh,
                        unsigned short* __restrict__ Wl)
{
    int t = blockIdx.x*256 + threadIdx.x;
    int k = t >> 7, c = t & 127;
    unsigned short h, l;
    f2bf(Wm[k*128 + c], h, l);
    Wh[c*128 + k] = h;
    Wl[c*128 + k] = l;
}

#define APITCH 40
#define WPITCH 42
#define WPIT2 40
#define A32PITCH 36
#define DYN_WH_OFF 36864
#define DYN_WL_OFF 57344
#define DYN_BYTES  77824

// ---------- bf16 3-split tensor-core GEMM ----------
__global__ void __launch_bounds__(256, 2) k_tgemm_bf(
    const float* __restrict__ A, const float* __restrict__ W, float* __restrict__ C,
    int K, int M, const float* __restrict__ bias, int doRelu, int accum)
{
    __shared__ unsigned short sAh[128*APITCH], sAl[128*APITCH];
    __shared__ unsigned short sWh[128*WPITCH], sWl[128*WPITCH];
    const int tid = threadIdx.x;
    const int w = tid >> 5, lane = tid & 31;
    const int g = lane >> 2, t = lane & 3;
    const int wr0 = (w >> 1) * 32, wc0 = (w & 1) * 64;
    const long long row0 = (long long)blockIdx.x * 128;
    const int col0 = blockIdx.y * 128;

    float acc[2][8][4];
#pragma unroll
    for (int a = 0; a < 2; a++)
#pragma unroll
        for (int b = 0; b < 8; b++)
#pragma unroll
            for (int c = 0; c < 4; c++) acc[a][b][c] = 0.f;

    for (int k0 = 0; k0 < K; k0 += 32) {
        __syncthreads();
#pragma unroll
        for (int i = 0; i < 4; i++) {
            int f = tid + 256 * i;
            int r = f >> 3, j = (f & 7) << 2;
            float4 v = *(const float4*)(A + (row0 + r) * K + k0 + j);
            unsigned short h, l;
            f2bf(v.x, h, l); sAh[r*APITCH+j+0] = h; sAl[r*APITCH+j+0] = l;
            f2bf(v.y, h, l); sAh[r*APITCH+j+1] = h; sAl[r*APITCH+j+1] = l;
            f2bf(v.z, h, l); sAh[r*APITCH+j+2] = h; sAl[r*APITCH+j+2] = l;
            f2bf(v.w, h, l); sAh[r*APITCH+j+3] = h; sAl[r*APITCH+j+3] = l;
        }
#pragma unroll
        for (int i = 0; i < 4; i++) {
            int f = tid + 256 * i;
            int kk = f >> 5, c = (f & 31) << 2;
            float4 v = *(const float4*)(W + (long long)(k0 + kk) * M + col0 + c);
            unsigned short h, l;
            f2bf(v.x, h, l); sWh[(c+0)*WPITCH+kk] = h; sWl[(c+0)*WPITCH+kk] = l;
            f2bf(v.y, h, l); sWh[(c+1)*WPITCH+kk] = h; sWl[(c+1)*WPITCH+kk] = l;
            f2bf(v.z, h, l); sWh[(c+2)*WPITCH+kk] = h; sWl[(c+2)*WPITCH+kk] = l;
            f2bf(v.w, h, l); sWh[(c+3)*WPITCH+kk] = h; sWl[(c+3)*WPITCH+kk] = l;
        }
        __syncthreads();
#pragma unroll
        for (int ks = 0; ks < 32; ks += 16) {
            unsigned ah[2][4], al[2][4];
#pragma unroll
            for (int mt = 0; mt < 2; mt++) {
                int rb = wr0 + mt * 16 + g;
                const unsigned short* p = &sAh[rb*APITCH + ks + 2*t];
                ah[mt][0] = *(const unsigned*)p;
                ah[mt][1] = *(const unsigned*)(p + 8*APITCH);
                ah[mt][2] = *(const unsigned*)(p + 8);
                ah[mt][3] = *(const unsigned*)(p + 8*APITCH + 8);
                const unsigned short* q = &sAl[rb*APITCH + ks + 2*t];
                al[mt][0] = *(const unsigned*)q;
                al[mt][1] = *(const unsigned*)(q + 8*APITCH);
                al[mt][2] = *(const unsigned*)(q + 8);
                al[mt][3] = *(const unsigned*)(q + 8*APITCH + 8);
            }
#pragma unroll
            for (int nt = 0; nt < 8; nt++) {
                int cn = wc0 + nt * 8 + g;
                unsigned bh[2], bl[2];
                const unsigned short* p = &sWh[cn*WPITCH + ks + 2*t];
                bh[0] = *(const unsigned*)p; bh[1] = *(const unsigned*)(p + 8);
                const unsigned short* q = &sWl[cn*WPITCH + ks + 2*t];
                bl[0] = *(const unsigned*)q; bl[1] = *(const unsigned*)(q + 8);
#pragma unroll
                for (int mt = 0; mt < 2; mt++) {
                    mma16(acc[mt][nt], ah[mt], bh);
                    mma16(acc[mt][nt], ah[mt], bl);
                    mma16(acc[mt][nt], al[mt], bh);
                }
            }
        }
    }
#pragma unroll
    for (int mt = 0; mt < 2; mt++) {
#pragma unroll
        for (int nt = 0; nt < 8; nt++) {
            int c = col0 + wc0 + nt * 8 + t * 2;
            long long r0 = row0 + wr0 + mt * 16 + g;
            float b0 = bias ? bias[c] : 0.f, b1 = bias ? bias[c+1] : 0.f;
            float v0 = acc[mt][nt][0] + b0, v1 = acc[mt][nt][1] + b1;
            float v2 = acc[mt][nt][2] + b0, v3 = acc[mt][nt][3] + b1;
            if (accum) {
                float2 o0 = *(const float2*)(C + r0 * M + c);
                float2 o1 = *(const float2*)(C + (r0 + 8) * M + c);
                v0 += o0.x; v1 += o0.y; v2 += o1.x; v3 += o1.y;
            }
            if (doRelu) {
                v0 = fmaxf(v0, 0.f); v1 = fmaxf(v1, 0.f);
                v2 = fmaxf(v2, 0.f); v3 = fmaxf(v3, 0.f);
            }
            *(float2*)(C + r0 * M + c)       = make_float2(v0, v1);
            *(float2*)(C + (r0 + 8) * M + c) = make_float2(v2, v3);
        }
    }
}

// ---------- batched variant: blockIdx.y selects one of 3 (W,C) pairs; A shared; K=64, M=128 ----------
__global__ void __launch_bounds__(256, 2) k_tgemm_bf3(
    const float* __restrict__ A,
    const float* __restrict__ W0, const float* __restrict__ W1, const float* __restrict__ W2,
    float* __restrict__ C0, float* __restrict__ C1, float* __restrict__ C2, int reluMask)
{
    const float* W = (blockIdx.y == 0) ? W0 : ((blockIdx.y == 1) ? W1 : W2);
    float* C = (blockIdx.y == 0) ? C0 : ((blockIdx.y == 1) ? C1 : C2);
    const int doRelu = (reluMask >> blockIdx.y) & 1;
    __shared__ unsigned short sAh[128*APITCH], sAl[128*APITCH];
    __shared__ unsigned short sWh[128*WPITCH], sWl[128*WPITCH];
    const int tid = threadIdx.x;
    const int w = tid >> 5, lane = tid & 31;
    const int g = lane >> 2, t = lane & 3;
    const int wr0 = (w >> 1) * 32, wc0 = (w & 1) * 64;
    const long long row0 = (long long)blockIdx.x * 128;

    float acc[2][8][4];
#pragma unroll
    for (int a = 0; a < 2; a++)
#pragma unroll
        for (int b = 0; b < 8; b++)
#pragma unroll
            for (int c = 0; c < 4; c++) acc[a][b][c] = 0.f;

    for (int k0 = 0; k0 < 64; k0 += 32) {
        __syncthreads();
#pragma unroll
        for (int i = 0; i < 4; i++) {
            int f = tid + 256 * i;
            int r = f >> 3, j = (f & 7) << 2;
            float4 v = *(const float4*)(A + (row0 + r) * 64 + k0 + j);
            unsigned short h, l;
            f2bf(v.x, h, l); sAh[r*APITCH+j+0] = h; sAl[r*APITCH+j+0] = l;
            f2bf(v.y, h, l); sAh[r*APITCH+j+1] = h; sAl[r*APITCH+j+1] = l;
            f2bf(v.z, h, l); sAh[r*APITCH+j+2] = h; sAl[r*APITCH+j+2] = l;
            f2bf(v.w, h, l); sAh[r*APITCH+j+3] = h; sAl[r*APITCH+j+3] = l;
        }
#pragma unroll
        for (int i = 0; i < 4; i++) {
            int f = tid + 256 * i;
            int kk = f >> 5, c = (f & 31) << 2;
            float4 v = *(const float4*)(W + (long long)(k0 + kk) * 128 + c);
            unsigned short h, l;
            f2bf(v.x, h, l); sWh[(c+0)*WPITCH+kk] = h; sWl[(c+0)*WPITCH+kk] = l;
            f2bf(v.y, h, l); sWh[(c+1)*WPITCH+kk] = h; sWl[(c+1)*WPITCH+kk] = l;
            f2bf(v.z, h, l); sWh[(c+2)*WPITCH+kk] = h; sWl[(c+2)*WPITCH+kk] = l;
            f2bf(v.w, h, l); sWh[(c+3)*WPITCH+kk] = h; sWl[(c+3)*WPITCH+kk] = l;
        }
        __syncthreads();
#pragma unroll
        for (int ks = 0; ks < 32; ks += 16) {
            unsigned ah[2][4], al[2][4];
#pragma unroll
            for (int mt = 0; mt < 2; mt++) {
                int rb = wr0 + mt * 16 + g;
                const unsigned short* p = &sAh[rb*APITCH + ks + 2*t];
                ah[mt][0] = *(const unsigned*)p;
                ah[mt][1] = *(const unsigned*)(p + 8*APITCH);
                ah[mt][2] = *(const unsigned*)(p + 8);
                ah[mt][3] = *(const unsigned*)(p + 8*APITCH + 8);
                const unsigned short* q = &sAl[rb*APITCH + ks + 2*t];
                al[mt][0] = *(const unsigned*)q;
                al[mt][1] = *(const unsigned*)(q + 8*APITCH);
                al[mt][2] = *(const unsigned*)(q + 8);
                al[mt][3] = *(const unsigned*)(q + 8*APITCH + 8);
            }
#pragma unroll
            for (int nt = 0; nt < 8; nt++) {
                int cn = wc0 + nt * 8 + g;
                unsigned bh[2], bl[2];
                const unsigned short* p = &sWh[cn*WPITCH + ks + 2*t];
                bh[0] = *(const unsigned*)p; bh[1] = *(const unsigned*)(p + 8);
                const unsigned short* q = &sWl[cn*WPITCH + ks + 2*t];
                bl[0] = *(const unsigned*)q; bl[1] = *(const unsigned*)(q + 8);
#pragma unroll
                for (int mt = 0; mt < 2; mt++) {
                    mma16(acc[mt][nt], ah[mt], bh);
                    mma16(acc[mt][nt], ah[mt], bl);
                    mma16(acc[mt][nt], al[mt], bh);
                }
            }
        }
    }
#pragma unroll
    for (int mt = 0; mt < 2; mt++) {
#pragma unroll
        for (int nt = 0; nt < 8; nt++) {
            int c = wc0 + nt * 8 + t * 2;
            long long r0 = row0 + wr0 + mt * 16 + g;
            float v0 = acc[mt][nt][0], v1 = acc[mt][nt][1];
            float v2 = acc[mt][nt][2], v3 = acc[mt][nt][3];
            if (doRelu) {
                v0 = fmaxf(v0, 0.f); v1 = fmaxf(v1, 0.f);
                v2 = fmaxf(v2, 0.f); v3 = fmaxf(v3, 0.f);
            }
            *(float2*)(C + r0 * 128 + c)       = make_float2(v0, v1);
            *(float2*)(C + (r0 + 8) * 128 + c) = make_float2(v2, v3);
        }
    }
}

// ---------- concat GEMM: C = [A0|A1|A2] @ W(384x128), K-chunk selects A buffer ----------
__global__ void __launch_bounds__(256, 2) k_tgemm_cat3(
    const float* __restrict__ A0, const float* __restrict__ A1, const float* __restrict__ A2,
    const float* __restrict__ W, float* __restrict__ C)
{
    __shared__ unsigned short sAh[128*APITCH], sAl[128*APITCH];
    __shared__ unsigned short sWh[128*WPITCH], sWl[128*WPITCH];
    const int tid = threadIdx.x;
    const int w = tid >> 5, lane = tid & 31;
    const int g = lane >> 2, t = lane & 3;
    const int wr0 = (w >> 1) * 32, wc0 = (w & 1) * 64;
    const long long row0 = (long long)blockIdx.x * 128;

    float acc[2][8][4];
#pragma unroll
    for (int a = 0; a < 2; a++)
#pragma unroll
        for (int b = 0; b < 8; b++)
#pragma unroll
            for (int c = 0; c < 4; c++) acc[a][b][c] = 0.f;

    for (int ch = 0; ch < 12; ch++) {
        const int k0 = ch * 32;
        const float* A = (ch < 4) ? A0 : ((ch < 8) ? A1 : A2);
        const int kloc = (ch & 3) * 32;
        __syncthreads();
#pragma unroll
        for (int i = 0; i < 4; i++) {
            int f = tid + 256 * i;
            int r = f >> 3, j = (f & 7) << 2;
            float4 v = *(const float4*)(A + (row0 + r) * 128 + kloc + j);
            unsigned short h, l;
            f2bf(v.x, h, l); sAh[r*APITCH+j+0] = h; sAl[r*APITCH+j+0] = l;
            f2bf(v.y, h, l); sAh[r*APITCH+j+1] = h; sAl[r*APITCH+j+1] = l;
            f2bf(v.z, h, l); sAh[r*APITCH+j+2] = h; sAl[r*APITCH+j+2] = l;
            f2bf(v.w, h, l); sAh[r*APITCH+j+3] = h; sAl[r*APITCH+j+3] = l;
        }
#pragma unroll
        for (int i = 0; i < 4; i++) {
            int f = tid + 256 * i;
            int kk = f >> 5, c = (f & 31) << 2;
            float4 v = *(const float4*)(W + (long long)(k0 + kk) * 128 + c);
            unsigned short h, l;
            f2bf(v.x, h, l); sWh[(c+0)*WPITCH+kk] = h; sWl[(c+0)*WPITCH+kk] = l;
            f2bf(v.y, h, l); sWh[(c+1)*WPITCH+kk] = h; sWl[(c+1)*WPITCH+kk] = l;
            f2bf(v.z, h, l); sWh[(c+2)*WPITCH+kk] = h; sWl[(c+2)*WPITCH+kk] = l;
            f2bf(v.w, h, l); sWh[(c+3)*WPITCH+kk] = h; sWl[(c+3)*WPITCH+kk] = l;
        }
        __syncthreads();
#pragma unroll
        for (int ks = 0; ks < 32; ks += 16) {
            unsigned ah[2][4], al[2][4];
#pragma unroll
            for (int mt = 0; mt < 2; mt++) {
                int rb = wr0 + mt * 16 + g;
                const unsigned short* p = &sAh[rb*APITCH + ks + 2*t];
                ah[mt][0] = *(const unsigned*)p;
                ah[mt][1] = *(const unsigned*)(p + 8*APITCH);
                ah[mt][2] = *(const unsigned*)(p + 8);
                ah[mt][3] = *(const unsigned*)(p + 8*APITCH + 8);
                const unsigned short* q = &sAl[rb*APITCH + ks + 2*t];
                al[mt][0] = *(const unsigned*)q;
                al[mt][1] = *(const unsigned*)(q + 8*APITCH);
                al[mt][2] = *(const unsigned*)(q + 8);
                al[mt][3] = *(const unsigned*)(q + 8*APITCH + 8);
            }
#pragma unroll
            for (int nt = 0; nt < 8; nt++) {
                int cn = wc0 + nt * 8 + g;
                unsigned bh[2], bl[2];
                const unsigned short* p = &sWh[cn*WPITCH + ks + 2*t];
                bh[0] = *(const unsigned*)p; bh[1] = *(const unsigned*)(p + 8);
                const unsigned short* q = &sWl[cn*WPITCH + ks + 2*t];
                bl[0] = *(const unsigned*)q; bl[1] = *(const unsigned*)(q + 8);
#pragma unroll
                for (int mt = 0; mt < 2; mt++) {
                    mma16(acc[mt][nt], ah[mt], bh);
                    mma16(acc[mt][nt], ah[mt], bl);
                    mma16(acc[mt][nt], al[mt], bh);
                }
            }
        }
    }
#pragma unroll
    for (int mt = 0; mt < 2; mt++) {
#pragma unroll
        for (int nt = 0; nt < 8; nt++) {
            int c = wc0 + nt * 8 + t * 2;
            long long r0 = row0 + wr0 + mt * 16 + g;
            *(float2*)(C + r0 * 128 + c)       = make_float2(acc[mt][nt][0], acc[mt][nt][1]);
            *(float2*)(C + (r0 + 8) * 128 + c) = make_float2(acc[mt][nt][2], acc[mt][nt][3]);
        }
    }
}

// ---------- small SIMT GEMM for 32-row rel_emb GEMMs ----------
__global__ void k_sgemm(const float* __restrict__ A, const float* __restrict__ W,
                        float* __restrict__ C, int rows, int K, int M)
{
    __shared__ float As[16][64];
    __shared__ float Ws[16][64];
    const int tid = threadIdx.x;
    const int tx = tid & 15, ty = tid >> 4;
    const int row0 = blockIdx.x * 64, col0 = blockIdx.y * 64;
    const int la_r = tid >> 2, la_k = (tid & 3) << 2;
    const int lw_k = tid >> 4, lw_c = (tid & 15) << 2;
    float acc[4][4];
#pragma unroll
    for (int i = 0; i < 4; i++)
#pragma unroll
        for (int j = 0; j < 4; j++) acc[i][j] = 0.f;
    for (int k0 = 0; k0 < K; k0 += 16) {
        float4 av = make_float4(0.f,0.f,0.f,0.f);
        if (row0 + la_r < rows)
            av = *(const float4*)(A + (size_t)(row0 + la_r) * K + (k0 + la_k));
        As[la_k+0][la_r] = av.x; As[la_k+1][la_r] = av.y;
        As[la_k+2][la_r] = av.z; As[la_k+3][la_r] = av.w;
        *(float4*)&Ws[lw_k][lw_c] = *(const float4*)(W + (size_t)(k0+lw_k)*M + col0 + lw_c);
        __syncthreads();
#pragma unroll
        for (int k = 0; k < 16; k++) {
            float4 a4 = *(const float4*)&As[k][ty<<2];
            float4 w4 = *(const float4*)&Ws[k][tx<<2];
            float ar[4] = {a4.x,a4.y,a4.z,a4.w};
            float wr[4] = {w4.x,w4.y,w4.z,w4.w};
#pragma unroll
            for (int i = 0; i < 4; i++)
#pragma unroll
                for (int j = 0; j < 4; j++) acc[i][j] += ar[i]*wr[j];
        }
        __syncthreads();
    }
#pragma unroll
    for (int i = 0; i < 4; i++) {
        int r = row0 + (ty<<2) + i;
        if (r < rows)
#pragma unroll
            for (int j = 0; j < 4; j++)
                C[(size_t)r*M + col0 + (tx<<2) + j] = acc[i][j];
    }
}

// ---------- bf16 tensor-core fused edge attention (permuted int32 indices) ----------
__global__ void __launch_bounds__(256, 2) k_edge_att_tc(
    const float* __restrict__ X,
    const unsigned short* __restrict__ Wh, const unsigned short* __restrict__ Wl,
    const float* __restrict__ addvec, const int* __restrict__ idx_add,
    const int* __restrict__ idx_src, const float* __restrict__ w2,
    const float* __restrict__ ie, const float* __restrict__ V,
    float* __restrict__ outp, int mode,
    const float* __restrict__ Pm, const float* __restrict__ Qm,
    const float* __restrict__ Dm, const int* __restrict__ idx_et,
    const int* __restrict__ idx_dst, float* __restrict__ ie_out)
{
    extern __shared__ char dynsm[];
    float* pA32 = (float*)dynsm;
    unsigned short* pWh = (unsigned short*)(dynsm + DYN_WH_OFF);
    unsigned short* pWl = (unsigned short*)(dynsm + DYN_WL_OFF);
    __shared__ unsigned short sAh[128*APITCH], sAl[128*APITCH];
    __shared__ int ia_s[128], is_s[128], iet_s[128], idd_s[128];
    __shared__ float a_s[128], part_s[256], w2_s[128];

    const int tid = threadIdx.x;
    const int w = tid >> 5, lane = tid & 31;
    const int g = lane >> 2, t = lane & 3;
    const int wr0 = (w >> 1) * 32, wc0 = (w & 1) * 64;
    const long long e0 = (long long)blockIdx.x * 128;

    if (tid < 128) {
        ia_s[tid] = idx_add[e0 + tid];
        is_s[tid] = idx_src[e0 + tid];
        w2_s[tid] = w2[tid];
        if (mode == 2) {
            iet_s[tid] = idx_et[e0 + tid];
            idd_s[tid] = idx_dst[e0 + tid];
        }
    }

    auto issue = [&](int chunk) {
        int b = chunk & 1;
        int k0 = chunk * 32;
        if (mode != 2) {
            float* dA = pA32 + b * 4608;
#pragma unroll
            for (int it = 0; it < 4; it++) {
                int f = tid + 256 * it;
                int r = f >> 3, j = (f & 7) << 2;
                cp16(dA + r*A32PITCH + j, X + (e0 + r)*HH + k0 + j);
            }
        }
        unsigned short* dWh = pWh + b * 5120;
        unsigned short* dWl = pWl + b * 5120;
#pragma unroll
        for (int it = 0; it < 2; it++) {
            int f = tid + 256 * it;
            int c = f >> 2, seg = f & 3;
            cp16(dWh + c*WPIT2 + seg*8, Wh + c*128 + k0 + seg*8);
            cp16(dWl + c*WPIT2 + seg*8, Wl + c*128 + k0 + seg*8);
        }
        asm volatile("cp.async.commit_group;");
    };

    float acc[2][8][4];
#pragma unroll
    for (int a = 0; a < 2; a++)
#pragma unroll
        for (int b = 0; b < 8; b++)
#pragma unroll
            for (int c = 0; c < 4; c++) acc[a][b][c] = 0.f;

    issue(0);
    for (int ch = 0; ch < 4; ch++) {
        __syncthreads();
        if (ch < 3) {
            issue(ch + 1);
            asm volatile("cp.async.wait_group 1;");
        } else {
            asm volatile("cp.async.wait_group 0;");
        }
        __syncthreads();
        const int b = ch & 1;
        const int k0 = ch * 32;
        if (mode == 2) {
#pragma unroll
            for (int i = 0; i < 4; i++) {
                int f = tid + 256 * i;
                int r = f >> 3, j = (f & 7) << 2;
                int s = is_s[r], et = iet_s[r], dd = idd_s[r];
                float4 p = *(const float4*)(Pm + (size_t)s*HH + k0 + j);
                float4 q = *(const float4*)(Qm + (size_t)et*HH + k0 + j);
                float4 dv = *(const float4*)(Dm + (size_t)dd*HH + k0 + j);
                float4 v;
                v.x = fmaxf(p.x+q.x+dv.x, 0.f); v.y = fmaxf(p.y+q.y+dv.y, 0.f);
                v.z = fmaxf(p.z+q.z+dv.z, 0.f); v.w = fmaxf(p.w+q.w+dv.w, 0.f);
                *(float4*)(ie_out + (e0 + r)*HH + k0 + j) = v;
                unsigned short h, l;
                f2bf(v.x, h, l); sAh[r*APITCH+j+0] = h; sAl[r*APITCH+j+0] = l;
                f2bf(v.y, h, l); sAh[r*APITCH+j+1] = h; sAl[r*APITCH+j+1] = l;
                f2bf(v.z, h, l); sAh[r*APITCH+j+2] = h; sAl[r*APITCH+j+2] = l;
                f2bf(v.w, h, l); sAh[r*APITCH+j+3] = h; sAl[r*APITCH+j+3] = l;
            }
        } else {
            const float* sA = pA32 + b * 4608;
#pragma unroll
            for (int i = 0; i < 4; i++) {
                int f = tid + 256 * i;
                int r = f >> 3, j = (f & 7) << 2;
                float4 v = *(const float4*)(sA + r*A32PITCH + j);
                unsigned short h, l;
                f2bf(v.x, h, l); sAh[r*APITCH+j+0] = h; sAl[r*APITCH+j+0] = l;
                f2bf(v.y, h, l); sAh[r*APITCH+j+1] = h; sAl[r*APITCH+j+1] = l;
                f2bf(v.z, h, l); sAh[r*APITCH+j+2] = h; sAl[r*APITCH+j+2] = l;
                f2bf(v.w, h, l); sAh[r*APITCH+j+3] = h; sAl[r*APITCH+j+3] = l;
            }
        }
        __syncthreads();
        const unsigned short* cWh = pWh + b * 5120;
        const unsigned short* cWl = pWl + b * 5120;
#pragma unroll
        for (int ks = 0; ks < 32; ks += 16) {
            unsigned ah[2][4], al[2][4];
#pragma unroll
            for (int mt = 0; mt < 2; mt++) {
                int rb = wr0 + mt * 16 + g;
                const unsigned short* p = &sAh[rb*APITCH + ks + 2*t];
                ah[mt][0] = *(const unsigned*)p;
                ah[mt][1] = *(const unsigned*)(p + 8*APITCH);
                ah[mt][2] = *(const unsigned*)(p + 8);
                ah[mt][3] = *(const unsigned*)(p + 8*APITCH + 8);
                const unsigned short* q = &sAl[rb*APITCH + ks + 2*t];
                al[mt][0] = *(const unsigned*)q;
                al[mt][1] = *(const unsigned*)(q + 8*APITCH);
                al[mt][2] = *(const unsigned*)(q + 8);
                al[mt][3] = *(const unsigned*)(q + 8*APITCH + 8);
            }
#pragma unroll
            for (int nt = 0; nt < 8; nt++) {
                int cn = wc0 + nt * 8 + g;
                unsigned bh[2], bl[2];
                const unsigned short* p = &cWh[cn*WPIT2 + ks + 2*t];
                bh[0] = *(const unsigned*)p; bh[1] = *(const unsigned*)(p + 8);
                const unsigned short* q = &cWl[cn*WPIT2 + ks + 2*t];
                bl[0] = *(const unsigned*)q; bl[1] = *(const unsigned*)(q + 8);
#pragma unroll
                for (int mt = 0; mt < 2; mt++) {
                    mma16(acc[mt][nt], ah[mt], bh);
                    mma16(acc[mt][nt], ah[mt], bl);
                    mma16(acc[mt][nt], al[mt], bh);
                }
            }
        }
    }

    // attention scalar
#pragma unroll
    for (int mt = 0; mt < 2; mt++) {
        int r0 = wr0 + mt * 16 + g, r1 = r0 + 8;
        const float2* ar0 = (const float2*)(addvec + (size_t)ia_s[r0] * HH);
        const float2* ar1 = (const float2*)(addvec + (size_t)ia_s[r1] * HH);
        float p0 = 0.f, p1 = 0.f;
#pragma unroll
        for (int nt = 0; nt < 8; nt++) {
            int c = wc0 + nt * 8 + t * 2;
            float w0 = w2_s[c], w1 = w2_s[c+1];
            float2 a0 = ar0[c >> 1], a1 = ar1[c >> 1];
            p0 += fmaxf(acc[mt][nt][0] + a0.x, 0.f) * w0
                + fmaxf(acc[mt][nt][1] + a0.y, 0.f) * w1;
            p1 += fmaxf(acc[mt][nt][2] + a1.x, 0.f) * w0
                + fmaxf(acc[mt][nt][3] + a1.y, 0.f) * w1;
        }
        p0 += __shfl_xor_sync(0xffffffffu, p0, 1);
        p0 += __shfl_xor_sync(0xffffffffu, p0, 2);
        p1 += __shfl_xor_sync(0xffffffffu, p1, 1);
        p1 += __shfl_xor_sync(0xffffffffu, p1, 2);
        if (t == 0) {
            part_s[r0 * 2 + (w & 1)] = p0;
            part_s[r1 * 2 + (w & 1)] = p1;
        }
    }
    __syncthreads();
    if (tid < 128) {
        float ps = part_s[tid * 2] + part_s[tid * 2 + 1];
        a_s[tid] = 1.f / (1.f + expf(-ps));
    }
    __syncthreads();

    // output epilogue
#pragma unroll
    for (int i = 0; i < 16; i++) {
        int f = tid + 256 * i;
        int r = f >> 5, q = (f & 31) << 2;
        size_t base = (size_t)(e0 + r) * HH + q;
        float4 iv = *(const float4*)(ie + base);
        float a = a_s[r];
        float4 o;
        if (mode == 1) {
            float4 v4 = *(const float4*)(V + (size_t)is_s[r] * HH + q);
            o.x = fmaxf(iv.x + a*v4.x, 0.f); o.y = fmaxf(iv.y + a*v4.y, 0.f);
            o.z = fmaxf(iv.z + a*v4.z, 0.f); o.w = fmaxf(iv.w + a*v4.w, 0.f);
        } else {
            o = make_float4(iv.x*a, iv.y*a, iv.z*a, iv.w*a);
        }
        *(float4*)(outp + base) = o;
    }
}

// ---------- CSR build ----------
__global__ void k_cnt_zero() {
    int t = blockIdx.x*256 + threadIdx.x;
    if (t < NN) g_cnt[t] = 0;
}
__global__ void k_count(const void* dstp) {
    int e = blockIdx.x*256 + threadIdx.x;
    if (e < NE) atomicAdd(&g_cnt[ld_idx(dstp, e, 0)], 1);
}
__global__ void __launch_bounds__(1024) k_scan1() {
    __shared__ int wsum[32];
    int b = blockIdx.x, t = threadIdx.x;
    int lane = t & 31, wid = t >> 5;
    int v = g_cnt[b*1024 + t];
    int orig = v;
#pragma unroll
    for (int off = 1; off < 32; off <<= 1) {
        int u = __shfl_up_sync(0xffffffffu, v, off);
        if (lane >= off) v += u;
    }
    if (lane == 31) wsum[wid] = v;
    __syncthreads();
    if (wid == 0) {
        int y = wsum[lane];
#pragma unroll
        for (int off = 1; off < 32; off <<= 1) {
            int u = __shfl_up_sync(0xffffffffu, y, off);
            if (lane >= off) y += u;
        }
        wsum[lane] = y;
    }
    __syncthreads();
    int incl = v + (wid ? wsum[wid-1] : 0);
    g_off[b*1024 + t] = incl - orig;
    if (t == 1023) g_bsum[b] = incl;
}
__global__ void k_scan2() {
    int t = threadIdx.x;
    int v = (t < 16) ? g_bsum[t] : 0;
    int x = v;
#pragma unroll
    for (int off = 1; off < 32; off <<= 1) {
        int u = __shfl_up_sync(0xffffffffu, x, off);
        if (t >= off) x += u;
    }
    if (t < 16) g_bpre[t] = x - v;
    if (t == 15) g_off[NN] = x;
}
__global__ void k_scan3() {
    int i = blockIdx.x*256 + threadIdx.x;
    if (i < NN) {
        int o = g_off[i] + g_bpre[i >> 10];
        g_off[i] = o;
        g_cur[i] = o;
    }
}
__global__ void k_fill(const void* dstp) {
    int e = blockIdx.x*256 + threadIdx.x;
    if (e < NE) {
        int d = ld_idx(dstp, e, 0);
        int pos = atomicAdd(&g_cur[d], 1);
        g_eid[pos] = e;
    }
}
// permute index arrays into CSR (dst-sorted) edge order
__global__ void k_perm(const void* src, const void* dstp, const void* etp, const void* elp) {
    int i = blockIdx.x*256 + threadIdx.x;
    if (i < NE) {
        int e = g_eid[i];
        g_srcp[i] = ld_idx(src, e, 0);
        g_dstp[i] = ld_idx(dstp, e, 0);
        g_etp[i]  = ld_idx(etp, e, 1);
        g_elp[i]  = ld_idx(elp, e, 1);
    }
}

// ---------- CSR gather aggregation (contiguous segments after permutation) ----------
__global__ void __launch_bounds__(128) k_gather(const float* __restrict__ me,
                                                const float* __restrict__ addb,
                                                float* __restrict__ out)
{
    int n = blockIdx.x, j = threadIdx.x;
    int o0 = g_off[n], o1 = g_off[n+1];
    float s = addb ? addb[(size_t)n*HH + j] : 0.f;
    for (int i = o0; i < o1; i++)
        s += me[(size_t)i*HH + j];
    out[(size_t)n*HH + j] = s;
}

// ---------- GRU prep ----------
__global__ void k_msg(const float* __restrict__ gru_bias) {
    int t = blockIdx.x*256 + threadIdx.x;
    float v = fmaxf(g_nodeh[t] + gru_bias[t & 127], 0.f);
    g_msg[t] = v;
    int r = t >> 7;
    int s = r & (SS - 1);
    if (s < 2) {
        int b = r / SS;
        g_msg2[((size_t)(b*2 + s))*HH + (t & 127)] = v;
    }
}
__global__ void k_h0() {
    int b = blockIdx.x, j = threadIdx.x;
    float m = -1e30f;
    for (int s = 0; s < SS; s++)
        m = fmaxf(m, g_nodeh[((size_t)(b*SS + s))*HH + j]);
    g_h0[b*HH + j] = m;
}
__global__ void k_twih(const float* __restrict__ Wih) {
    int t = blockIdx.x*256 + threadIdx.x;
    if (t < 2*384*128) {
        int d = t / (384*128), rem = t % (384*128);
        int o = rem / 128, k = rem % 128;
        g_WihT[d*384*128 + k*384 + o] = Wih[t];
    }
}

__global__ void __launch_bounds__(384) k_gru(const float* __restrict__ Whh,
                                             const float* __restrict__ bhh)
{
    const int b = blockIdx.x, dir = blockIdx.y;
    const int o = threadIdx.x;
    float w[128];
    const float* wr = Whh + ((size_t)dir*384 + o)*128;
#pragma unroll
    for (int k = 0; k < 128; k += 4) {
        float4 v = *(const float4*)(wr + k);
        w[k]=v.x; w[k+1]=v.y; w[k+2]=v.z; w[k+3]=v.w;
    }
    const float bh = bhh[dir*384 + o];
    __shared__ float h_s[128];
    __shared__ float gh_s[384];
    if (o < 128) h_s[o] = g_h0[b*128 + o];
    __syncthreads();
    const int nsteps = (dir == 0) ? 2 : SS;
    for (int i2 = 0; i2 < nsteps; i2++) {
        int t = (dir == 0) ? i2 : (SS - 1 - i2);
        float gh = bh;
#pragma unroll
        for (int k = 0; k < 128; k += 4) {
            float4 hv = *(const float4*)&h_s[k];
            gh += w[k]*hv.x + w[k+1]*hv.y + w[k+2]*hv.z + w[k+3]*hv.w;
        }
        gh_s[o] = gh;
        __syncthreads();
        if (o < 128) {
            const float* gi = (dir == 0) ? (g_gif + (size_t)(b*2 + t)*384)
                                         : (g_gi  + (size_t)(b*SS + t)*384);
            float ir = gi[o], iz = gi[128+o], inn = gi[256+o];
            float r = 1.f/(1.f+expf(-(ir + gh_s[o])));
            float z = 1.f/(1.f+expf(-(iz + gh_s[128+o])));
            float n = tanhf(inn + r*gh_s[256+o]);
            float hnew = (1.f-z)*n + z*h_s[o];
            if (dir == 0) {
                if (i2 == 0)      g_y[0*BB*128 + b*128 + o] = hnew;
                else if (i2 == 1) g_y[1*BB*128 + b*128 + o] = hnew;
            } else {
                if (i2 == SS-1)      g_y[2*BB*128 + b*128 + o] = hnew;
                else if (i2 == SS-2) g_y[3*BB*128 + b*128 + o] = hnew;
            }
            h_s[o] = hnew;
        }
        __syncthreads();
    }
}

__global__ void k_final(const float* __restrict__ Wo, const float* __restrict__ bo,
                        const float* __restrict__ rel_emb, const void* trg,
                        const float* __restrict__ l1W, const float* __restrict__ l1b,
                        const float* __restrict__ l2W, const float* __restrict__ l2b,
                        float* __restrict__ out)
{
    const int b = blockIdx.x, j = threadIdx.x;
    __shared__ float conv[128];
    __shared__ float s16[16];
    float hh = bo[j], ht = bo[j];
    const float* yf0 = g_y + 0*BB*128 + b*128;
    const float* yf1 = g_y + 1*BB*128 + b*128;
    const float* yb0 = g_y + 2*BB*128 + b*128;
    const float* yb1 = g_y + 3*BB*128 + b*128;
    for (int k = 0; k < 128; k++) {
        float wk = Wo[k*128 + j];
        hh += yf0[k]*wk; ht += yf1[k]*wk;
    }
    for (int k = 0; k < 128; k++) {
        float wk = Wo[(128+k)*128 + j];
        hh += yb0[k]*wk; ht += yb1[k]*wk;
    }
    hh = fmaxf(hh, 0.f); ht = fmaxf(ht, 0.f);
    int tr = ld_idx(trg, b, 1);
    conv[j] = tanhf(hh + rel_emb[tr*128 + j] - ht);
    __syncthreads();
    if (j < 16) {
        float s = l1b[j];
        for (int k = 0; k < 128; k++) s += conv[k]*l1W[k*16 + j];
        s16[j] = s;
    }
    __syncthreads();
    if (j == 0) {
        float o = l2b[0];
        for (int i = 0; i < 16; i++) o += s16[i]*l2W[i];
        out[b] = o;
    }
}

extern "C" void kernel_launch(void* const* d_in, const int* in_sizes, int n_in,
                              void* d_out, int out_size)
{
    const float* node_feat = (const float*)d_in[0];
    const float* rel_emb   = (const float*)d_in[1];
    const float* W_i_node  = (const float*)d_in[2];
    const float* W_i_edge  = (const float*)d_in[3];
    const float* W_att_in1 = (const float*)d_in[4];
    const float* W_att_in2 = (const float*)d_in[5];
    const float* W_h_node  = (const float*)d_in[6];
    const float* W_h_edge  = (const float*)d_in[7];
    const float* W_att1    = (const float*)d_in[8];
    const float* W_att2    = (const float*)d_in[9];
    const float* comm_W    = (const float*)d_in[10];
    const float* W_o       = (const float*)d_in[11];
    const float* b_o       = (const float*)d_in[12];
    const float* gru_bias  = (const float*)d_in[13];
    const float* gru_Wih   = (const float*)d_in[14];
    const float* gru_Whh   = (const float*)d_in[15];
    const float* gru_bih   = (const float*)d_in[16];
    const float* gru_bhh   = (const float*)d_in[17];
    const float* lin1_W    = (const float*)d_in[18];
    const float* lin1_b    = (const float*)d_in[19];
    const float* lin2_W    = (const float*)d_in[20];
    const float* lin2_b    = (const float*)d_in[21];
    const void*  src       = d_in[22];
    const void*  dst       = d_in[23];
    const void*  etype     = d_in[24];
    const void*  elabel    = d_in[25];
    const void*  trg       = d_in[26];
    float* out = (float*)d_out;

    float *ge_ie, *ge_me, *ge_in, *ge_P, *ge_D, *ge_U, *ge_mn, *ge_agg, *ge_V;
    float *ge_nodeh, *ge_msg, *ge_scr, *ge_gi, *ge_gif, *ge_msg2, *ge_WihT, *ge_Qrel, *ge_Qd;
    unsigned short *ge_Wh, *ge_Wl;
    int *ge_srcp, *ge_dstp, *ge_etp, *ge_elp;
    cudaGetSymbolAddress((void**)&ge_ie, g_ie);
    cudaGetSymbolAddress((void**)&ge_me, g_me);
    cudaGetSymbolAddress((void**)&ge_in, g_in);
    cudaGetSymbolAddress((void**)&ge_P, g_P);
    cudaGetSymbolAddress((void**)&ge_D, g_D);
    cudaGetSymbolAddress((void**)&ge_U, g_U);
    cudaGetSymbolAddress((void**)&ge_mn, g_mn);
    cudaGetSymbolAddress((void**)&ge_agg, g_agg);
    cudaGetSymbolAddress((void**)&ge_V, g_V);
    cudaGetSymbolAddress((void**)&ge_nodeh, g_nodeh);
    cudaGetSymbolAddress((void**)&ge_msg, g_msg);
    cudaGetSymbolAddress((void**)&ge_scr, g_scr);
    cudaGetSymbolAddress((void**)&ge_gi, g_gi);
    cudaGetSymbolAddress((void**)&ge_gif, g_gif);
    cudaGetSymbolAddress((void**)&ge_msg2, g_msg2);
    cudaGetSymbolAddress((void**)&ge_WihT, g_WihT);
    cudaGetSymbolAddress((void**)&ge_Qrel, g_Qrel);
    cudaGetSymbolAddress((void**)&ge_Qd, g_Qd);
    cudaGetSymbolAddress((void**)&ge_Wh, g_Whg);
    cudaGetSymbolAddress((void**)&ge_Wl, g_Wlg);
    cudaGetSymbolAddress((void**)&ge_srcp, g_srcp);
    cudaGetSymbolAddress((void**)&ge_dstp, g_dstp);
    cudaGetSymbolAddress((void**)&ge_etp, g_etp);
    cudaGetSymbolAddress((void**)&ge_elp, g_elp);

    cudaFuncSetAttribute(k_edge_att_tc, cudaFuncAttributeMaxDynamicSharedMemorySize, DYN_BYTES);

    k_detect<<<1, 32>>>(src, etype);

    // CSR of dst + edge permutation
    k_cnt_zero<<<NN/256, 256>>>();
    k_count<<<NE/256, 256>>>(dst);
    k_scan1<<<16, 1024>>>();
    k_scan2<<<1, 32>>>();
    k_scan3<<<NN/256, 256>>>();
    k_fill<<<NE/256, 256>>>(dst);
    k_perm<<<NE/256, 256>>>(src, dst, etype, elabel);

    // edge attention weights -> bf16 hi/lo
    k_wconv<<<64, 256>>>(W_att_in1 + 128*128, ge_Wh,           ge_Wl);
    k_wconv<<<64, 256>>>(W_att1,              ge_Wh + 16384,   ge_Wl + 16384);
    k_wconv<<<64, 256>>>(W_att1 + 32768,      ge_Wh + 32768,   ge_Wl + 32768);

    // node-side GEMMs: P, D, input_node in ONE batched launch
    k_tgemm_bf3<<<dim3(NN/128, 3), 256>>>(node_feat,
        W_i_edge, W_i_edge + 192*128, W_i_node,
        ge_P, ge_D, ge_in, /*reluMask=*/0b100);
    // small rel_emb GEMMs
    k_sgemm<<<dim3(1,2), 256>>>(rel_emb, W_i_edge + 64*128,         ge_Qrel,        RR, 128, 128);
    k_sgemm<<<dim3(1,2), 256>>>(rel_emb, W_att1 + 128*128,          ge_Qd,          RR, 128, 128);
    k_sgemm<<<dim3(1,2), 256>>>(rel_emb, W_att1 + 32768 + 128*128,  ge_Qd + RR*128, RR, 128, 128);

    // fused edge_init + input attention (mode 2), permuted order
    k_tgemm_bf<<<dim3(NN/128, 1), 256>>>(ge_in, W_att_in1, ge_U, 128, 128, NULL, 0, 0);
    k_edge_att_tc<<<NE/128, 256, DYN_BYTES>>>(NULL, ge_Wh, ge_Wl, ge_U, ge_srcp, ge_srcp,
                                              W_att_in2, ge_ie, NULL, ge_me, 2,
                                              ge_P, ge_Qrel, ge_D, ge_etp, ge_dstp, ge_ie);

    // two message-passing depths
    for (int d = 0; d < 2; d++) {
        const float* mn_old = (d == 0) ? ge_in : ge_mn;
        k_gather<<<NN, 128>>>(ge_me, mn_old, ge_scr);
        k_tgemm_bf<<<dim3(NN/128, 1), 256>>>(ge_scr, W_h_node + d*16384, ge_mn, 128, 128, NULL, 1, 0);
        k_tgemm_bf<<<dim3(NN/128, 1), 256>>>(ge_mn, W_h_edge + d*16384, ge_V, 128, 128, NULL, 0, 0);
        k_edge_att_tc<<<NE/128, 256, DYN_BYTES>>>(ge_me, ge_Wh + (d+1)*16384, ge_Wl + (d+1)*16384,
                                                  ge_Qd + d*RR*128, ge_elp,
                                                  ge_srcp, W_att2 + d*128, ge_ie, ge_V, ge_me, 1,
                                                  NULL, NULL, NULL, NULL, NULL, NULL);
    }

    // readout aggregation + single concat GEMM
    k_gather<<<NN, 128>>>(ge_me, NULL, ge_agg);
    k_tgemm_cat3<<<dim3(NN/128, 1), 256>>>(ge_agg, ge_mn, ge_in, comm_W, ge_nodeh);

    // GRU
    k_msg<<<NN*128/256, 256>>>(gru_bias);
    k_h0<<<BB, 128>>>();
    k_twih<<<(2*384*128 + 255)/256, 256>>>(gru_Wih);
    k_tgemm_bf<<<dim3(1, 3), 256>>>(ge_msg2, ge_WihT,           ge_gif, 128, 384, gru_bih,       0, 0);
    k_tgemm_bf<<<dim3(NN/128, 3), 256>>>(ge_msg, ge_WihT + 384*128, ge_gi, 128, 384, gru_bih + 384, 0, 0);
    k_gru<<<dim3(BB, 2), 384>>>(gru_Whh, gru_bhh);

    k_final<<<BB, 128>>>(W_o, b_o, rel_emb, trg, lin1_W, lin1_b, lin2_W, lin2_b, out);
}

// round 13
// speedup vs baseline: 1.3900x; 1.0583x over previous
#include <cuda_runtime.h>
#include <cuda_bf16.h>
#include <math.h>

#define NN 16384
#define NE 262144
#define HH 128
#define BB 64
#define SS 256
#define RR 32

__device__ float g_ie[NE*HH];
__device__ unsigned short g_meh[NE*HH];
__device__ unsigned short g_mel[NE*HH];
__device__ float g_in[NN*HH];
__device__ float g_P[NN*HH];
__device__ float g_D[NN*HH];
__device__ float g_U[NN*HH];
__device__ float g_mn[NN*HH];
__device__ float g_agg[NN*HH];
__device__ float g_V[NN*HH];
__device__ float g_nodeh[NN*HH];
__device__ float g_msg[NN*HH];
__device__ float g_scr[NN*HH];
__device__ float g_gi[NN*384];
__device__ float g_gif[128*384];
__device__ float g_msg2[128*HH];
__device__ float g_WihT[2*384*128];
__device__ float g_Qrel[RR*HH];
__device__ float g_Qd[2*RR*HH];
__device__ float g_h0[BB*HH];
__device__ float g_y[4*BB*HH];
__device__ int   g_is64[2];
__device__ int   g_cnt[NN];
__device__ int   g_off[NN+1];
__device__ int   g_cur[NN];
__device__ int   g_eid[NE];
__device__ int   g_bsum[16], g_bpre[16];
__device__ int   g_srcp[NE], g_dstp[NE], g_etp[NE], g_elp[NE];
__device__ unsigned short g_Whg[3*16384];
__device__ unsigned short g_Wlg[3*16384];

__device__ __forceinline__ int ld_idx(const void* p, long long i, int sel) {
    if (g_is64[sel]) return (int)((const long long*)p)[i];
    return ((const int*)p)[i];
}

__global__ void k_detect(const void* src, const void* et) {
    if (threadIdx.x == 0) {
        const unsigned long long* a = (const unsigned long long*)src;
        int v = 1;
        for (int i = 0; i < 8; i++) if (a[i] >= (unsigned long long)NN) v = 0;
        g_is64[0] = v;
        const unsigned long long* b = (const unsigned long long*)et;
        v = 1;
        for (int i = 0; i < 8; i++) if (b[i] >= (unsigned long long)RR) v = 0;
        g_is64[1] = v;
    }
}

__device__ __forceinline__ void f2bf(float x, unsigned short& h, unsigned short& l) {
    __nv_bfloat16 bh = __float2bfloat16(x);
    h = __bfloat16_as_ushort(bh);
    l = __bfloat16_as_ushort(__float2bfloat16(x - __bfloat162float(bh)));
}

__device__ __forceinline__ float bf2f(unsigned short u) {
    return __bfloat162float(__ushort_as_bfloat16(u));
}

__device__ __forceinline__ void mma16(float* d, const unsigned* a, const unsigned* b) {
    asm volatile("mma.sync.aligned.m16n8k16.row.col.f32.bf16.bf16.f32 "
        "{%0,%1,%2,%3}, {%4,%5,%6,%7}, {%8,%9}, {%0,%1,%2,%3};"
        : "+f"(d[0]), "+f"(d[1]), "+f"(d[2]), "+f"(d[3])
        : "r"(a[0]), "r"(a[1]), "r"(a[2]), "r"(a[3]), "r"(b[0]), "r"(b[1]));
}

__device__ __forceinline__ void cp16(const void* smem_dst, const void* gsrc) {
    unsigned d = (unsigned)__cvta_generic_to_shared(smem_dst);
    asm volatile("cp.async.cg.shared.global [%0], [%1], 16;" :: "r"(d), "l"(gsrc));
}

__global__ void k_wconv(const float* __restrict__ Wm,
                        unsigned short* __restrict__ Wh,
                        unsigned short* __restrict__ Wl)
{
    int t = blockIdx.x*256 + threadIdx.x;
    int k = t >> 7, c = t & 127;
    unsigned short h, l;
    f2bf(Wm[k*128 + c], h, l);
    Wh[c*128 + k] = h;
    Wl[c*128 + k] = l;
}

#define APITCH 40
#define WPITCH 42
#define PIT 40
// dynamic smem (edge_att): Ah dbl, Al dbl, Wh dbl, Wl dbl; each slot 5120 ushorts
#define EA_AH 0
#define EA_AL 20480
#define EA_WH 40960
#define EA_WL 61440
#define DYN_BYTES 81920

// ---------- bf16 3-split tensor-core GEMM ----------
__global__ void __launch_bounds__(256, 2) k_tgemm_bf(
    const float* __restrict__ A, const float* __restrict__ W, float* __restrict__ C,
    int K, int M, const float* __restrict__ bias, int doRelu, int accum)
{
    __shared__ unsigned short sAh[128*APITCH], sAl[128*APITCH];
    __shared__ unsigned short sWh[128*WPITCH], sWl[128*WPITCH];
    const int tid = threadIdx.x;
    const int w = tid >> 5, lane = tid & 31;
    const int g = lane >> 2, t = lane & 3;
    const int wr0 = (w >> 1) * 32, wc0 = (w & 1) * 64;
    const long long row0 = (long long)blockIdx.x * 128;
    const int col0 = blockIdx.y * 128;

    float acc[2][8][4];
#pragma unroll
    for (int a = 0; a < 2; a++)
#pragma unroll
        for (int b = 0; b < 8; b++)
#pragma unroll
            for (int c = 0; c < 4; c++) acc[a][b][c] = 0.f;

    for (int k0 = 0; k0 < K; k0 += 32) {
        __syncthreads();
#pragma unroll
        for (int i = 0; i < 4; i++) {
            int f = tid + 256 * i;
            int r = f >> 3, j = (f & 7) << 2;
            float4 v = *(const float4*)(A + (row0 + r) * K + k0 + j);
            unsigned short h, l;
            f2bf(v.x, h, l); sAh[r*APITCH+j+0] = h; sAl[r*APITCH+j+0] = l;
            f2bf(v.y, h, l); sAh[r*APITCH+j+1] = h; sAl[r*APITCH+j+1] = l;
            f2bf(v.z, h, l); sAh[r*APITCH+j+2] = h; sAl[r*APITCH+j+2] = l;
            f2bf(v.w, h, l); sAh[r*APITCH+j+3] = h; sAl[r*APITCH+j+3] = l;
        }
#pragma unroll
        for (int i = 0; i < 4; i++) {
            int f = tid + 256 * i;
            int kk = f >> 5, c = (f & 31) << 2;
            float4 v = *(const float4*)(W + (long long)(k0 + kk) * M + col0 + c);
            unsigned short h, l;
            f2bf(v.x, h, l); sWh[(c+0)*WPITCH+kk] = h; sWl[(c+0)*WPITCH+kk] = l;
            f2bf(v.y, h, l); sWh[(c+1)*WPITCH+kk] = h; sWl[(c+1)*WPITCH+kk] = l;
            f2bf(v.z, h, l); sWh[(c+2)*WPITCH+kk] = h; sWl[(c+2)*WPITCH+kk] = l;
            f2bf(v.w, h, l); sWh[(c+3)*WPITCH+kk] = h; sWl[(c+3)*WPITCH+kk] = l;
        }
        __syncthreads();
#pragma unroll
        for (int ks = 0; ks < 32; ks += 16) {
            unsigned ah[2][4], al[2][4];
#pragma unroll
            for (int mt = 0; mt < 2; mt++) {
                int rb = wr0 + mt * 16 + g;
                const unsigned short* p = &sAh[rb*APITCH + ks + 2*t];
                ah[mt][0] = *(const unsigned*)p;
                ah[mt][1] = *(const unsigned*)(p + 8*APITCH);
                ah[mt][2] = *(const unsigned*)(p + 8);
                ah[mt][3] = *(const unsigned*)(p + 8*APITCH + 8);
                const unsigned short* q = &sAl[rb*APITCH + ks + 2*t];
                al[mt][0] = *(const unsigned*)q;
                al[mt][1] = *(const unsigned*)(q + 8*APITCH);
                al[mt][2] = *(const unsigned*)(q + 8);
                al[mt][3] = *(const unsigned*)(q + 8*APITCH + 8);
            }
#pragma unroll
            for (int nt = 0; nt < 8; nt++) {
                int cn = wc0 + nt * 8 + g;
                unsigned bh[2], bl[2];
                const unsigned short* p = &sWh[cn*WPITCH + ks + 2*t];
                bh[0] = *(const unsigned*)p; bh[1] = *(const unsigned*)(p + 8);
                const unsigned short* q = &sWl[cn*WPITCH + ks + 2*t];
                bl[0] = *(const unsigned*)q; bl[1] = *(const unsigned*)(q + 8);
#pragma unroll
                for (int mt = 0; mt < 2; mt++) {
                    mma16(acc[mt][nt], ah[mt], bh);
                    mma16(acc[mt][nt], ah[mt], bl);
                    mma16(acc[mt][nt], al[mt], bh);
                }
            }
        }
    }
#pragma unroll
    for (int mt = 0; mt < 2; mt++) {
#pragma unroll
        for (int nt = 0; nt < 8; nt++) {
            int c = col0 + wc0 + nt * 8 + t * 2;
            long long r0 = row0 + wr0 + mt * 16 + g;
            float b0 = bias ? bias[c] : 0.f, b1 = bias ? bias[c+1] : 0.f;
            float v0 = acc[mt][nt][0] + b0, v1 = acc[mt][nt][1] + b1;
            float v2 = acc[mt][nt][2] + b0, v3 = acc[mt][nt][3] + b1;
            if (accum) {
                float2 o0 = *(const float2*)(C + r0 * M + c);
                float2 o1 = *(const float2*)(C + (r0 + 8) * M + c);
                v0 += o0.x; v1 += o0.y; v2 += o1.x; v3 += o1.y;
            }
            if (doRelu) {
                v0 = fmaxf(v0, 0.f); v1 = fmaxf(v1, 0.f);
                v2 = fmaxf(v2, 0.f); v3 = fmaxf(v3, 0.f);
            }
            *(float2*)(C + r0 * M + c)       = make_float2(v0, v1);
            *(float2*)(C + (r0 + 8) * M + c) = make_float2(v2, v3);
        }
    }
}

// ---------- batched variant: blockIdx.y selects one of 3 (W,C) pairs; A shared; K=64 ----------
__global__ void __launch_bounds__(256, 2) k_tgemm_bf3(
    const float* __restrict__ A,
    const float* __restrict__ W0, const float* __restrict__ W1, const float* __restrict__ W2,
    float* __restrict__ C0, float* __restrict__ C1, float* __restrict__ C2, int reluMask)
{
    const float* W = (blockIdx.y == 0) ? W0 : ((blockIdx.y == 1) ? W1 : W2);
    float* C = (blockIdx.y == 0) ? C0 : ((blockIdx.y == 1) ? C1 : C2);
    const int doRelu = (reluMask >> blockIdx.y) & 1;
    __shared__ unsigned short sAh[128*APITCH], sAl[128*APITCH];
    __shared__ unsigned short sWh[128*WPITCH], sWl[128*WPITCH];
    const int tid = threadIdx.x;
    const int w = tid >> 5, lane = tid & 31;
    const int g = lane >> 2, t = lane & 3;
    const int wr0 = (w >> 1) * 32, wc0 = (w & 1) * 64;
    const long long row0 = (long long)blockIdx.x * 128;

    float acc[2][8][4];
#pragma unroll
    for (int a = 0; a < 2; a++)
#pragma unroll
        for (int b = 0; b < 8; b++)
#pragma unroll
            for (int c = 0; c < 4; c++) acc[a][b][c] = 0.f;

    for (int k0 = 0; k0 < 64; k0 += 32) {
        __syncthreads();
#pragma unroll
        for (int i = 0; i < 4; i++) {
            int f = tid + 256 * i;
            int r = f >> 3, j = (f & 7) << 2;
            float4 v = *(const float4*)(A + (row0 + r) * 64 + k0 + j);
            unsigned short h, l;
            f2bf(v.x, h, l); sAh[r*APITCH+j+0] = h; sAl[r*APITCH+j+0] = l;
            f2bf(v.y, h, l); sAh[r*APITCH+j+1] = h; sAl[r*APITCH+j+1] = l;
            f2bf(v.z, h, l); sAh[r*APITCH+j+2] = h; sAl[r*APITCH+j+2] = l;
            f2bf(v.w, h, l); sAh[r*APITCH+j+3] = h; sAl[r*APITCH+j+3] = l;
        }
#pragma unroll
        for (int i = 0; i < 4; i++) {
            int f = tid + 256 * i;
            int kk = f >> 5, c = (f & 31) << 2;
            float4 v = *(const float4*)(W + (long long)(k0 + kk) * 128 + c);
            unsigned short h, l;
            f2bf(v.x, h, l); sWh[(c+0)*WPITCH+kk] = h; sWl[(c+0)*WPITCH+kk] = l;
            f2bf(v.y, h, l); sWh[(c+1)*WPITCH+kk] = h; sWl[(c+1)*WPITCH+kk] = l;
            f2bf(v.z, h, l); sWh[(c+2)*WPITCH+kk] = h; sWl[(c+2)*WPITCH+kk] = l;
            f2bf(v.w, h, l); sWh[(c+3)*WPITCH+kk] = h; sWl[(c+3)*WPITCH+kk] = l;
        }
        __syncthreads();
#pragma unroll
        for (int ks = 0; ks < 32; ks += 16) {
            unsigned ah[2][4], al[2][4];
#pragma unroll
            for (int mt = 0; mt < 2; mt++) {
                int rb = wr0 + mt * 16 + g;
                const unsigned short* p = &sAh[rb*APITCH + ks + 2*t];
                ah[mt][0] = *(const unsigned*)p;
                ah[mt][1] = *(const unsigned*)(p + 8*APITCH);
                ah[mt][2] = *(const unsigned*)(p + 8);
                ah[mt][3] = *(const unsigned*)(p + 8*APITCH + 8);
                const unsigned short* q = &sAl[rb*APITCH + ks + 2*t];
                al[mt][0] = *(const unsigned*)q;
                al[mt][1] = *(const unsigned*)(q + 8*APITCH);
                al[mt][2] = *(const unsigned*)(q + 8);
                al[mt][3] = *(const unsigned*)(q + 8*APITCH + 8);
            }
#pragma unroll
            for (int nt = 0; nt < 8; nt++) {
                int cn = wc0 + nt * 8 + g;
                unsigned bh[2], bl[2];
                const unsigned short* p = &sWh[cn*WPITCH + ks + 2*t];
                bh[0] = *(const unsigned*)p; bh[1] = *(const unsigned*)(p + 8);
                const unsigned short* q = &sWl[cn*WPITCH + ks + 2*t];
                bl[0] = *(const unsigned*)q; bl[1] = *(const unsigned*)(q + 8);
#pragma unroll
                for (int mt = 0; mt < 2; mt++) {
                    mma16(acc[mt][nt], ah[mt], bh);
                    mma16(acc[mt][nt], ah[mt], bl);
                    mma16(acc[mt][nt], al[mt], bh);
                }
            }
        }
    }
#pragma unroll
    for (int mt = 0; mt < 2; mt++) {
#pragma unroll
        for (int nt = 0; nt < 8; nt++) {
            int c = wc0 + nt * 8 + t * 2;
            long long r0 = row0 + wr0 + mt * 16 + g;
            float v0 = acc[mt][nt][0], v1 = acc[mt][nt][1];
            float v2 = acc[mt][nt][2], v3 = acc[mt][nt][3];
            if (doRelu) {
                v0 = fmaxf(v0, 0.f); v1 = fmaxf(v1, 0.f);
                v2 = fmaxf(v2, 0.f); v3 = fmaxf(v3, 0.f);
            }
            *(float2*)(C + r0 * 128 + c)       = make_float2(v0, v1);
            *(float2*)(C + (r0 + 8) * 128 + c) = make_float2(v2, v3);
        }
    }
}

// ---------- concat GEMM: C = [A0|A1|A2] @ W(384x128) ----------
__global__ void __launch_bounds__(256, 2) k_tgemm_cat3(
    const float* __restrict__ A0, const float* __restrict__ A1, const float* __restrict__ A2,
    const float* __restrict__ W, float* __restrict__ C)
{
    __shared__ unsigned short sAh[128*APITCH], sAl[128*APITCH];
    __shared__ unsigned short sWh[128*WPITCH], sWl[128*WPITCH];
    const int tid = threadIdx.x;
    const int w = tid >> 5, lane = tid & 31;
    const int g = lane >> 2, t = lane & 3;
    const int wr0 = (w >> 1) * 32, wc0 = (w & 1) * 64;
    const long long row0 = (long long)blockIdx.x * 128;

    float acc[2][8][4];
#pragma unroll
    for (int a = 0; a < 2; a++)
#pragma unroll
        for (int b = 0; b < 8; b++)
#pragma unroll
            for (int c = 0; c < 4; c++) acc[a][b][c] = 0.f;

    for (int ch = 0; ch < 12; ch++) {
        const int k0 = ch * 32;
        const float* A = (ch < 4) ? A0 : ((ch < 8) ? A1 : A2);
        const int kloc = (ch & 3) * 32;
        __syncthreads();
#pragma unroll
        for (int i = 0; i < 4; i++) {
            int f = tid + 256 * i;
            int r = f >> 3, j = (f & 7) << 2;
            float4 v = *(const float4*)(A + (row0 + r) * 128 + kloc + j);
            unsigned short h, l;
            f2bf(v.x, h, l); sAh[r*APITCH+j+0] = h; sAl[r*APITCH+j+0] = l;
            f2bf(v.y, h, l); sAh[r*APITCH+j+1] = h; sAl[r*APITCH+j+1] = l;
            f2bf(v.z, h, l); sAh[r*APITCH+j+2] = h; sAl[r*APITCH+j+2] = l;
            f2bf(v.w, h, l); sAh[r*APITCH+j+3] = h; sAl[r*APITCH+j+3] = l;
        }
#pragma unroll
        for (int i = 0; i < 4; i++) {
            int f = tid + 256 * i;
            int kk = f >> 5, c = (f & 31) << 2;
            float4 v = *(const float4*)(W + (long long)(k0 + kk) * 128 + c);
            unsigned short h, l;
            f2bf(v.x, h, l); sWh[(c+0)*WPITCH+kk] = h; sWl[(c+0)*WPITCH+kk] = l;
            f2bf(v.y, h, l); sWh[(c+1)*WPITCH+kk] = h; sWl[(c+1)*WPITCH+kk] = l;
            f2bf(v.z, h, l); sWh[(c+2)*WPITCH+kk] = h; sWl[(c+2)*WPITCH+kk] = l;
            f2bf(v.w, h, l); sWh[(c+3)*WPITCH+kk] = h; sWl[(c+3)*WPITCH+kk] = l;
        }
        __syncthreads();
#pragma unroll
        for (int ks = 0; ks < 32; ks += 16) {
            unsigned ah[2][4], al[2][4];
#pragma unroll
            for (int mt = 0; mt < 2; mt++) {
                int rb = wr0 + mt * 16 + g;
                const unsigned short* p = &sAh[rb*APITCH + ks + 2*t];
                ah[mt][0] = *(const unsigned*)p;
                ah[mt][1] = *(const unsigned*)(p + 8*APITCH);
                ah[mt][2] = *(const unsigned*)(p + 8);
                ah[mt][3] = *(const unsigned*)(p + 8*APITCH + 8);
                const unsigned short* q = &sAl[rb*APITCH + ks + 2*t];
                al[mt][0] = *(const unsigned*)q;
                al[mt][1] = *(const unsigned*)(q + 8*APITCH);
                al[mt][2] = *(const unsigned*)(q + 8);
                al[mt][3] = *(const unsigned*)(q + 8*APITCH + 8);
            }
#pragma unroll
            for (int nt = 0; nt < 8; nt++) {
                int cn = wc0 + nt * 8 + g;
                unsigned bh[2], bl[2];
                const unsigned short* p = &sWh[cn*WPITCH + ks + 2*t];
                bh[0] = *(const unsigned*)p; bh[1] = *(const unsigned*)(p + 8);
                const unsigned short* q = &sWl[cn*WPITCH + ks + 2*t];
                bl[0] = *(const unsigned*)q; bl[1] = *(const unsigned*)(q + 8);
#pragma unroll
                for (int mt = 0; mt < 2; mt++) {
                    mma16(acc[mt][nt], ah[mt], bh);
                    mma16(acc[mt][nt], ah[mt], bl);
                    mma16(acc[mt][nt], al[mt], bh);
                }
            }
        }
    }
#pragma unroll
    for (int mt = 0; mt < 2; mt++) {
#pragma unroll
        for (int nt = 0; nt < 8; nt++) {
            int c = wc0 + nt * 8 + t * 2;
            long long r0 = row0 + wr0 + mt * 16 + g;
            *(float2*)(C + r0 * 128 + c)       = make_float2(acc[mt][nt][0], acc[mt][nt][1]);
            *(float2*)(C + (r0 + 8) * 128 + c) = make_float2(acc[mt][nt][2], acc[mt][nt][3]);
        }
    }
}

// ---------- small SIMT GEMM for 32-row rel_emb GEMMs ----------
__global__ void k_sgemm(const float* __restrict__ A, const float* __restrict__ W,
                        float* __restrict__ C, int rows, int K, int M)
{
    __shared__ float As[16][64];
    __shared__ float Ws[16][64];
    const int tid = threadIdx.x;
    const int tx = tid & 15, ty = tid >> 4;
    const int row0 = blockIdx.x * 64, col0 = blockIdx.y * 64;
    const int la_r = tid >> 2, la_k = (tid & 3) << 2;
    const int lw_k = tid >> 4, lw_c = (tid & 15) << 2;
    float acc[4][4];
#pragma unroll
    for (int i = 0; i < 4; i++)
#pragma unroll
        for (int j = 0; j < 4; j++) acc[i][j] = 0.f;
    for (int k0 = 0; k0 < K; k0 += 16) {
        float4 av = make_float4(0.f,0.f,0.f,0.f);
        if (row0 + la_r < rows)
            av = *(const float4*)(A + (size_t)(row0 + la_r) * K + (k0 + la_k));
        As[la_k+0][la_r] = av.x; As[la_k+1][la_r] = av.y;
        As[la_k+2][la_r] = av.z; As[la_k+3][la_r] = av.w;
        *(float4*)&Ws[lw_k][lw_c] = *(const float4*)(W + (size_t)(k0+lw_k)*M + col0 + lw_c);
        __syncthreads();
#pragma unroll
        for (int k = 0; k < 16; k++) {
            float4 a4 = *(const float4*)&As[k][ty<<2];
            float4 w4 = *(const float4*)&Ws[k][tx<<2];
            float ar[4] = {a4.x,a4.y,a4.z,a4.w};
            float wr[4] = {w4.x,w4.y,w4.z,w4.w};
#pragma unroll
            for (int i = 0; i < 4; i++)
#pragma unroll
                for (int j = 0; j < 4; j++) acc[i][j] += ar[i]*wr[j];
        }
        __syncthreads();
    }
#pragma unroll
    for (int i = 0; i < 4; i++) {
        int r = row0 + (ty<<2) + i;
        if (r < rows)
#pragma unroll
            for (int j = 0; j < 4; j++)
                C[(size_t)r*M + col0 + (tx<<2) + j] = acc[i][j];
    }
}

// ---------- bf16 edge attention: A already bf16 hi/lo (mode 1) or computed (mode 2) ----------
// mode 1: A = me (bf16 hi/lo via cp.async); out = relu(ie + a*V[src]) -> bf16 hi/lo
// mode 2: A = relu(P[src]+Q[et]+D[dst]) computed, ie written fp32; out = ie*a -> bf16 hi/lo
__global__ void __launch_bounds__(256, 2) k_edge_att_tc(
    const unsigned short* __restrict__ Xh, const unsigned short* __restrict__ Xl,
    const unsigned short* __restrict__ Wh, const unsigned short* __restrict__ Wl,
    const float* __restrict__ addvec, const int* __restrict__ idx_add,
    const int* __restrict__ idx_src, const float* __restrict__ w2,
    const float* __restrict__ ie, const float* __restrict__ V,
    unsigned short* __restrict__ outh, unsigned short* __restrict__ outl, int mode,
    const float* __restrict__ Pm, const float* __restrict__ Qm,
    const float* __restrict__ Dm, const int* __restrict__ idx_et,
    const int* __restrict__ idx_dst, float* __restrict__ ie_out)
{
    extern __shared__ char dynsm[];
    unsigned short* pAh = (unsigned short*)(dynsm + EA_AH);
    unsigned short* pAl = (unsigned short*)(dynsm + EA_AL);
    unsigned short* pWh = (unsigned short*)(dynsm + EA_WH);
    unsigned short* pWl = (unsigned short*)(dynsm + EA_WL);
    __shared__ int ia_s[128], is_s[128], iet_s[128], idd_s[128];
    __shared__ float a_s[128], part_s[256], w2_s[128];

    const int tid = threadIdx.x;
    const int w = tid >> 5, lane = tid & 31;
    const int g = lane >> 2, t = lane & 3;
    const int wr0 = (w >> 1) * 32, wc0 = (w & 1) * 64;
    const long long e0 = (long long)blockIdx.x * 128;

    if (tid < 128) {
        ia_s[tid] = idx_add[e0 + tid];
        is_s[tid] = idx_src[e0 + tid];
        w2_s[tid] = w2[tid];
        if (mode == 2) {
            iet_s[tid] = idx_et[e0 + tid];
            idd_s[tid] = idx_dst[e0 + tid];
        }
    }

    auto issue = [&](int chunk) {
        int b = chunk & 1;
        int k0 = chunk * 32;
        if (mode != 2) {
            unsigned short* dAh = pAh + b * 5120;
            unsigned short* dAl = pAl + b * 5120;
#pragma unroll
            for (int it = 0; it < 2; it++) {
                int f = tid + 256 * it;
                int r = f >> 2, seg = f & 3;
                cp16(dAh + r*PIT + seg*8, Xh + (e0 + r)*HH + k0 + seg*8);
                cp16(dAl + r*PIT + seg*8, Xl + (e0 + r)*HH + k0 + seg*8);
            }
        }
        unsigned short* dWh = pWh + b * 5120;
        unsigned short* dWl = pWl + b * 5120;
#pragma unroll
        for (int it = 0; it < 2; it++) {
            int f = tid + 256 * it;
            int c = f >> 2, seg = f & 3;
            cp16(dWh + c*PIT + seg*8, Wh + c*128 + k0 + seg*8);
            cp16(dWl + c*PIT + seg*8, Wl + c*128 + k0 + seg*8);
        }
        asm volatile("cp.async.commit_group;");
    };

    float acc[2][8][4];
#pragma unroll
    for (int a = 0; a < 2; a++)
#pragma unroll
        for (int b = 0; b < 8; b++)
#pragma unroll
            for (int c = 0; c < 4; c++) acc[a][b][c] = 0.f;

    issue(0);
    for (int ch = 0; ch < 4; ch++) {
        __syncthreads();   // drain reads of the buffer about to be overwritten
        if (ch < 3) {
            issue(ch + 1);
            asm volatile("cp.async.wait_group 1;");
        } else {
            asm volatile("cp.async.wait_group 0;");
        }
        __syncthreads();
        const int b = ch & 1;
        const int k0 = ch * 32;
        if (mode == 2) {
            unsigned short* dAh = pAh + b * 5120;
            unsigned short* dAl = pAl + b * 5120;
#pragma unroll
            for (int i = 0; i < 4; i++) {
                int f = tid + 256 * i;
                int r = f >> 3, j = (f & 7) << 2;
                int s = is_s[r], et = iet_s[r], dd = idd_s[r];
                float4 p = *(const float4*)(Pm + (size_t)s*HH + k0 + j);
                float4 q = *(const float4*)(Qm + (size_t)et*HH + k0 + j);
                float4 dv = *(const float4*)(Dm + (size_t)dd*HH + k0 + j);
                float4 v;
                v.x = fmaxf(p.x+q.x+dv.x, 0.f); v.y = fmaxf(p.y+q.y+dv.y, 0.f);
                v.z = fmaxf(p.z+q.z+dv.z, 0.f); v.w = fmaxf(p.w+q.w+dv.w, 0.f);
                *(float4*)(ie_out + (e0 + r)*HH + k0 + j) = v;
                unsigned short h, l;
                f2bf(v.x, h, l); dAh[r*PIT+j+0] = h; dAl[r*PIT+j+0] = l;
                f2bf(v.y, h, l); dAh[r*PIT+j+1] = h; dAl[r*PIT+j+1] = l;
                f2bf(v.z, h, l); dAh[r*PIT+j+2] = h; dAl[r*PIT+j+2] = l;
                f2bf(v.w, h, l); dAh[r*PIT+j+3] = h; dAl[r*PIT+j+3] = l;
            }
            __syncthreads();
        }
        const unsigned short* cAh = pAh + b * 5120;
        const unsigned short* cAl = pAl + b * 5120;
        const unsigned short* cWh = pWh + b * 5120;
        const unsigned short* cWl = pWl + b * 5120;
#pragma unroll
        for (int ks = 0; ks < 32; ks += 16) {
            unsigned ah[2][4], al[2][4];
#pragma unroll
            for (int mt = 0; mt < 2; mt++) {
                int rb = wr0 + mt * 16 + g;
                const unsigned short* p = &cAh[rb*PIT + ks + 2*t];
                ah[mt][0] = *(const unsigned*)p;
                ah[mt][1] = *(const unsigned*)(p + 8*PIT);
                ah[mt][2] = *(const unsigned*)(p + 8);
                ah[mt][3] = *(const unsigned*)(p + 8*PIT + 8);
                const unsigned short* q = &cAl[rb*PIT + ks + 2*t];
                al[mt][0] = *(const unsigned*)q;
                al[mt][1] = *(const unsigned*)(q + 8*PIT);
                al[mt][2] = *(const unsigned*)(q + 8);
                al[mt][3] = *(const unsigned*)(q + 8*PIT + 8);
            }
#pragma unroll
            for (int nt = 0; nt < 8; nt++) {
                int cn = wc0 + nt * 8 + g;
                unsigned bh[2], bl[2];
                const unsigned short* p = &cWh[cn*PIT + ks + 2*t];
                bh[0] = *(const unsigned*)p; bh[1] = *(const unsigned*)(p + 8);
                const unsigned short* q = &cWl[cn*PIT + ks + 2*t];
                bl[0] = *(const unsigned*)q; bl[1] = *(const unsigned*)(q + 8);
#pragma unroll
                for (int mt = 0; mt < 2; mt++) {
                    mma16(acc[mt][nt], ah[mt], bh);
                    mma16(acc[mt][nt], ah[mt], bl);
                    mma16(acc[mt][nt], al[mt], bh);
                }
            }
        }
    }

    // attention scalar
#pragma unroll
    for (int mt = 0; mt < 2; mt++) {
        int r0 = wr0 + mt * 16 + g, r1 = r0 + 8;
        const float2* ar0 = (const float2*)(addvec + (size_t)ia_s[r0] * HH);
        const float2* ar1 = (const float2*)(addvec + (size_t)ia_s[r1] * HH);
        float p0 = 0.f, p1 = 0.f;
#pragma unroll
        for (int nt = 0; nt < 8; nt++) {
            int c = wc0 + nt * 8 + t * 2;
            float w0 = w2_s[c], w1 = w2_s[c+1];
            float2 a0 = ar0[c >> 1], a1 = ar1[c >> 1];
            p0 += fmaxf(acc[mt][nt][0] + a0.x, 0.f) * w0
                + fmaxf(acc[mt][nt][1] + a0.y, 0.f) * w1;
            p1 += fmaxf(acc[mt][nt][2] + a1.x, 0.f) * w0
                + fmaxf(acc[mt][nt][3] + a1.y, 0.f) * w1;
        }
        p0 += __shfl_xor_sync(0xffffffffu, p0, 1);
        p0 += __shfl_xor_sync(0xffffffffu, p0, 2);
        p1 += __shfl_xor_sync(0xffffffffu, p1, 1);
        p1 += __shfl_xor_sync(0xffffffffu, p1, 2);
        if (t == 0) {
            part_s[r0 * 2 + (w & 1)] = p0;
            part_s[r1 * 2 + (w & 1)] = p1;
        }
    }
    __syncthreads();
    if (tid < 128) {
        float ps = part_s[tid * 2] + part_s[tid * 2 + 1];
        a_s[tid] = 1.f / (1.f + expf(-ps));
    }
    __syncthreads();

    // output epilogue: write me as bf16 hi/lo
#pragma unroll
    for (int i = 0; i < 16; i++) {
        int f = tid + 256 * i;
        int r = f >> 5, q = (f & 31) << 2;
        size_t base = (size_t)(e0 + r) * HH + q;
        float4 iv = *(const float4*)(ie + base);
        float a = a_s[r];
        float4 o;
        if (mode == 1) {
            float4 v4 = *(const float4*)(V + (size_t)is_s[r] * HH + q);
            o.x = fmaxf(iv.x + a*v4.x, 0.f); o.y = fmaxf(iv.y + a*v4.y, 0.f);
            o.z = fmaxf(iv.z + a*v4.z, 0.f); o.w = fmaxf(iv.w + a*v4.w, 0.f);
        } else {
            o = make_float4(iv.x*a, iv.y*a, iv.z*a, iv.w*a);
        }
        ushort4 oh, ol;
        f2bf(o.x, oh.x, ol.x); f2bf(o.y, oh.y, ol.y);
        f2bf(o.z, oh.z, ol.z); f2bf(o.w, oh.w, ol.w);
        *(ushort4*)(outh + base) = oh;
        *(ushort4*)(outl + base) = ol;
    }
}

// ---------- CSR build ----------
__global__ void k_cnt_zero() {
    int t = blockIdx.x*256 + threadIdx.x;
    if (t < NN) g_cnt[t] = 0;
}
__global__ void k_count(const void* dstp) {
    int e = blockIdx.x*256 + threadIdx.x;
    if (e < NE) atomicAdd(&g_cnt[ld_idx(dstp, e, 0)], 1);
}
__global__ void __launch_bounds__(1024) k_scan1() {
    __shared__ int wsum[32];
    int b = blockIdx.x, t = threadIdx.x;
    int lane = t & 31, wid = t >> 5;
    int v = g_cnt[b*1024 + t];
    int orig = v;
#pragma unroll
    for (int off = 1; off < 32; off <<= 1) {
        int u = __shfl_up_sync(0xffffffffu, v, off);
        if (lane >= off) v += u;
    }
    if (lane == 31) wsum[wid] = v;
    __syncthreads();
    if (wid == 0) {
        int y = wsum[lane];
#pragma unroll
        for (int off = 1; off < 32; off <<= 1) {
            int u = __shfl_up_sync(0xffffffffu, y, off);
            if (lane >= off) y += u;
        }
        wsum[lane] = y;
    }
    __syncthreads();
    int incl = v + (wid ? wsum[wid-1] : 0);
    g_off[b*1024 + t] = incl - orig;
    if (t == 1023) g_bsum[b] = incl;
}
__global__ void k_scan2() {
    int t = threadIdx.x;
    int v = (t < 16) ? g_bsum[t] : 0;
    int x = v;
#pragma unroll
    for (int off = 1; off < 32; off <<= 1) {
        int u = __shfl_up_sync(0xffffffffu, x, off);
        if (t >= off) x += u;
    }
    if (t < 16) g_bpre[t] = x - v;
    if (t == 15) g_off[NN] = x;
}
__global__ void k_scan3() {
    int i = blockIdx.x*256 + threadIdx.x;
    if (i < NN) {
        int o = g_off[i] + g_bpre[i >> 10];
        g_off[i] = o;
        g_cur[i] = o;
    }
}
__global__ void k_fill(const void* dstp) {
    int e = blockIdx.x*256 + threadIdx.x;
    if (e < NE) {
        int d = ld_idx(dstp, e, 0);
        int pos = atomicAdd(&g_cur[d], 1);
        g_eid[pos] = e;
    }
}
__global__ void k_perm(const void* src, const void* dstp, const void* etp, const void* elp) {
    int i = blockIdx.x*256 + threadIdx.x;
    if (i < NE) {
        int e = g_eid[i];
        g_srcp[i] = ld_idx(src, e, 0);
        g_dstp[i] = ld_idx(dstp, e, 0);
        g_etp[i]  = ld_idx(etp, e, 1);
        g_elp[i]  = ld_idx(elp, e, 1);
    }
}

// ---------- CSR gather aggregation (contiguous, bf16 hi/lo reconstruct) ----------
__global__ void __launch_bounds__(128) k_gather(const unsigned short* __restrict__ meh,
                                                const unsigned short* __restrict__ mel,
                                                const float* __restrict__ addb,
                                                float* __restrict__ out)
{
    int n = blockIdx.x, j = threadIdx.x;
    int o0 = g_off[n], o1 = g_off[n+1];
    float s = addb ? addb[(size_t)n*HH + j] : 0.f;
    for (int i = o0; i < o1; i++)
        s += bf2f(meh[(size_t)i*HH + j]) + bf2f(mel[(size_t)i*HH + j]);
    out[(size_t)n*HH + j] = s;
}

// ---------- GRU prep ----------
__global__ void k_msg(const float* __restrict__ gru_bias) {
    int t = blockIdx.x*256 + threadIdx.x;
    float v = fmaxf(g_nodeh[t] + gru_bias[t & 127], 0.f);
    g_msg[t] = v;
    int r = t >> 7;
    int s = r & (SS - 1);
    if (s < 2) {
        int b = r / SS;
        g_msg2[((size_t)(b*2 + s))*HH + (t & 127)] = v;
    }
}
__global__ void k_h0() {
    int b = blockIdx.x, j = threadIdx.x;
    float m = -1e30f;
    for (int s = 0; s < SS; s++)
        m = fmaxf(m, g_nodeh[((size_t)(b*SS + s))*HH + j]);
    g_h0[b*HH + j] = m;
}
__global__ void k_twih(const float* __restrict__ Wih) {
    int t = blockIdx.x*256 + threadIdx.x;
    if (t < 2*384*128) {
        int d = t / (384*128), rem = t % (384*128);
        int o = rem / 128, k = rem % 128;
        g_WihT[d*384*128 + k*384 + o] = Wih[t];
    }
}

__global__ void __launch_bounds__(384) k_gru(const float* __restrict__ Whh,
                                             const float* __restrict__ bhh)
{
    const int b = blockIdx.x, dir = blockIdx.y;
    const int o = threadIdx.x;
    float w[128];
    const float* wr = Whh + ((size_t)dir*384 + o)*128;
#pragma unroll
    for (int k = 0; k < 128; k += 4) {
        float4 v = *(const float4*)(wr + k);
        w[k]=v.x; w[k+1]=v.y; w[k+2]=v.z; w[k+3]=v.w;
    }
    const float bh = bhh[dir*384 + o];
    __shared__ float h_s[128];
    __shared__ float gh_s[384];
    if (o < 128) h_s[o] = g_h0[b*128 + o];
    __syncthreads();
    const int nsteps = (dir == 0) ? 2 : SS;
    for (int i2 = 0; i2 < nsteps; i2++) {
        int t = (dir == 0) ? i2 : (SS - 1 - i2);
        float g0 = 0.f, g1 = 0.f, g2 = 0.f, g3 = 0.f;
#pragma unroll
        for (int k = 0; k < 128; k += 16) {
            float4 a = *(const float4*)&h_s[k];
            float4 b4 = *(const float4*)&h_s[k+4];
            float4 c4 = *(const float4*)&h_s[k+8];
            float4 d4 = *(const float4*)&h_s[k+12];
            g0 += w[k]*a.x + w[k+1]*a.y + w[k+2]*a.z + w[k+3]*a.w;
            g1 += w[k+4]*b4.x + w[k+5]*b4.y + w[k+6]*b4.z + w[k+7]*b4.w;
            g2 += w[k+8]*c4.x + w[k+9]*c4.y + w[k+10]*c4.z + w[k+11]*c4.w;
            g3 += w[k+12]*d4.x + w[k+13]*d4.y + w[k+14]*d4.z + w[k+15]*d4.w;
        }
        gh_s[o] = bh + ((g0 + g1) + (g2 + g3));
        __syncthreads();
        if (o < 128) {
            const float* gi = (dir == 0) ? (g_gif + (size_t)(b*2 + t)*384)
                                         : (g_gi  + (size_t)(b*SS + t)*384);
            float ir = gi[o], iz = gi[128+o], inn = gi[256+o];
            float r = 1.f/(1.f+expf(-(ir + gh_s[o])));
            float z = 1.f/(1.f+expf(-(iz + gh_s[128+o])));
            float n = tanhf(inn + r*gh_s[256+o]);
            float hnew = (1.f-z)*n + z*h_s[o];
            if (dir == 0) {
                if (i2 == 0)      g_y[0*BB*128 + b*128 + o] = hnew;
                else if (i2 == 1) g_y[1*BB*128 + b*128 + o] = hnew;
            } else {
                if (i2 == SS-1)      g_y[2*BB*128 + b*128 + o] = hnew;
                else if (i2 == SS-2) g_y[3*BB*128 + b*128 + o] = hnew;
            }
            h_s[o] = hnew;
        }
        __syncthreads();
    }
}

__global__ void k_final(const float* __restrict__ Wo, const float* __restrict__ bo,
                        const float* __restrict__ rel_emb, const void* trg,
                        const float* __restrict__ l1W, const float* __restrict__ l1b,
                        const float* __restrict__ l2W, const float* __restrict__ l2b,
                        float* __restrict__ out)
{
    const int b = blockIdx.x, j = threadIdx.x;
    __shared__ float conv[128];
    __shared__ float s16[16];
    float hh = bo[j], ht = bo[j];
    const float* yf0 = g_y + 0*BB*128 + b*128;
    const float* yf1 = g_y + 1*BB*128 + b*128;
    const float* yb0 = g_y + 2*BB*128 + b*128;
    const float* yb1 = g_y + 3*BB*128 + b*128;
    for (int k = 0; k < 128; k++) {
        float wk = Wo[k*128 + j];
        hh += yf0[k]*wk; ht += yf1[k]*wk;
    }
    for (int k = 0; k < 128; k++) {
        float wk = Wo[(128+k)*128 + j];
        hh += yb0[k]*wk; ht += yb1[k]*wk;
    }
    hh = fmaxf(hh, 0.f); ht = fmaxf(ht, 0.f);
    int tr = ld_idx(trg, b, 1);
    conv[j] = tanhf(hh + rel_emb[tr*128 + j] - ht);
    __syncthreads();
    if (j < 16) {
        float s = l1b[j];
        for (int k = 0; k < 128; k++) s += conv[k]*l1W[k*16 + j];
        s16[j] = s;
    }
    __syncthreads();
    if (j == 0) {
        float o = l2b[0];
        for (int i = 0; i < 16; i++) o += s16[i]*l2W[i];
        out[b] = o;
    }
}

extern "C" void kernel_launch(void* const* d_in, const int* in_sizes, int n_in,
                              void* d_out, int out_size)
{
    const float* node_feat = (const float*)d_in[0];
    const float* rel_emb   = (const float*)d_in[1];
    const float* W_i_node  = (const float*)d_in[2];
    const float* W_i_edge  = (const float*)d_in[3];
    const float* W_att_in1 = (const float*)d_in[4];
    const float* W_att_in2 = (const float*)d_in[5];
    const float* W_h_node  = (const float*)d_in[6];
    const float* W_h_edge  = (const float*)d_in[7];
    const float* W_att1    = (const float*)d_in[8];
    const float* W_att2    = (const float*)d_in[9];
    const float* comm_W    = (const float*)d_in[10];
    const float* W_o       = (const float*)d_in[11];
    const float* b_o       = (const float*)d_in[12];
    const float* gru_bias  = (const float*)d_in[13];
    const float* gru_Wih   = (const float*)d_in[14];
    const float* gru_Whh   = (const float*)d_in[15];
    const float* gru_bih   = (const float*)d_in[16];
    const float* gru_bhh   = (const float*)d_in[17];
    const float* lin1_W    = (const float*)d_in[18];
    const float* lin1_b    = (const float*)d_in[19];
    const float* lin2_W    = (const float*)d_in[20];
    const float* lin2_b    = (const float*)d_in[21];
    const void*  src       = d_in[22];
    const void*  dst       = d_in[23];
    const void*  etype     = d_in[24];
    const void*  elabel    = d_in[25];
    const void*  trg       = d_in[26];
    float* out = (float*)d_out;

    float *ge_ie, *ge_in, *ge_P, *ge_D, *ge_U, *ge_mn, *ge_agg, *ge_V;
    float *ge_nodeh, *ge_msg, *ge_scr, *ge_gi, *ge_gif, *ge_msg2, *ge_WihT, *ge_Qrel, *ge_Qd;
    unsigned short *ge_Wh, *ge_Wl, *ge_meh, *ge_mel;
    int *ge_srcp, *ge_dstp, *ge_etp, *ge_elp;
    cudaGetSymbolAddress((void**)&ge_ie, g_ie);
    cudaGetSymbolAddress((void**)&ge_meh, g_meh);
    cudaGetSymbolAddress((void**)&ge_mel, g_mel);
    cudaGetSymbolAddress((void**)&ge_in, g_in);
    cudaGetSymbolAddress((void**)&ge_P, g_P);
    cudaGetSymbolAddress((void**)&ge_D, g_D);
    cudaGetSymbolAddress((void**)&ge_U, g_U);
    cudaGetSymbolAddress((void**)&ge_mn, g_mn);
    cudaGetSymbolAddress((void**)&ge_agg, g_agg);
    cudaGetSymbolAddress((void**)&ge_V, g_V);
    cudaGetSymbolAddress((void**)&ge_nodeh, g_nodeh);
    cudaGetSymbolAddress((void**)&ge_msg, g_msg);
    cudaGetSymbolAddress((void**)&ge_scr, g_scr);
    cudaGetSymbolAddress((void**)&ge_gi, g_gi);
    cudaGetSymbolAddress((void**)&ge_gif, g_gif);
    cudaGetSymbolAddress((void**)&ge_msg2, g_msg2);
    cudaGetSymbolAddress((void**)&ge_WihT, g_WihT);
    cudaGetSymbolAddress((void**)&ge_Qrel, g_Qrel);
    cudaGetSymbolAddress((void**)&ge_Qd, g_Qd);
    cudaGetSymbolAddress((void**)&ge_Wh, g_Whg);
    cudaGetSymbolAddress((void**)&ge_Wl, g_Wlg);
    cudaGetSymbolAddress((void**)&ge_srcp, g_srcp);
    cudaGetSymbolAddress((void**)&ge_dstp, g_dstp);
    cudaGetSymbolAddress((void**)&ge_etp, g_etp);
    cudaGetSymbolAddress((void**)&ge_elp, g_elp);

    cudaFuncSetAttribute(k_edge_att_tc, cudaFuncAttributeMaxDynamicSharedMemorySize, DYN_BYTES);

    k_detect<<<1, 32>>>(src, etype);

    // CSR of dst + edge permutation
    k_cnt_zero<<<NN/256, 256>>>();
    k_count<<<NE/256, 256>>>(dst);
    k_scan1<<<16, 1024>>>();
    k_scan2<<<1, 32>>>();
    k_scan3<<<NN/256, 256>>>();
    k_fill<<<NE/256, 256>>>(dst);
    k_perm<<<NE/256, 256>>>(src, dst, etype, elabel);

    // edge attention weights -> bf16 hi/lo
    k_wconv<<<64, 256>>>(W_att_in1 + 128*128, ge_Wh,           ge_Wl);
    k_wconv<<<64, 256>>>(W_att1,              ge_Wh + 16384,   ge_Wl + 16384);
    k_wconv<<<64, 256>>>(W_att1 + 32768,      ge_Wh + 32768,   ge_Wl + 32768);

    // node-side GEMMs: P, D, input_node in one batched launch
    k_tgemm_bf3<<<dim3(NN/128, 3), 256>>>(node_feat,
        W_i_edge, W_i_edge + 192*128, W_i_node,
        ge_P, ge_D, ge_in, /*reluMask=*/0b100);
    // small rel_emb GEMMs
    k_sgemm<<<dim3(1,2), 256>>>(rel_emb, W_i_edge + 64*128,         ge_Qrel,        RR, 128, 128);
    k_sgemm<<<dim3(1,2), 256>>>(rel_emb, W_att1 + 128*128,          ge_Qd,          RR, 128, 128);
    k_sgemm<<<dim3(1,2), 256>>>(rel_emb, W_att1 + 32768 + 128*128,  ge_Qd + RR*128, RR, 128, 128);

    // fused edge_init + input attention (mode 2)
    k_tgemm_bf<<<dim3(NN/128, 1), 256>>>(ge_in, W_att_in1, ge_U, 128, 128, NULL, 0, 0);
    k_edge_att_tc<<<NE/128, 256, DYN_BYTES>>>(NULL, NULL, ge_Wh, ge_Wl, ge_U, ge_srcp, ge_srcp,
                                              W_att_in2, ge_ie, NULL, ge_meh, ge_mel, 2,
                                              ge_P, ge_Qrel, ge_D, ge_etp, ge_dstp, ge_ie);

    // two message-passing depths
    for (int d = 0; d < 2; d++) {
        const float* mn_old = (d == 0) ? ge_in : ge_mn;
        k_gather<<<NN, 128>>>(ge_meh, ge_mel, mn_old, ge_scr);
        k_tgemm_bf<<<dim3(NN/128, 1), 256>>>(ge_scr, W_h_node + d*16384, ge_mn, 128, 128, NULL, 1, 0);
        k_tgemm_bf<<<dim3(NN/128, 1), 256>>>(ge_mn, W_h_edge + d*16384, ge_V, 128, 128, NULL, 0, 0);
        k_edge_att_tc<<<NE/128, 256, DYN_BYTES>>>(ge_meh, ge_mel,
                                                  ge_Wh + (d+1)*16384, ge_Wl + (d+1)*16384,
                                                  ge_Qd + d*RR*128, ge_elp,
                                                  ge_srcp, W_att2 + d*128, ge_ie, ge_V,
                                                  ge_meh, ge_mel, 1,
                                                  NULL, NULL, NULL, NULL, NULL, NULL);
    }

    // readout aggregation + single concat GEMM
    k_gather<<<NN, 128>>>(ge_meh, ge_mel, NULL, ge_agg);
    k_tgemm_cat3<<<dim3(NN/128, 1), 256>>>(ge_agg, ge_mn, ge_in, comm_W, ge_nodeh);

    // GRU
    k_msg<<<NN*128/256, 256>>>(gru_bias);
    k_h0<<<BB, 128>>>();
    k_twih<<<(2*384*128 + 255)/256, 256>>>(gru_Wih);
    k_tgemm_bf<<<dim3(1, 3), 256>>>(ge_msg2, ge_WihT,           ge_gif, 128, 384, gru_bih,       0, 0);
    k_tgemm_bf<<<dim3(NN/128, 3), 256>>>(ge_msg, ge_WihT + 384*128, ge_gi, 128, 384, gru_bih + 384, 0, 0);
    k_gru<<<dim3(BB, 2), 384>>>(gru_Whh, gru_bhh);

    k_final<<<BB, 128>>>(W_o, b_o, rel_emb, trg, lin1_W, lin1_b, lin2_W, lin2_b, out);
}

// round 15
// speedup vs baseline: 1.4419x; 1.0374x over previous
#include <cuda_runtime.h>
#include <cuda_bf16.h>
#include <math.h>

#define NN 16384
#define NE 262144
#define HH 128
#define BB 64
#define SS 256
#define RR 32

__device__ float g_ie[NE*HH];
__device__ unsigned short g_meh[NE*HH];
__device__ unsigned short g_mel[NE*HH];
__device__ float g_in[NN*HH];
__device__ float g_P[NN*HH];
__device__ float g_D[NN*HH];
__device__ float g_U[NN*HH];
__device__ float g_mn[NN*HH];
__device__ float g_agg[NN*HH];
__device__ float g_V[NN*HH];
__device__ float g_nodeh[NN*HH];
__device__ float g_msg[NN*HH];
__device__ float g_scr[NN*HH];
__device__ float g_gi[NN*384];
__device__ float g_gif[128*384];
__device__ float g_msg2[128*HH];
__device__ float g_WihT[2*384*128];
__device__ float g_Qrel[RR*HH];
__device__ float g_Qd[2*RR*HH];
__device__ float g_h0[BB*HH];
__device__ float g_y[4*BB*HH];
__device__ int   g_is64[2];
__device__ int   g_cnt[NN];
__device__ int   g_off[NN+1];
__device__ int   g_cur[NN];
__device__ int   g_eid[NE];
__device__ int   g_bsum[16], g_bpre[16];
__device__ int   g_srcp[NE], g_dstp[NE], g_etp[NE], g_elp[NE];
__device__ unsigned short g_Whg[3*16384];
__device__ unsigned short g_Wlg[3*16384];

__device__ __forceinline__ int ld_idx(const void* p, long long i, int sel) {
    if (g_is64[sel]) return (int)((const long long*)p)[i];
    return ((const int*)p)[i];
}

__global__ void k_detect(const void* src, const void* et) {
    if (threadIdx.x == 0) {
        const unsigned long long* a = (const unsigned long long*)src;
        int v = 1;
        for (int i = 0; i < 8; i++) if (a[i] >= (unsigned long long)NN) v = 0;
        g_is64[0] = v;
        const unsigned long long* b = (const unsigned long long*)et;
        v = 1;
        for (int i = 0; i < 8; i++) if (b[i] >= (unsigned long long)RR) v = 0;
        g_is64[1] = v;
    }
}

__device__ __forceinline__ void f2bf(float x, unsigned short& h, unsigned short& l) {
    __nv_bfloat16 bh = __float2bfloat16(x);
    h = __bfloat16_as_ushort(bh);
    l = __bfloat16_as_ushort(__float2bfloat16(x - __bfloat162float(bh)));
}

__device__ __forceinline__ float bf2f(unsigned short u) {
    return __bfloat162float(__ushort_as_bfloat16(u));
}

__device__ __forceinline__ void mma16(float* d, const unsigned* a, const unsigned* b) {
    asm volatile("mma.sync.aligned.m16n8k16.row.col.f32.bf16.bf16.f32 "
        "{%0,%1,%2,%3}, {%4,%5,%6,%7}, {%8,%9}, {%0,%1,%2,%3};"
        : "+f"(d[0]), "+f"(d[1]), "+f"(d[2]), "+f"(d[3])
        : "r"(a[0]), "r"(a[1]), "r"(a[2]), "r"(a[3]), "r"(b[0]), "r"(b[1]));
}

__device__ __forceinline__ void cp16(const void* smem_dst, const void* gsrc) {
    unsigned d = (unsigned)__cvta_generic_to_shared(smem_dst);
    asm volatile("cp.async.cg.shared.global [%0], [%1], 16;" :: "r"(d), "l"(gsrc));
}

// merged weight pre-conversion: 3 matrices in one launch (grid 192)
__global__ void k_wconv3(const float* __restrict__ W0, const float* __restrict__ W1,
                         const float* __restrict__ W2,
                         unsigned short* __restrict__ Wh, unsigned short* __restrict__ Wl)
{
    int sel = blockIdx.x >> 6;
    const float* Wm = (sel == 0) ? W0 : ((sel == 1) ? W1 : W2);
    int t = (blockIdx.x & 63)*256 + threadIdx.x;   // 16384 per matrix
    int k = t >> 7, c = t & 127;
    unsigned short h, l;
    f2bf(Wm[k*128 + c], h, l);
    Wh[sel*16384 + c*128 + k] = h;
    Wl[sel*16384 + c*128 + k] = l;
}

#define APITCH 40
#define WPITCH 42
#define PIT 40
#define EA_AH 0
#define EA_AL 20480
#define EA_WH 40960
#define EA_WL 61440
#define DYN_BYTES 81920

// ---------- bf16 3-split tensor-core GEMM ----------
__global__ void __launch_bounds__(256, 2) k_tgemm_bf(
    const float* __restrict__ A, const float* __restrict__ W, float* __restrict__ C,
    int K, int M, const float* __restrict__ bias, int doRelu, int accum)
{
    __shared__ unsigned short sAh[128*APITCH], sAl[128*APITCH];
    __shared__ unsigned short sWh[128*WPITCH], sWl[128*WPITCH];
    const int tid = threadIdx.x;
    const int w = tid >> 5, lane = tid & 31;
    const int g = lane >> 2, t = lane & 3;
    const int wr0 = (w >> 1) * 32, wc0 = (w & 1) * 64;
    const long long row0 = (long long)blockIdx.x * 128;
    const int col0 = blockIdx.y * 128;

    float acc[2][8][4];
#pragma unroll
    for (int a = 0; a < 2; a++)
#pragma unroll
        for (int b = 0; b < 8; b++)
#pragma unroll
            for (int c = 0; c < 4; c++) acc[a][b][c] = 0.f;

    for (int k0 = 0; k0 < K; k0 += 32) {
        __syncthreads();
#pragma unroll
        for (int i = 0; i < 4; i++) {
            int f = tid + 256 * i;
            int r = f >> 3, j = (f & 7) << 2;
            float4 v = *(const float4*)(A + (row0 + r) * K + k0 + j);
            unsigned short h, l;
            f2bf(v.x, h, l); sAh[r*APITCH+j+0] = h; sAl[r*APITCH+j+0] = l;
            f2bf(v.y, h, l); sAh[r*APITCH+j+1] = h; sAl[r*APITCH+j+1] = l;
            f2bf(v.z, h, l); sAh[r*APITCH+j+2] = h; sAl[r*APITCH+j+2] = l;
            f2bf(v.w, h, l); sAh[r*APITCH+j+3] = h; sAl[r*APITCH+j+3] = l;
        }
#pragma unroll
        for (int i = 0; i < 4; i++) {
            int f = tid + 256 * i;
            int kk = f >> 5, c = (f & 31) << 2;
            float4 v = *(const float4*)(W + (long long)(k0 + kk) * M + col0 + c);
            unsigned short h, l;
            f2bf(v.x, h, l); sWh[(c+0)*WPITCH+kk] = h; sWl[(c+0)*WPITCH+kk] = l;
            f2bf(v.y, h, l); sWh[(c+1)*WPITCH+kk] = h; sWl[(c+1)*WPITCH+kk] = l;
            f2bf(v.z, h, l); sWh[(c+2)*WPITCH+kk] = h; sWl[(c+2)*WPITCH+kk] = l;
            f2bf(v.w, h, l); sWh[(c+3)*WPITCH+kk] = h; sWl[(c+3)*WPITCH+kk] = l;
        }
        __syncthreads();
#pragma unroll
        for (int ks = 0; ks < 32; ks += 16) {
            unsigned ah[2][4], al[2][4];
#pragma unroll
            for (int mt = 0; mt < 2; mt++) {
                int rb = wr0 + mt * 16 + g;
                const unsigned short* p = &sAh[rb*APITCH + ks + 2*t];
                ah[mt][0] = *(const unsigned*)p;
                ah[mt][1] = *(const unsigned*)(p + 8*APITCH);
                ah[mt][2] = *(const unsigned*)(p + 8);
                ah[mt][3] = *(const unsigned*)(p + 8*APITCH + 8);
                const unsigned short* q = &sAl[rb*APITCH + ks + 2*t];
                al[mt][0] = *(const unsigned*)q;
                al[mt][1] = *(const unsigned*)(q + 8*APITCH);
                al[mt][2] = *(const unsigned*)(q + 8);
                al[mt][3] = *(const unsigned*)(q + 8*APITCH + 8);
            }
#pragma unroll
            for (int nt = 0; nt < 8; nt++) {
                int cn = wc0 + nt * 8 + g;
                unsigned bh[2], bl[2];
                const unsigned short* p = &sWh[cn*WPITCH + ks + 2*t];
                bh[0] = *(const unsigned*)p; bh[1] = *(const unsigned*)(p + 8);
                const unsigned short* q = &sWl[cn*WPITCH + ks + 2*t];
                bl[0] = *(const unsigned*)q; bl[1] = *(const unsigned*)(q + 8);
#pragma unroll
                for (int mt = 0; mt < 2; mt++) {
                    mma16(acc[mt][nt], ah[mt], bh);
                    mma16(acc[mt][nt], ah[mt], bl);
                    mma16(acc[mt][nt], al[mt], bh);
                }
            }
        }
    }
#pragma unroll
    for (int mt = 0; mt < 2; mt++) {
#pragma unroll
        for (int nt = 0; nt < 8; nt++) {
            int c = col0 + wc0 + nt * 8 + t * 2;
            long long r0 = row0 + wr0 + mt * 16 + g;
            float b0 = bias ? bias[c] : 0.f, b1 = bias ? bias[c+1] : 0.f;
            float v0 = acc[mt][nt][0] + b0, v1 = acc[mt][nt][1] + b1;
            float v2 = acc[mt][nt][2] + b0, v3 = acc[mt][nt][3] + b1;
            if (accum) {
                float2 o0 = *(const float2*)(C + r0 * M + c);
                float2 o1 = *(const float2*)(C + (r0 + 8) * M + c);
                v0 += o0.x; v1 += o0.y; v2 += o1.x; v3 += o1.y;
            }
            if (doRelu) {
                v0 = fmaxf(v0, 0.f); v1 = fmaxf(v1, 0.f);
                v2 = fmaxf(v2, 0.f); v3 = fmaxf(v3, 0.f);
            }
            *(float2*)(C + r0 * M + c)       = make_float2(v0, v1);
            *(float2*)(C + (r0 + 8) * M + c) = make_float2(v2, v3);
        }
    }
}

// ---------- batched: blockIdx.y selects one of 3 (W,C); A shared; K=64 ----------
__global__ void __launch_bounds__(256, 2) k_tgemm_bf3(
    const float* __restrict__ A,
    const float* __restrict__ W0, const float* __restrict__ W1, const float* __restrict__ W2,
    float* __restrict__ C0, float* __restrict__ C1, float* __restrict__ C2, int reluMask)
{
    const float* W = (blockIdx.y == 0) ? W0 : ((blockIdx.y == 1) ? W1 : W2);
    float* C = (blockIdx.y == 0) ? C0 : ((blockIdx.y == 1) ? C1 : C2);
    const int doRelu = (reluMask >> blockIdx.y) & 1;
    __shared__ unsigned short sAh[128*APITCH], sAl[128*APITCH];
    __shared__ unsigned short sWh[128*WPITCH], sWl[128*WPITCH];
    const int tid = threadIdx.x;
    const int w = tid >> 5, lane = tid & 31;
    const int g = lane >> 2, t = lane & 3;
    const int wr0 = (w >> 1) * 32, wc0 = (w & 1) * 64;
    const long long row0 = (long long)blockIdx.x * 128;

    float acc[2][8][4];
#pragma unroll
    for (int a = 0; a < 2; a++)
#pragma unroll
        for (int b = 0; b < 8; b++)
#pragma unroll
            for (int c = 0; c < 4; c++) acc[a][b][c] = 0.f;

    for (int k0 = 0; k0 < 64; k0 += 32) {
        __syncthreads();
#pragma unroll
        for (int i = 0; i < 4; i++) {
            int f = tid + 256 * i;
            int r = f >> 3, j = (f & 7) << 2;
            float4 v = *(const float4*)(A + (row0 + r) * 64 + k0 + j);
            unsigned short h, l;
            f2bf(v.x, h, l); sAh[r*APITCH+j+0] = h; sAl[r*APITCH+j+0] = l;
            f2bf(v.y, h, l); sAh[r*APITCH+j+1] = h; sAl[r*APITCH+j+1] = l;
            f2bf(v.z, h, l); sAh[r*APITCH+j+2] = h; sAl[r*APITCH+j+2] = l;
            f2bf(v.w, h, l); sAh[r*APITCH+j+3] = h; sAl[r*APITCH+j+3] = l;
        }
#pragma unroll
        for (int i = 0; i < 4; i++) {
            int f = tid + 256 * i;
            int kk = f >> 5, c = (f & 31) << 2;
            float4 v = *(const float4*)(W + (long long)(k0 + kk) * 128 + c);
            unsigned short h, l;
            f2bf(v.x, h, l); sWh[(c+0)*WPITCH+kk] = h; sWl[(c+0)*WPITCH+kk] = l;
            f2bf(v.y, h, l); sWh[(c+1)*WPITCH+kk] = h; sWl[(c+1)*WPITCH+kk] = l;
            f2bf(v.z, h, l); sWh[(c+2)*WPITCH+kk] = h; sWl[(c+2)*WPITCH+kk] = l;
            f2bf(v.w, h, l); sWh[(c+3)*WPITCH+kk] = h; sWl[(c+3)*WPITCH+kk] = l;
        }
        __syncthreads();
#pragma unroll
        for (int ks = 0; ks < 32; ks += 16) {
            unsigned ah[2][4], al[2][4];
#pragma unroll
            for (int mt = 0; mt < 2; mt++) {
                int rb = wr0 + mt * 16 + g;
                const unsigned short* p = &sAh[rb*APITCH + ks + 2*t];
                ah[mt][0] = *(const unsigned*)p;
                ah[mt][1] = *(const unsigned*)(p + 8*APITCH);
                ah[mt][2] = *(const unsigned*)(p + 8);
                ah[mt][3] = *(const unsigned*)(p + 8*APITCH + 8);
                const unsigned short* q = &sAl[rb*APITCH + ks + 2*t];
                al[mt][0] = *(const unsigned*)q;
                al[mt][1] = *(const unsigned*)(q + 8*APITCH);
                al[mt][2] = *(const unsigned*)(q + 8);
                al[mt][3] = *(const unsigned*)(q + 8*APITCH + 8);
            }
#pragma unroll
            for (int nt = 0; nt < 8; nt++) {
                int cn = wc0 + nt * 8 + g;
                unsigned bh[2], bl[2];
                const unsigned short* p = &sWh[cn*WPITCH + ks + 2*t];
                bh[0] = *(const unsigned*)p; bh[1] = *(const unsigned*)(p + 8);
                const unsigned short* q = &sWl[cn*WPITCH + ks + 2*t];
                bl[0] = *(const unsigned*)q; bl[1] = *(const unsigned*)(q + 8);
#pragma unroll
                for (int mt = 0; mt < 2; mt++) {
                    mma16(acc[mt][nt], ah[mt], bh);
                    mma16(acc[mt][nt], ah[mt], bl);
                    mma16(acc[mt][nt], al[mt], bh);
                }
            }
        }
    }
#pragma unroll
    for (int mt = 0; mt < 2; mt++) {
#pragma unroll
        for (int nt = 0; nt < 8; nt++) {
            int c = wc0 + nt * 8 + t * 2;
            long long r0 = row0 + wr0 + mt * 16 + g;
            float v0 = acc[mt][nt][0], v1 = acc[mt][nt][1];
            float v2 = acc[mt][nt][2], v3 = acc[mt][nt][3];
            if (doRelu) {
                v0 = fmaxf(v0, 0.f); v1 = fmaxf(v1, 0.f);
                v2 = fmaxf(v2, 0.f); v3 = fmaxf(v3, 0.f);
            }
            *(float2*)(C + r0 * 128 + c)       = make_float2(v0, v1);
            *(float2*)(C + (r0 + 8) * 128 + c) = make_float2(v2, v3);
        }
    }
}

// ---------- concat GEMM: C = [A0|A1|A2] @ W(384x128) ----------
__global__ void __launch_bounds__(256, 2) k_tgemm_cat3(
    const float* __restrict__ A0, const float* __restrict__ A1, const float* __restrict__ A2,
    const float* __restrict__ W, float* __restrict__ C)
{
    __shared__ unsigned short sAh[128*APITCH], sAl[128*APITCH];
    __shared__ unsigned short sWh[128*WPITCH], sWl[128*WPITCH];
    const int tid = threadIdx.x;
    const int w = tid >> 5, lane = tid & 31;
    const int g = lane >> 2, t = lane & 3;
    const int wr0 = (w >> 1) * 32, wc0 = (w & 1) * 64;
    const long long row0 = (long long)blockIdx.x * 128;

    float acc[2][8][4];
#pragma unroll
    for (int a = 0; a < 2; a++)
#pragma unroll
        for (int b = 0; b < 8; b++)
#pragma unroll
            for (int c = 0; c < 4; c++) acc[a][b][c] = 0.f;

    for (int ch = 0; ch < 12; ch++) {
        const int k0 = ch * 32;
        const float* A = (ch < 4) ? A0 : ((ch < 8) ? A1 : A2);
        const int kloc = (ch & 3) * 32;
        __syncthreads();
#pragma unroll
        for (int i = 0; i < 4; i++) {
            int f = tid + 256 * i;
            int r = f >> 3, j = (f & 7) << 2;
            float4 v = *(const float4*)(A + (row0 + r) * 128 + kloc + j);
            unsigned short h, l;
            f2bf(v.x, h, l); sAh[r*APITCH+j+0] = h; sAl[r*APITCH+j+0] = l;
            f2bf(v.y, h, l); sAh[r*APITCH+j+1] = h; sAl[r*APITCH+j+1] = l;
            f2bf(v.z, h, l); sAh[r*APITCH+j+2] = h; sAl[r*APITCH+j+2] = l;
            f2bf(v.w, h, l); sAh[r*APITCH+j+3] = h; sAl[r*APITCH+j+3] = l;
        }
#pragma unroll
        for (int i = 0; i < 4; i++) {
            int f = tid + 256 * i;
            int kk = f >> 5, c = (f & 31) << 2;
            float4 v = *(const float4*)(W + (long long)(k0 + kk) * 128 + c);
            unsigned short h, l;
            f2bf(v.x, h, l); sWh[(c+0)*WPITCH+kk] = h; sWl[(c+0)*WPITCH+kk] = l;
            f2bf(v.y, h, l); sWh[(c+1)*WPITCH+kk] = h; sWl[(c+1)*WPITCH+kk] = l;
            f2bf(v.z, h, l); sWh[(c+2)*WPITCH+kk] = h; sWl[(c+2)*WPITCH+kk] = l;
            f2bf(v.w, h, l); sWh[(c+3)*WPITCH+kk] = h; sWl[(c+3)*WPITCH+kk] = l;
        }
        __syncthreads();
#pragma unroll
        for (int ks = 0; ks < 32; ks += 16) {
            unsigned ah[2][4], al[2][4];
#pragma unroll
            for (int mt = 0; mt < 2; mt++) {
                int rb = wr0 + mt * 16 + g;
                const unsigned short* p = &sAh[rb*APITCH + ks + 2*t];
                ah[mt][0] = *(const unsigned*)p;
                ah[mt][1] = *(const unsigned*)(p + 8*APITCH);
                ah[mt][2] = *(const unsigned*)(p + 8);
                ah[mt][3] = *(const unsigned*)(p + 8*APITCH + 8);
                const unsigned short* q = &sAl[rb*APITCH + ks + 2*t];
                al[mt][0] = *(const unsigned*)q;
                al[mt][1] = *(const unsigned*)(q + 8*APITCH);
                al[mt][2] = *(const unsigned*)(q + 8);
                al[mt][3] = *(const unsigned*)(q + 8*APITCH + 8);
            }
#pragma unroll
            for (int nt = 0; nt < 8; nt++) {
                int cn = wc0 + nt * 8 + g;
                unsigned bh[2], bl[2];
                const unsigned short* p = &sWh[cn*WPITCH + ks + 2*t];
                bh[0] = *(const unsigned*)p; bh[1] = *(const unsigned*)(p + 8);
                const unsigned short* q = &sWl[cn*WPITCH + ks + 2*t];
                bl[0] = *(const unsigned*)q; bl[1] = *(const unsigned*)(q + 8);
#pragma unroll
                for (int mt = 0; mt < 2; mt++) {
                    mma16(acc[mt][nt], ah[mt], bh);
                    mma16(acc[mt][nt], ah[mt], bl);
                    mma16(acc[mt][nt], al[mt], bh);
                }
            }
        }
    }
#pragma unroll
    for (int mt = 0; mt < 2; mt++) {
#pragma unroll
        for (int nt = 0; nt < 8; nt++) {
            int c = wc0 + nt * 8 + t * 2;
            long long r0 = row0 + wr0 + mt * 16 + g;
            *(float2*)(C + r0 * 128 + c)       = make_float2(acc[mt][nt][0], acc[mt][nt][1]);
            *(float2*)(C + (r0 + 8) * 128 + c) = make_float2(acc[mt][nt][2], acc[mt][nt][3]);
        }
    }
}

// ---------- batched small SIMT GEMM: 3 (W,C) pairs, rows=32, K=128, M=128 ----------
__global__ void k_sgemm3(const float* __restrict__ A,
                         const float* __restrict__ W0, const float* __restrict__ W1,
                         const float* __restrict__ W2,
                         float* __restrict__ C0, float* __restrict__ C1, float* __restrict__ C2)
{
    const int sel = blockIdx.y >> 1;
    const float* W = (sel == 0) ? W0 : ((sel == 1) ? W1 : W2);
    float* C = (sel == 0) ? C0 : ((sel == 1) ? C1 : C2);
    __shared__ float As[16][64];
    __shared__ float Ws[16][64];
    const int tid = threadIdx.x;
    const int tx = tid & 15, ty = tid >> 4;
    const int col0 = (blockIdx.y & 1) * 64;
    const int la_r = tid >> 2, la_k = (tid & 3) << 2;
    const int lw_k = tid >> 4, lw_c = (tid & 15) << 2;
    float acc[4][4];
#pragma unroll
    for (int i = 0; i < 4; i++)
#pragma unroll
        for (int j = 0; j < 4; j++) acc[i][j] = 0.f;
    for (int k0 = 0; k0 < 128; k0 += 16) {
        float4 av = make_float4(0.f,0.f,0.f,0.f);
        if (la_r < RR)
            av = *(const float4*)(A + (size_t)la_r * 128 + (k0 + la_k));
        As[la_k+0][la_r] = av.x; As[la_k+1][la_r] = av.y;
        As[la_k+2][la_r] = av.z; As[la_k+3][la_r] = av.w;
        *(float4*)&Ws[lw_k][lw_c] = *(const float4*)(W + (size_t)(k0+lw_k)*128 + col0 + lw_c);
        __syncthreads();
#pragma unroll
        for (int k = 0; k < 16; k++) {
            float4 a4 = *(const float4*)&As[k][ty<<2];
            float4 w4 = *(const float4*)&Ws[k][tx<<2];
            float ar[4] = {a4.x,a4.y,a4.z,a4.w};
            float wr[4] = {w4.x,w4.y,w4.z,w4.w};
#pragma unroll
            for (int i = 0; i < 4; i++)
#pragma unroll
                for (int j = 0; j < 4; j++) acc[i][j] += ar[i]*wr[j];
        }
        __syncthreads();
    }
#pragma unroll
    for (int i = 0; i < 4; i++) {
        int r = (ty<<2) + i;
        if (r < RR)
#pragma unroll
            for (int j = 0; j < 4; j++)
                C[(size_t)r*128 + col0 + (tx<<2) + j] = acc[i][j];
    }
}

// ---------- bf16 edge attention ----------
__global__ void __launch_bounds__(256, 2) k_edge_att_tc(
    const unsigned short* __restrict__ Xh, const unsigned short* __restrict__ Xl,
    const unsigned short* __restrict__ Wh, const unsigned short* __restrict__ Wl,
    const float* __restrict__ addvec, const int* __restrict__ idx_add,
    const int* __restrict__ idx_src, const float* __restrict__ w2,
    const float* __restrict__ ie, const float* __restrict__ V,
    unsigned short* __restrict__ outh, unsigned short* __restrict__ outl, int mode,
    const float* __restrict__ Pm, const float* __restrict__ Qm,
    const float* __restrict__ Dm, const int* __restrict__ idx_et,
    const int* __restrict__ idx_dst, float* __restrict__ ie_out)
{
    extern __shared__ char dynsm[];
    unsigned short* pAh = (unsigned short*)(dynsm + EA_AH);
    unsigned short* pAl = (unsigned short*)(dynsm + EA_AL);
    unsigned short* pWh = (unsigned short*)(dynsm + EA_WH);
    unsigned short* pWl = (unsigned short*)(dynsm + EA_WL);
    __shared__ int ia_s[128], is_s[128], iet_s[128], idd_s[128];
    __shared__ float a_s[128], part_s[256], w2_s[128];

    const int tid = threadIdx.x;
    const int w = tid >> 5, lane = tid & 31;
    const int g = lane >> 2, t = lane & 3;
    const int wr0 = (w >> 1) * 32, wc0 = (w & 1) * 64;
    const long long e0 = (long long)blockIdx.x * 128;

    if (tid < 128) {
        ia_s[tid] = idx_add[e0 + tid];
        is_s[tid] = idx_src[e0 + tid];
        w2_s[tid] = w2[tid];
        if (mode == 2) {
            iet_s[tid] = idx_et[e0 + tid];
            idd_s[tid] = idx_dst[e0 + tid];
        }
    }

    auto issue = [&](int chunk) {
        int b = chunk & 1;
        int k0 = chunk * 32;
        if (mode != 2) {
            unsigned short* dAh = pAh + b * 5120;
            unsigned short* dAl = pAl + b * 5120;
#pragma unroll
            for (int it = 0; it < 2; it++) {
                int f = tid + 256 * it;
                int r = f >> 2, seg = f & 3;
                cp16(dAh + r*PIT + seg*8, Xh + (e0 + r)*HH + k0 + seg*8);
                cp16(dAl + r*PIT + seg*8, Xl + (e0 + r)*HH + k0 + seg*8);
            }
        }
        unsigned short* dWh = pWh + b * 5120;
        unsigned short* dWl = pWl + b * 5120;
#pragma unroll
        for (int it = 0; it < 2; it++) {
            int f = tid + 256 * it;
            int c = f >> 2, seg = f & 3;
            cp16(dWh + c*PIT + seg*8, Wh + c*128 + k0 + seg*8);
            cp16(dWl + c*PIT + seg*8, Wl + c*128 + k0 + seg*8);
        }
        asm volatile("cp.async.commit_group;");
    };

    float acc[2][8][4];
#pragma unroll
    for (int a = 0; a < 2; a++)
#pragma unroll
        for (int b = 0; b < 8; b++)
#pragma unroll
            for (int c = 0; c < 4; c++) acc[a][b][c] = 0.f;

    issue(0);
    for (int ch = 0; ch < 4; ch++) {
        __syncthreads();
        if (ch < 3) {
            issue(ch + 1);
            asm volatile("cp.async.wait_group 1;");
        } else {
            asm volatile("cp.async.wait_group 0;");
        }
        __syncthreads();
        const int b = ch & 1;
        const int k0 = ch * 32;
        if (mode == 2) {
            unsigned short* dAh = pAh + b * 5120;
            unsigned short* dAl = pAl + b * 5120;
#pragma unroll
            for (int i = 0; i < 4; i++) {
                int f = tid + 256 * i;
                int r = f >> 3, j = (f & 7) << 2;
                int s = is_s[r], et = iet_s[r], dd = idd_s[r];
                float4 p = *(const float4*)(Pm + (size_t)s*HH + k0 + j);
                float4 q = *(const float4*)(Qm + (size_t)et*HH + k0 + j);
                float4 dv = *(const float4*)(Dm + (size_t)dd*HH + k0 + j);
                float4 v;
                v.x = fmaxf(p.x+q.x+dv.x, 0.f); v.y = fmaxf(p.y+q.y+dv.y, 0.f);
                v.z = fmaxf(p.z+q.z+dv.z, 0.f); v.w = fmaxf(p.w+q.w+dv.w, 0.f);
                *(float4*)(ie_out + (e0 + r)*HH + k0 + j) = v;
                unsigned short h, l;
                f2bf(v.x, h, l); dAh[r*PIT+j+0] = h; dAl[r*PIT+j+0] = l;
                f2bf(v.y, h, l); dAh[r*PIT+j+1] = h; dAl[r*PIT+j+1] = l;
                f2bf(v.z, h, l); dAh[r*PIT+j+2] = h; dAl[r*PIT+j+2] = l;
                f2bf(v.w, h, l); dAh[r*PIT+j+3] = h; dAl[r*PIT+j+3] = l;
            }
            __syncthreads();
        }
        const unsigned short* cAh = pAh + b * 5120;
        const unsigned short* cAl = pAl + b * 5120;
        const unsigned short* cWh = pWh + b * 5120;
        const unsigned short* cWl = pWl + b * 5120;
#pragma unroll
        for (int ks = 0; ks < 32; ks += 16) {
            unsigned ah[2][4], al[2][4];
#pragma unroll
            for (int mt = 0; mt < 2; mt++) {
                int rb = wr0 + mt * 16 + g;
                const unsigned short* p = &cAh[rb*PIT + ks + 2*t];
                ah[mt][0] = *(const unsigned*)p;
                ah[mt][1] = *(const unsigned*)(p + 8*PIT);
                ah[mt][2] = *(const unsigned*)(p + 8);
                ah[mt][3] = *(const unsigned*)(p + 8*PIT + 8);
                const unsigned short* q = &cAl[rb*PIT + ks + 2*t];
                al[mt][0] = *(const unsigned*)q;
                al[mt][1] = *(const unsigned*)(q + 8*PIT);
                al[mt][2] = *(const unsigned*)(q + 8);
                al[mt][3] = *(const unsigned*)(q + 8*PIT + 8);
            }
#pragma unroll
            for (int nt = 0; nt < 8; nt++) {
                int cn = wc0 + nt * 8 + g;
                unsigned bh[2], bl[2];
                const unsigned short* p = &cWh[cn*PIT + ks + 2*t];
                bh[0] = *(const unsigned*)p; bh[1] = *(const unsigned*)(p + 8);
                const unsigned short* q = &cWl[cn*PIT + ks + 2*t];
                bl[0] = *(const unsigned*)q; bl[1] = *(const unsigned*)(q + 8);
#pragma unroll
                for (int mt = 0; mt < 2; mt++) {
                    mma16(acc[mt][nt], ah[mt], bh);
                    mma16(acc[mt][nt], ah[mt], bl);
                    mma16(acc[mt][nt], al[mt], bh);
                }
            }
        }
    }

    // attention scalar
#pragma unroll
    for (int mt = 0; mt < 2; mt++) {
        int r0 = wr0 + mt * 16 + g, r1 = r0 + 8;
        const float2* ar0 = (const float2*)(addvec + (size_t)ia_s[r0] * HH);
        const float2* ar1 = (const float2*)(addvec + (size_t)ia_s[r1] * HH);
        float p0 = 0.f, p1 = 0.f;
#pragma unroll
        for (int nt = 0; nt < 8; nt++) {
            int c = wc0 + nt * 8 + t * 2;
            float w0 = w2_s[c], w1 = w2_s[c+1];
            float2 a0 = ar0[c >> 1], a1 = ar1[c >> 1];
            p0 += fmaxf(acc[mt][nt][0] + a0.x, 0.f) * w0
                + fmaxf(acc[mt][nt][1] + a0.y, 0.f) * w1;
            p1 += fmaxf(acc[mt][nt][2] + a1.x, 0.f) * w0
                + fmaxf(acc[mt][nt][3] + a1.y, 0.f) * w1;
        }
        p0 += __shfl_xor_sync(0xffffffffu, p0, 1);
        p0 += __shfl_xor_sync(0xffffffffu, p0, 2);
        p1 += __shfl_xor_sync(0xffffffffu, p1, 1);
        p1 += __shfl_xor_sync(0xffffffffu, p1, 2);
        if (t == 0) {
            part_s[r0 * 2 + (w & 1)] = p0;
            part_s[r1 * 2 + (w & 1)] = p1;
        }
    }
    __syncthreads();
    if (tid < 128) {
        float ps = part_s[tid * 2] + part_s[tid * 2 + 1];
        a_s[tid] = 1.f / (1.f + expf(-ps));
    }
    __syncthreads();

    // output epilogue
#pragma unroll
    for (int i = 0; i < 16; i++) {
        int f = tid + 256 * i;
        int r = f >> 5, q = (f & 31) << 2;
        size_t base = (size_t)(e0 + r) * HH + q;
        float4 iv = *(const float4*)(ie + base);
        float a = a_s[r];
        float4 o;
        if (mode == 1) {
            float4 v4 = *(const float4*)(V + (size_t)is_s[r] * HH + q);
            o.x = fmaxf(iv.x + a*v4.x, 0.f); o.y = fmaxf(iv.y + a*v4.y, 0.f);
            o.z = fmaxf(iv.z + a*v4.z, 0.f); o.w = fmaxf(iv.w + a*v4.w, 0.f);
        } else {
            o = make_float4(iv.x*a, iv.y*a, iv.z*a, iv.w*a);
        }
        ushort4 oh, ol;
        f2bf(o.x, oh.x, ol.x); f2bf(o.y, oh.y, ol.y);
        f2bf(o.z, oh.z, ol.z); f2bf(o.w, oh.w, ol.w);
        *(ushort4*)(outh + base) = oh;
        *(ushort4*)(outl + base) = ol;
    }
}

// ---------- CSR build ----------
__global__ void k_cnt_zero() {
    int t = blockIdx.x*256 + threadIdx.x;
    if (t < NN) g_cnt[t] = 0;
}
__global__ void k_count(const void* dstp) {
    int e = blockIdx.x*256 + threadIdx.x;
    if (e < NE) atomicAdd(&g_cnt[ld_idx(dstp, e, 0)], 1);
}
__global__ void __launch_bounds__(1024) k_scan1() {
    __shared__ int wsum[32];
    int b = blockIdx.x, t = threadIdx.x;
    int lane = t & 31, wid = t >> 5;
    int v = g_cnt[b*1024 + t];
    int orig = v;
#pragma unroll
    for (int off = 1; off < 32; off <<= 1) {
        int u = __shfl_up_sync(0xffffffffu, v, off);
        if (lane >= off) v += u;
    }
    if (lane == 31) wsum[wid] = v;
    __syncthreads();
    if (wid == 0) {
        int y = wsum[lane];
#pragma unroll
        for (int off = 1; off < 32; off <<= 1) {
            int u = __shfl_up_sync(0xffffffffu, y, off);
            if (lane >= off) y += u;
        }
        wsum[lane] = y;
    }
    __syncthreads();
    int incl = v + (wid ? wsum[wid-1] : 0);
    g_off[b*1024 + t] = incl - orig;
    if (t == 1023) g_bsum[b] = incl;
}
__global__ void k_scan2() {
    int t = threadIdx.x;
    int v = (t < 16) ? g_bsum[t] : 0;
    int x = v;
#pragma unroll
    for (int off = 1; off < 32; off <<= 1) {
        int u = __shfl_up_sync(0xffffffffu, x, off);
        if (t >= off) x += u;
    }
    if (t < 16) g_bpre[t] = x - v;
    if (t == 15) g_off[NN] = x;
}
__global__ void k_scan3() {
    int i = blockIdx.x*256 + threadIdx.x;
    if (i < NN) {
        int o = g_off[i] + g_bpre[i >> 10];
        g_off[i] = o;
        g_cur[i] = o;
    }
}
__global__ void k_fill(const void* dstp) {
    int e = blockIdx.x*256 + threadIdx.x;
    if (e < NE) {
        int d = ld_idx(dstp, e, 0);
        int pos = atomicAdd(&g_cur[d], 1);
        g_eid[pos] = e;
    }
}
__global__ void k_perm(const void* src, const void* dstp, const void* etp, const void* elp) {
    int i = blockIdx.x*256 + threadIdx.x;
    if (i < NE) {
        int e = g_eid[i];
        g_srcp[i] = ld_idx(src, e, 0);
        g_dstp[i] = ld_idx(dstp, e, 0);
        g_etp[i]  = ld_idx(etp, e, 1);
        g_elp[i]  = ld_idx(elp, e, 1);
    }
}

// ---------- CSR gather aggregation ----------
__global__ void __launch_bounds__(128) k_gather(const unsigned short* __restrict__ meh,
                                                const unsigned short* __restrict__ mel,
                                                const float* __restrict__ addb,
                                                float* __restrict__ out)
{
    int n = blockIdx.x, j = threadIdx.x;
    int o0 = g_off[n], o1 = g_off[n+1];
    float s = addb ? addb[(size_t)n*HH + j] : 0.f;
    for (int i = o0; i < o1; i++)
        s += bf2f(meh[(size_t)i*HH + j]) + bf2f(mel[(size_t)i*HH + j]);
    out[(size_t)n*HH + j] = s;
}

// ---------- GRU prep ----------
__global__ void k_msg(const float* __restrict__ gru_bias) {
    int t = blockIdx.x*256 + threadIdx.x;
    float v = fmaxf(g_nodeh[t] + gru_bias[t & 127], 0.f);
    g_msg[t] = v;
    int r = t >> 7;
    int s = r & (SS - 1);
    if (s < 2) {
        int b = r / SS;
        g_msg2[((size_t)(b*2 + s))*HH + (t & 127)] = v;
    }
}
__global__ void k_h0() {
    int b = blockIdx.x, j = threadIdx.x;
    float m = -1e30f;
    for (int s = 0; s < SS; s++)
        m = fmaxf(m, g_nodeh[((size_t)(b*SS + s))*HH + j]);
    g_h0[b*HH + j] = m;
}
__global__ void k_twih(const float* __restrict__ Wih) {
    int t = blockIdx.x*256 + threadIdx.x;
    if (t < 2*384*128) {
        int d = t / (384*128), rem = t % (384*128);
        int o = rem / 128, k = rem % 128;
        g_WihT[d*384*128 + k*384 + o] = Wih[t];
    }
}

// ---------- GRU with packed f32x2 FMA ----------
__global__ void __launch_bounds__(384) k_gru(const float* __restrict__ Whh,
                                             const float* __restrict__ bhh)
{
    const int b = blockIdx.x, dir = blockIdx.y;
    const int o = threadIdx.x;
    unsigned long long wp[64];
    const float* wr = Whh + ((size_t)dir*384 + o)*128;
#pragma unroll
    for (int i = 0; i < 64; i++)
        wp[i] = *(const unsigned long long*)(wr + 2*i);
    const float bh = bhh[dir*384 + o];
    __shared__ float h_s[128];
    __shared__ float gh_s[384];
    if (o < 128) h_s[o] = g_h0[b*128 + o];
    __syncthreads();
    const int nsteps = (dir == 0) ? 2 : SS;
    for (int i2 = 0; i2 < nsteps; i2++) {
        int t = (dir == 0) ? i2 : (SS - 1 - i2);
        unsigned long long a0 = 0ull, a1 = 0ull, a2 = 0ull, a3 = 0ull;
#pragma unroll
        for (int k = 0; k < 64; k += 4) {
            unsigned long long h0 = *(const unsigned long long*)&h_s[2*k];
            unsigned long long h1 = *(const unsigned long long*)&h_s[2*k+2];
            unsigned long long h2 = *(const unsigned long long*)&h_s[2*k+4];
            unsigned long long h3 = *(const unsigned long long*)&h_s[2*k+6];
            asm("fma.rn.f32x2 %0, %1, %2, %0;" : "+l"(a0) : "l"(wp[k+0]), "l"(h0));
            asm("fma.rn.f32x2 %0, %1, %2, %0;" : "+l"(a1) : "l"(wp[k+1]), "l"(h1));
            asm("fma.rn.f32x2 %0, %1, %2, %0;" : "+l"(a2) : "l"(wp[k+2]), "l"(h2));
            asm("fma.rn.f32x2 %0, %1, %2, %0;" : "+l"(a3) : "l"(wp[k+3]), "l"(h3));
        }
        asm("add.rn.f32x2 %0, %0, %1;" : "+l"(a0) : "l"(a1));
        asm("add.rn.f32x2 %0, %0, %1;" : "+l"(a2) : "l"(a3));
        asm("add.rn.f32x2 %0, %0, %1;" : "+l"(a0) : "l"(a2));
        float lo, hi;
        asm("mov.b64 {%0, %1}, %2;" : "=f"(lo), "=f"(hi) : "l"(a0));
        gh_s[o] = bh + lo + hi;
        __syncthreads();
        if (o < 128) {
            const float* gi = (dir == 0) ? (g_gif + (size_t)(b*2 + t)*384)
                                         : (g_gi  + (size_t)(b*SS + t)*384);
            float ir = gi[o], iz = gi[128+o], inn = gi[256+o];
            float r = 1.f/(1.f+expf(-(ir + gh_s[o])));
            float z = 1.f/(1.f+expf(-(iz + gh_s[128+o])));
            float n = tanhf(inn + r*gh_s[256+o]);
            float hnew = (1.f-z)*n + z*h_s[o];
            if (dir == 0) {
                if (i2 == 0)      g_y[0*BB*128 + b*128 + o] = hnew;
                else if (i2 == 1) g_y[1*BB*128 + b*128 + o] = hnew;
            } else {
                if (i2 == SS-1)      g_y[2*BB*128 + b*128 + o] = hnew;
                else if (i2 == SS-2) g_y[3*BB*128 + b*128 + o] = hnew;
            }
            h_s[o] = hnew;
        }
        __syncthreads();
    }
}

__global__ void k_final(const float* __restrict__ Wo, const float* __restrict__ bo,
                        const float* __restrict__ rel_emb, const void* trg,
                        const float* __restrict__ l1W, const float* __restrict__ l1b,
                        const float* __restrict__ l2W, const float* __restrict__ l2b,
                        float* __restrict__ out)
{
    const int b = blockIdx.x, j = threadIdx.x;
    __shared__ float conv[128];
    __shared__ float s16[16];
    float hh = bo[j], ht = bo[j];
    const float* yf0 = g_y + 0*BB*128 + b*128;
    const float* yf1 = g_y + 1*BB*128 + b*128;
    const float* yb0 = g_y + 2*BB*128 + b*128;
    const float* yb1 = g_y + 3*BB*128 + b*128;
    for (int k = 0; k < 128; k++) {
        float wk = Wo[k*128 + j];
        hh += yf0[k]*wk; ht += yf1[k]*wk;
    }
    for (int k = 0; k < 128; k++) {
        float wk = Wo[(128+k)*128 + j];
        hh += yb0[k]*wk; ht += yb1[k]*wk;
    }
    hh = fmaxf(hh, 0.f); ht = fmaxf(ht, 0.f);
    int tr = ld_idx(trg, b, 1);
    conv[j] = tanhf(hh + rel_emb[tr*128 + j] - ht);
    __syncthreads();
    if (j < 16) {
        float s = l1b[j];
        for (int k = 0; k < 128; k++) s += conv[k]*l1W[k*16 + j];
        s16[j] = s;
    }
    __syncthreads();
    if (j == 0) {
        float o = l2b[0];
        for (int i = 0; i < 16; i++) o += s16[i]*l2W[i];
        out[b] = o;
    }
}

extern "C" void kernel_launch(void* const* d_in, const int* in_sizes, int n_in,
                              void* d_out, int out_size)
{
    const float* node_feat = (const float*)d_in[0];
    const float* rel_emb   = (const float*)d_in[1];
    const float* W_i_node  = (const float*)d_in[2];
    const float* W_i_edge  = (const float*)d_in[3];
    const float* W_att_in1 = (const float*)d_in[4];
    const float* W_att_in2 = (const float*)d_in[5];
    const float* W_h_node  = (const float*)d_in[6];
    const float* W_h_edge  = (const float*)d_in[7];
    const float* W_att1    = (const float*)d_in[8];
    const float* W_att2    = (const float*)d_in[9];
    const float* comm_W    = (const float*)d_in[10];
    const float* W_o       = (const float*)d_in[11];
    const float* b_o       = (const float*)d_in[12];
    const float* gru_bias  = (const float*)d_in[13];
    const float* gru_Wih   = (const float*)d_in[14];
    const float* gru_Whh   = (const float*)d_in[15];
    const float* gru_bih   = (const float*)d_in[16];
    const float* gru_bhh   = (const float*)d_in[17];
    const float* lin1_W    = (const float*)d_in[18];
    const float* lin1_b    = (const float*)d_in[19];
    const float* lin2_W    = (const float*)d_in[20];
    const float* lin2_b    = (const float*)d_in[21];
    const void*  src       = d_in[22];
    const void*  dst       = d_in[23];
    const void*  etype     = d_in[24];
    const void*  elabel    = d_in[25];
    const void*  trg       = d_in[26];
    float* out = (float*)d_out;

    float *ge_ie, *ge_in, *ge_P, *ge_D, *ge_U, *ge_mn, *ge_agg, *ge_V;
    float *ge_nodeh, *ge_msg, *ge_scr, *ge_gi, *ge_gif, *ge_msg2, *ge_WihT, *ge_Qrel, *ge_Qd;
    unsigned short *ge_Wh, *ge_Wl, *ge_meh, *ge_mel;
    int *ge_srcp, *ge_dstp, *ge_etp, *ge_elp;
    cudaGetSymbolAddress((void**)&ge_ie, g_ie);
    cudaGetSymbolAddress((void**)&ge_meh, g_meh);
    cudaGetSymbolAddress((void**)&ge_mel, g_mel);
    cudaGetSymbolAddress((void**)&ge_in, g_in);
    cudaGetSymbolAddress((void**)&ge_P, g_P);
    cudaGetSymbolAddress((void**)&ge_D, g_D);
    cudaGetSymbolAddress((void**)&ge_U, g_U);
    cudaGetSymbolAddress((void**)&ge_mn, g_mn);
    cudaGetSymbolAddress((void**)&ge_agg, g_agg);
    cudaGetSymbolAddress((void**)&ge_V, g_V);
    cudaGetSymbolAddress((void**)&ge_nodeh, g_nodeh);
    cudaGetSymbolAddress((void**)&ge_msg, g_msg);
    cudaGetSymbolAddress((void**)&ge_scr, g_scr);
    cudaGetSymbolAddress((void**)&ge_gi, g_gi);
    cudaGetSymbolAddress((void**)&ge_gif, g_gif);
    cudaGetSymbolAddress((void**)&ge_msg2, g_msg2);
    cudaGetSymbolAddress((void**)&ge_WihT, g_WihT);
    cudaGetSymbolAddress((void**)&ge_Qrel, g_Qrel);
    cudaGetSymbolAddress((void**)&ge_Qd, g_Qd);
    cudaGetSymbolAddress((void**)&ge_Wh, g_Whg);
    cudaGetSymbolAddress((void**)&ge_Wl, g_Wlg);
    cudaGetSymbolAddress((void**)&ge_srcp, g_srcp);
    cudaGetSymbolAddress((void**)&ge_dstp, g_dstp);
    cudaGetSymbolAddress((void**)&ge_etp, g_etp);
    cudaGetSymbolAddress((void**)&ge_elp, g_elp);

    cudaFuncSetAttribute(k_edge_att_tc, cudaFuncAttributeMaxDynamicSharedMemorySize, DYN_BYTES);

    k_detect<<<1, 32>>>(src, etype);

    // CSR of dst + edge permutation
    k_cnt_zero<<<NN/256, 256>>>();
    k_count<<<NE/256, 256>>>(dst);
    k_scan1<<<16, 1024>>>();
    k_scan2<<<1, 32>>>();
    k_scan3<<<NN/256, 256>>>();
    k_fill<<<NE/256, 256>>>(dst);
    k_perm<<<NE/256, 256>>>(src, dst, etype, elabel);

    // edge attention weights -> bf16 hi/lo (single launch)
    k_wconv3<<<192, 256>>>(W_att_in1 + 128*128, W_att1, W_att1 + 32768, ge_Wh, ge_Wl);

    // node-side GEMMs
    k_tgemm_bf3<<<dim3(NN/128, 3), 256>>>(node_feat,
        W_i_edge, W_i_edge + 192*128, W_i_node,
        ge_P, ge_D, ge_in, /*reluMask=*/0b100);
    // rel_emb GEMMs (single launch)
    k_sgemm3<<<dim3(1, 6), 256>>>(rel_emb,
        W_i_edge + 64*128, W_att1 + 128*128, W_att1 + 32768 + 128*128,
        ge_Qrel, ge_Qd, ge_Qd + RR*128);

    // fused edge_init + input attention (mode 2)
    k_tgemm_bf<<<dim3(NN/128, 1), 256>>>(ge_in, W_att_in1, ge_U, 128, 128, NULL, 0, 0);
    k_edge_att_tc<<<NE/128, 256, DYN_BYTES>>>(NULL, NULL, ge_Wh, ge_Wl, ge_U, ge_srcp, ge_srcp,
                                              W_att_in2, ge_ie, NULL, ge_meh, ge_mel, 2,
                                              ge_P, ge_Qrel, ge_D, ge_etp, ge_dstp, ge_ie);

    // two message-passing depths
    for (int d = 0; d < 2; d++) {
        const float* mn_old = (d == 0) ? ge_in : ge_mn;
        k_gather<<<NN, 128>>>(ge_meh, ge_mel, mn_old, ge_scr);
        k_tgemm_bf<<<dim3(NN/128, 1), 256>>>(ge_scr, W_h_node + d*16384, ge_mn, 128, 128, NULL, 1, 0);
        k_tgemm_bf<<<dim3(NN/128, 1), 256>>>(ge_mn, W_h_edge + d*16384, ge_V, 128, 128, NULL, 0, 0);
        k_edge_att_tc<<<NE/128, 256, DYN_BYTES>>>(ge_meh, ge_mel,
                                                  ge_Wh + (d+1)*16384, ge_Wl + (d+1)*16384,
                                                  ge_Qd + d*RR*128, ge_elp,
                                                  ge_srcp, W_att2 + d*128, ge_ie, ge_V,
                                                  ge_meh, ge_mel, 1,
                                                  NULL, NULL, NULL, NULL, NULL, NULL);
    }

    // readout aggregation + single concat GEMM
    k_gather<<<NN, 128>>>(ge_meh, ge_mel, NULL, ge_agg);
    k_tgemm_cat3<<<dim3(NN/128, 1), 256>>>(ge_agg, ge_mn, ge_in, comm_W, ge_nodeh);

    // GRU
    k_msg<<<NN*128/256, 256>>>(gru_bias);
    k_h0<<<BB, 128>>>();
    k_twih<<<(2*384*128 + 255)/256, 256>>>(gru_Wih);
    k_tgemm_bf<<<dim3(1, 3), 256>>>(ge_msg2, ge_WihT,           ge_gif, 128, 384, gru_bih,       0, 0);
    k_tgemm_bf<<<dim3(NN/128, 3), 256>>>(ge_msg, ge_WihT + 384*128, ge_gi, 128, 384, gru_bih + 384, 0, 0);
    k_gru<<<dim3(BB, 2), 384>>>(gru_Whh, gru_bhh);

    k_final<<<BB, 128>>>(W_o, b_o, rel_emb, trg, lin1_W, lin1_b, lin2_W, lin2_b, out);
}